// round 11
// baseline (speedup 1.0000x reference)
#include <cuda_runtime.h>
#include <cuda_bf16.h>
#include <cstdint>

#define BATCH 128
#define SLEN  1024
#define NSENT 64
#define QLEN  64
#define EMB   50
#define RUN   400
#define MEM   300
#define VOC   2000
#define N3V   (3 * VOC)      // 6000
#define NCH   125            // k16 chunks (2000/16)
#define NBLK  750            // n8 blocks (6000/8)

typedef unsigned long long ull;

__device__ __forceinline__ ull pack2(float lo, float hi) {
    ull r; asm("mov.b64 %0, {%1, %2};" : "=l"(r) : "f"(lo), "f"(hi)); return r;
}
__device__ __forceinline__ ull pdup(float v) { return pack2(v, v); }
__device__ __forceinline__ void fma2(ull& d, ull a, ull b) {
    asm("fma.rn.f32x2 %0, %1, %2, %0;" : "+l"(d) : "l"(a), "l"(b));
}
__device__ __forceinline__ void add2(ull& d, ull a) {
    asm("add.rn.f32x2 %0, %0, %1;" : "+l"(d) : "l"(a));
}
__device__ __forceinline__ float2 unpack2(ull v) {
    float2 r; asm("mov.b64 {%0, %1}, %2;" : "=f"(r.x), "=f"(r.y) : "l"(v)); return r;
}

// bf16 HMMA m16n8k16, f32 accum
__device__ __forceinline__ void mma_bf16(float& c0, float& c1, float& c2, float& c3,
                                         uint32_t a0, uint32_t a1, uint32_t a2, uint32_t a3,
                                         uint32_t b0, uint32_t b1) {
    asm volatile(
        "mma.sync.aligned.m16n8k16.row.col.f32.bf16.bf16.f32 "
        "{%0,%1,%2,%3}, {%4,%5,%6,%7}, {%8,%9}, {%0,%1,%2,%3};"
        : "+f"(c0), "+f"(c1), "+f"(c2), "+f"(c3)
        : "r"(a0), "r"(a1), "r"(a2), "r"(a3), "r"(b0), "r"(b1));
}

__device__ __forceinline__ uint32_t pk_bf2(float x, float y) {
    __nv_bfloat162 h = __floats2bfloat162_rn(x, y);
    return *reinterpret_cast<uint32_t*>(&h);
}
__device__ __forceinline__ float bf_hi(float v) {
    __nv_bfloat16 h = __float2bfloat16(v);
    return __bfloat162float(h);
}

// ---------------------------------------------------------------------------
// Device scratch
// ---------------------------------------------------------------------------
__device__ float g_table_i[1024 * 3 * RUN];
__device__ float g_table_q[64 * 3 * RUN];
__device__ float g_hinfo[(size_t)BATCH * SLEN * RUN];
__device__ float g_hq[(size_t)BATCH * QLEN * RUN];
__device__ float g_prod[(size_t)BATCH * NSENT * RUN];
__device__ float g_xzm[(size_t)BATCH * NSENT * 3 * MEM];
__device__ float g_hidden[(size_t)BATCH * NSENT * MEM];
__device__ float g_xza[(size_t)BATCH * NSENT * N3V];
__device__ float g_rec[(size_t)BATCH * N3V];
__device__ float g_hA[(size_t)BATCH * VOC];
__device__ float g_hB[(size_t)BATCH * VOC];
// B fragments: [NBLK][NCH][32] x uint4 (hi b0,b1 + lo b0,b1)
__device__ uint4 g_UaPk[(size_t)NBLK * NCH * 32];
// A fragments: [8 mblk][NCH][32] x uint4, hi and lo separate
__device__ uint4 g_hAHi[(size_t)8 * NCH * 32];
__device__ uint4 g_hALo[(size_t)8 * NCH * 32];

__device__ unsigned g_cnt[16 * 32];
__device__ volatile unsigned g_sns[16 * 32];

__device__ __forceinline__ float sigmoidf_(float x) { return 1.f / (1.f + expf(-x)); }

__device__ __forceinline__ void group_barrier(int slot, unsigned G, unsigned& sense) {
    __syncthreads();
    sense ^= 1u;
    if (threadIdx.x == 0 && threadIdx.y == 0 && threadIdx.z == 0) {
        __threadfence();
        unsigned prev = atomicAdd(&g_cnt[slot * 32], 1u);
        if (prev == G - 1u) {
            g_cnt[slot * 32] = 0u;
            __threadfence();
            g_sns[slot * 32] = sense;
        } else {
            while (g_sns[slot * 32] != sense) { }
        }
        __threadfence();
    }
    __syncthreads();
}

// ---------------------------------------------------------------------------
// table[v, j] = sum_e emb[v,e] * W[e,j] + b0[j]
// ---------------------------------------------------------------------------
__global__ void build_table_kernel(const float* __restrict__ emb,
                                   const float* __restrict__ W,
                                   const float* __restrict__ b0,
                                   float* __restrict__ table,
                                   int N3) {
    int v = blockIdx.y;
    int j = blockIdx.x * blockDim.x + threadIdx.x;
    __shared__ float se[EMB];
    if (threadIdx.x < EMB) se[threadIdx.x] = emb[(size_t)v * EMB + threadIdx.x];
    __syncthreads();
    if (j < N3) {
        float acc = b0[j];
#pragma unroll 10
        for (int e = 0; e < EMB; ++e) acc += se[e] * W[(size_t)e * N3 + j];
        table[(size_t)v * N3 + j] = acc;
    }
}

// ---------------------------------------------------------------------------
// Ua [2000,6000] -> packed bf16 B fragments (hi/lo), fragment-major.
// frag fp = (nb*NCH + kc)*32 + lane: n = nb*8 + (l>>2), k = kc*16 + 2*(l&3).
// uint4 = { (hi k,k+1), (hi k+8,k+9), (lo k,k+1), (lo k+8,k+9) }
// ---------------------------------------------------------------------------
__global__ void prep_ua_frag(const float* __restrict__ Ua, uint4* __restrict__ dst) {
    size_t fp = (size_t)blockIdx.x * blockDim.x + threadIdx.x;
    if (fp >= (size_t)NBLK * NCH * 32) return;
    int l  = fp & 31;
    int kc = (int)((fp >> 5) % NCH);
    int nb = (int)((fp >> 5) / NCH);
    int n = nb * 8 + (l >> 2);
    int k = kc * 16 + 2 * (l & 3);
    float u0 = Ua[(size_t)k * N3V + n];
    float u1 = Ua[(size_t)(k + 1) * N3V + n];
    float u8 = Ua[(size_t)(k + 8) * N3V + n];
    float u9 = Ua[(size_t)(k + 9) * N3V + n];
    float h0 = bf_hi(u0), h1 = bf_hi(u1), h8 = bf_hi(u8), h9 = bf_hi(u9);
    uint4 v;
    v.x = pk_bf2(h0, h1);
    v.y = pk_bf2(h8, h9);
    v.z = pk_bf2(u0 - h0, u1 - h1);
    v.w = pk_bf2(u8 - h8, u9 - h9);
    dst[fp] = v;
}

// ---------------------------------------------------------------------------
// Persistent GRU (r9 form, unchanged).
// ---------------------------------------------------------------------------
template <int H>
__global__ void __launch_bounds__(128, 1)
gru_seq_kernel(const float* __restrict__ xz,
               const int* __restrict__ tok,
               const float* __restrict__ U,
               const float* __restrict__ brec,
               float* __restrict__ hP, float* __restrict__ hQ,
               float* __restrict__ seq_out,
               const int* __restrict__ num_sent,
               int T) {
    extern __shared__ __align__(16) ull smu[];
    ull* su2 = smu;            // [H][48]
    ull* shd = smu + H * 48;   // [16][H]
    __shared__ ull sred[64 * 12];

    const int tx = threadIdx.x;
    const int ty = threadIdx.y;
    const int tz = threadIdx.z;
    const int tid64 = ty * 16 + tx;
    const int tid = tz * 64 + tid64;
    const int j0 = blockIdx.x * 32;
    const int b0 = blockIdx.y * 16;
    const int N3 = 3 * H;
    const int slot = blockIdx.y;
    const unsigned G = gridDim.x;
    unsigned sense = g_sns[slot * 32];

    for (int e = tid; e < H * 48; e += 128) {
        int k = e / 48, c = e - k * 48;
        int g = c >> 4, p = c & 15;
        int j = j0 + 2 * p;
        float lo = (j < H) ? U[(size_t)k * N3 + g * H + j] : 0.f;
        float hi = (j + 1 < H) ? U[(size_t)k * N3 + g * H + j + 1] : 0.f;
        su2[e] = pack2(lo, hi);
    }
    for (int e = tid; e < 16 * 32; e += 128) {
        int bb = e >> 5, jj = e & 31;
        if (j0 + jj < H) hP[(size_t)(b0 + bb) * H + j0 + jj] = 0.f;
    }
    group_barrier(slot, G, sense);

    float* hp = hP;
    float* hn = hQ;

    const int jA = j0 + 2 * tx;
    const int jB = jA + 1;
    float bzA = 0, brA = 0, bhA = 0, bzB = 0, brB = 0, bhB = 0;
    if (jA < H) { bzA = brec[jA]; brA = brec[H + jA]; bhA = brec[2 * H + jA]; }
    if (jB < H) { bzB = brec[jB]; brB = brec[H + jB]; bhB = brec[2 * H + jB]; }

    constexpr int Hh = H / 2;
    const int kBeg = tz * Hh;
    const ull* up = su2 + tx;

    for (int t = 0; t < T; ++t) {
        ull xzp[4], xrp[4], xhp[4];
        int padi[4];
        if (tz == 0 && jA < H) {
#pragma unroll
            for (int r = 0; r < 4; ++r) {
                const int b = b0 + 4 * ty + r;
                const float* xrow;
                if (tok) xrow = xz + (size_t)tok[(size_t)b * T + t] * N3;
                else     xrow = xz + ((size_t)b * T + t) * N3;
                xzp[r] = *reinterpret_cast<const ull*>(xrow + jA);
                xrp[r] = *reinterpret_cast<const ull*>(xrow + H + jA);
                xhp[r] = *reinterpret_cast<const ull*>(xrow + 2 * H + jA);
                padi[r] = num_sent ? num_sent[b] : 0x7fffffff;
            }
        }

        for (int e = tid; e < 16 * H; e += 128) {
            int row = e / H, k = e - row * H;
            shd[row * H + k] = pdup(hp[(size_t)(b0 + row) * H + k]);
        }
        __syncthreads();

        ull az[4] = {0,0,0,0}, ar[4] = {0,0,0,0}, ah[4] = {0,0,0,0};
        const ull* h0p = shd + (4 * ty + 0) * H + kBeg;
        const ull* h1p = shd + (4 * ty + 1) * H + kBeg;
        const ull* h2p = shd + (4 * ty + 2) * H + kBeg;
        const ull* h3p = shd + (4 * ty + 3) * H + kBeg;
        const ull* ub = up + kBeg * 48;
#pragma unroll 4
        for (int kk = 0; kk < Hh; ++kk) {
            ull uz = ub[kk * 48];
            ull ur = ub[kk * 48 + 16];
            ull uh = ub[kk * 48 + 32];
            ull h0 = h0p[kk], h1 = h1p[kk], h2 = h2p[kk], h3 = h3p[kk];
            fma2(az[0], h0, uz); fma2(az[1], h1, uz); fma2(az[2], h2, uz); fma2(az[3], h3, uz);
            fma2(ar[0], h0, ur); fma2(ar[1], h1, ur); fma2(ar[2], h2, ur); fma2(ar[3], h3, ur);
            fma2(ah[0], h0, uh); fma2(ah[1], h1, uh); fma2(ah[2], h2, uh); fma2(ah[3], h3, uh);
        }

        if (tz == 1) {
            ull* s = sred + tid64 * 12;
#pragma unroll
            for (int r = 0; r < 4; ++r) { s[r] = az[r]; s[4 + r] = ar[r]; s[8 + r] = ah[r]; }
        }
        __syncthreads();

        if (tz == 0) {
            const ull* s = sred + tid64 * 12;
#pragma unroll
            for (int r = 0; r < 4; ++r) { add2(az[r], s[r]); add2(ar[r], s[4 + r]); add2(ah[r], s[8 + r]); }

            if (jA < H) {
#pragma unroll
                for (int r = 0; r < 4; ++r) {
                    const int row = 4 * ty + r;
                    const int b = b0 + row;
                    float2 AZ = unpack2(az[r]);
                    float2 AR = unpack2(ar[r]);
                    float2 AH = unpack2(ah[r]);
                    float2 XZ = unpack2(xzp[r]);
                    float2 XR = unpack2(xrp[r]);
                    float2 XH = unpack2(xhp[r]);
                    float padv = (t <= padi[r]) ? 1.f : 0.f;
                    {
                        float z  = sigmoidf_(XZ.x + AZ.x + bzA);
                        float rr = sigmoidf_(XR.x + AR.x + brA);
                        float hh = tanhf(XH.x + rr * (AH.x + bhA));
                        float hprev = unpack2(shd[row * H + jA]).x;
                        float hnew = z * hprev + (1.f - z) * hh;
                        hn[(size_t)b * H + jA] = hnew;
                        seq_out[((size_t)b * T + t) * H + jA] = hnew * padv;
                    }
                    if (jB < H) {
                        float z  = sigmoidf_(XZ.y + AZ.y + bzB);
                        float rr = sigmoidf_(XR.y + AR.y + brB);
                        float hh = tanhf(XH.y + rr * (AH.y + bhB));
                        float hprev = unpack2(shd[row * H + jB]).x;
                        float hnew = z * hprev + (1.f - z) * hh;
                        hn[(size_t)b * H + jB] = hnew;
                        seq_out[((size_t)b * T + t) * H + jB] = hnew * padv;
                    }
                }
            }
        }
        group_barrier(slot, G, sense);
        float* tmp = hp; hp = hn; hn = tmp;
    }
}

// ---------------------------------------------------------------------------
// prod
// ---------------------------------------------------------------------------
__global__ void prod_kernel(const float* __restrict__ hinfo,
                            const float* __restrict__ hq,
                            const int* __restrict__ info_idx,
                            const int* __restrict__ num_sent,
                            const int* __restrict__ qidx,
                            float* __restrict__ prod) {
    const int nn = blockIdx.x;
    const int b  = blockIdx.y;
    const int si = info_idx[b * NSENT + nn];
    const int qi = qidx[b] - 1;
    const float padv = (nn <= num_sent[b]) ? 1.f : 0.f;
    const float* hi  = hinfo + ((size_t)b * SLEN + si) * RUN;
    const float* hqr = hq + ((size_t)b * QLEN + qi) * RUN;
    float* pr = prod + ((size_t)b * NSENT + nn) * RUN;
    for (int jj = threadIdx.x; jj < RUN; jj += blockDim.x)
        pr[jj] = hi[jj] * hqr[jj] * padv;
}

// ---------------------------------------------------------------------------
// Generic C = A@W + bias (xzm, xza)
// ---------------------------------------------------------------------------
__global__ void gemm_bias_kernel(const float* __restrict__ A,
                                 const float* __restrict__ W,
                                 const float* __restrict__ bias,
                                 float* __restrict__ C,
                                 int Mdim, int Kdim, int Ndim) {
    __shared__ __align__(16) float As[16][68];
    __shared__ __align__(16) float Bs[16][68];
    const int tid = threadIdx.x;
    const int tx = tid & 15;
    const int ty = tid >> 4;
    const int m0 = blockIdx.y * 64;
    const int n0 = blockIdx.x * 64;

    float acc[4][4];
#pragma unroll
    for (int i = 0; i < 4; ++i)
#pragma unroll
        for (int jj = 0; jj < 4; ++jj) acc[i][jj] = 0.f;

    for (int k0 = 0; k0 < Kdim; k0 += 16) {
        for (int e = tid; e < 1024; e += 256) {
            int mm = e >> 4, kk = e & 15;
            int m = m0 + mm, k = k0 + kk;
            As[kk][mm] = (m < Mdim && k < Kdim) ? A[(size_t)m * Kdim + k] : 0.f;
        }
        for (int e = tid; e < 1024; e += 256) {
            int kk = e >> 6, nn = e & 63;
            int k = k0 + kk, nv = n0 + nn;
            Bs[kk][nn] = (k < Kdim && nv < Ndim) ? W[(size_t)k * Ndim + nv] : 0.f;
        }
        __syncthreads();
#pragma unroll
        for (int kk = 0; kk < 16; ++kk) {
            float4 a4 = *reinterpret_cast<const float4*>(&As[kk][ty * 4]);
            float4 b4 = *reinterpret_cast<const float4*>(&Bs[kk][tx * 4]);
            float av[4] = {a4.x, a4.y, a4.z, a4.w};
            float bv[4] = {b4.x, b4.y, b4.z, b4.w};
#pragma unroll
            for (int i = 0; i < 4; ++i)
#pragma unroll
                for (int jj = 0; jj < 4; ++jj) acc[i][jj] += av[i] * bv[jj];
        }
        __syncthreads();
    }
#pragma unroll
    for (int i = 0; i < 4; ++i) {
        int m = m0 + ty * 4 + i;
        if (m >= Mdim) continue;
#pragma unroll
        for (int jj = 0; jj < 4; ++jj) {
            int nv = n0 + tx * 4 + jj;
            if (nv < Ndim) C[(size_t)m * Ndim + nv] = acc[i][jj] + bias[nv];
        }
    }
}

// ---------------------------------------------------------------------------
// Persistent answer GRU with mma.sync bf16 (hi/lo split, 3 MMAs).
// grid = 128 CTAs x 256 thr. Tiles: 125 x (128m x 48n), CTA<125.
// Warp w = m-block w (rows 16w..16w+15); 6 n-blocks per warp.
// Phase A0: hp -> A fragments (bf16 hi/lo) in fragment-major layout.
// Phase A1: fragment GEMM from global (no smem), epilogue -> rec (+ba1).
// Phase B: gates + softmax + combine.
// ---------------------------------------------------------------------------
#define ANS_G    128
#define ANS_NT   125
#define ANS_SLOT 15

__global__ void __launch_bounds__(256, 1)
answer_kernel(const float* __restrict__ xza,
              const float* __restrict__ ba1,
              float* __restrict__ rec,
              float* __restrict__ hP, float* __restrict__ hQ,
              float* __restrict__ out,
              const uint4* __restrict__ UaPk,
              uint4* __restrict__ hAHi,
              uint4* __restrict__ hALo) {
    __shared__ float red[256];

    const int tid = threadIdx.x;
    const int wid = tid >> 5;
    const int lid = tid & 31;
    const unsigned G = gridDim.x;
    unsigned sense = g_sns[ANS_SLOT * 32];
    const bool gemm_cta = (blockIdx.x < ANS_NT);

    for (int e = blockIdx.x * 256 + tid; e < BATCH * VOC; e += G * 256)
        hP[e] = 0.f;
    group_barrier(ANS_SLOT, G, sense);

    float* hp = hP;
    float* hn = hQ;

    for (int n = 0; n < NSENT; ++n) {
        // ---- phase A0: hp -> A fragments hi/lo (all CTAs; 32000 frags) ----
        {
            int f = blockIdx.x * 256 + tid;
            if (f < 8 * NCH * 32) {
                int l  = f & 31;
                int kc = (f >> 5) % NCH;
                int mb = (f >> 5) / NCH;
                int r = mb * 16 + (l >> 2);
                int c = kc * 16 + 2 * (l & 3);
                float2 v00 = *reinterpret_cast<const float2*>(hp + (size_t)r * VOC + c);
                float2 v10 = *reinterpret_cast<const float2*>(hp + (size_t)(r + 8) * VOC + c);
                float2 v01 = *reinterpret_cast<const float2*>(hp + (size_t)r * VOC + c + 8);
                float2 v11 = *reinterpret_cast<const float2*>(hp + (size_t)(r + 8) * VOC + c + 8);
                float h00x = bf_hi(v00.x), h00y = bf_hi(v00.y);
                float h10x = bf_hi(v10.x), h10y = bf_hi(v10.y);
                float h01x = bf_hi(v01.x), h01y = bf_hi(v01.y);
                float h11x = bf_hi(v11.x), h11y = bf_hi(v11.y);
                uint4 hi, lo;
                hi.x = pk_bf2(h00x, h00y); hi.y = pk_bf2(h10x, h10y);
                hi.z = pk_bf2(h01x, h01y); hi.w = pk_bf2(h11x, h11y);
                lo.x = pk_bf2(v00.x - h00x, v00.y - h00y);
                lo.y = pk_bf2(v10.x - h10x, v10.y - h10y);
                lo.z = pk_bf2(v01.x - h01x, v01.y - h01y);
                lo.w = pk_bf2(v11.x - h11x, v11.y - h11y);
                hAHi[f] = hi;
                hALo[f] = lo;
            }
        }
        group_barrier(ANS_SLOT, G, sense);

        // ---- phase A1: fragment GEMM ----
        if (gemm_cta) {
            const int tile = blockIdx.x;
            const int nbBase = tile * 6;
            const int mb = wid;                       // warp -> m-block
            float acc[6][4];
#pragma unroll
            for (int i = 0; i < 6; ++i)
#pragma unroll
                for (int c = 0; c < 4; ++c) acc[i][c] = 0.f;

            const uint4* Ah = hAHi + ((size_t)mb * NCH) * 32 + lid;
            const uint4* Al = hALo + ((size_t)mb * NCH) * 32 + lid;
            const uint4* B0 = UaPk + ((size_t)(nbBase + 0) * NCH) * 32 + lid;
            const uint4* B1 = UaPk + ((size_t)(nbBase + 1) * NCH) * 32 + lid;
            const uint4* B2 = UaPk + ((size_t)(nbBase + 2) * NCH) * 32 + lid;
            const uint4* B3 = UaPk + ((size_t)(nbBase + 3) * NCH) * 32 + lid;
            const uint4* B4 = UaPk + ((size_t)(nbBase + 4) * NCH) * 32 + lid;
            const uint4* B5 = UaPk + ((size_t)(nbBase + 5) * NCH) * 32 + lid;

            for (int kc = 0; kc < NCH; ++kc) {
                uint4 a = Ah[kc * 32];
                uint4 al = Al[kc * 32];
#pragma unroll
                for (int nb = 0; nb < 6; ++nb) {
                    const uint4* Bp = (nb == 0) ? B0 : (nb == 1) ? B1 : (nb == 2) ? B2
                                     : (nb == 3) ? B3 : (nb == 4) ? B4 : B5;
                    uint4 b = Bp[kc * 32];
                    mma_bf16(acc[nb][0], acc[nb][1], acc[nb][2], acc[nb][3],
                             a.x, a.y, a.z, a.w, b.x, b.y);           // Ahi*Bhi
                    mma_bf16(acc[nb][0], acc[nb][1], acc[nb][2], acc[nb][3],
                             a.x, a.y, a.z, a.w, b.z, b.w);           // Ahi*Blo
                    mma_bf16(acc[nb][0], acc[nb][1], acc[nb][2], acc[nb][3],
                             al.x, al.y, al.z, al.w, b.x, b.y);       // Alo*Bhi
                }
            }

            // epilogue: write rec (+ba1)
            const int r0 = mb * 16 + (lid >> 2);
#pragma unroll
            for (int nb = 0; nb < 6; ++nb) {
                int nc = (nbBase + nb) * 8 + 2 * (lid & 3);
                float b0 = ba1[nc], b1 = ba1[nc + 1];
                float2 v0 = { acc[nb][0] + b0, acc[nb][1] + b1 };
                float2 v1 = { acc[nb][2] + b0, acc[nb][3] + b1 };
                *reinterpret_cast<float2*>(rec + (size_t)r0 * N3V + nc) = v0;
                *reinterpret_cast<float2*>(rec + (size_t)(r0 + 8) * N3V + nc) = v1;
            }
        }
        group_barrier(ANS_SLOT, G, sense);

        // ---- phase B: gates + softmax + combine ----
        {
            const int b = blockIdx.x;   // G == 128 == BATCH
            const float* xrow = xza + ((size_t)b * NSENT + n) * N3V;
            const float* rrow = rec + (size_t)b * N3V;
            float zv[8], tv[8];
            float m = -1e30f;
#pragma unroll
            for (int i = 0; i < 8; ++i) {
                int jj = tid + i * 256;
                if (jj < VOC) {
                    float z = sigmoidf_(xrow[jj] + rrow[jj]);
                    float r = sigmoidf_(xrow[VOC + jj] + rrow[VOC + jj]);
                    float t = xrow[2 * VOC + jj] + r * rrow[2 * VOC + jj];
                    zv[i] = z; tv[i] = t;
                    m = fmaxf(m, t);
                } else { zv[i] = 0.f; tv[i] = -1e30f; }
            }
            red[tid] = m; __syncthreads();
            for (int s = 128; s > 0; s >>= 1) {
                if (tid < s) red[tid] = fmaxf(red[tid], red[tid + s]);
                __syncthreads();
            }
            m = red[0]; __syncthreads();

            float ev[8];
            float sum = 0.f;
#pragma unroll
            for (int i = 0; i < 8; ++i) {
                int jj = tid + i * 256;
                if (jj < VOC) { ev[i] = expf(tv[i] - m); sum += ev[i]; }
                else ev[i] = 0.f;
            }
            red[tid] = sum; __syncthreads();
            for (int s = 128; s > 0; s >>= 1) {
                if (tid < s) red[tid] += red[tid + s];
                __syncthreads();
            }
            const float inv = 1.f / red[0];
            __syncthreads();

#pragma unroll
            for (int i = 0; i < 8; ++i) {
                int jj = tid + i * 256;
                if (jj < VOC) {
                    float hh = ev[i] * inv;
                    float z  = zv[i];
                    float hprev = hp[(size_t)b * VOC + jj];
                    float hnew = z * hprev + (1.f - z) * hh;
                    hn[(size_t)b * VOC + jj] = hnew;
                    out[((size_t)b * NSENT + n) * VOC + jj] = hnew;
                }
            }
        }
        group_barrier(ANS_SLOT, G, sense);
        float* tmp = hp; hp = hn; hn = tmp;
    }
}

// ---------------------------------------------------------------------------
// Host orchestration
// ---------------------------------------------------------------------------
extern "C" void kernel_launch(void* const* d_in, const int* in_sizes, int n_in,
                              void* d_out, int out_size) {
    const int*   info      = (const int*)d_in[0];
    const int*   info_idx  = (const int*)d_in[1];
    const int*   num_sent  = (const int*)d_in[2];
    const int*   question  = (const int*)d_in[3];
    const int*   qidx      = (const int*)d_in[4];
    const float* info_emb  = (const float*)d_in[5];
    const float* Wi        = (const float*)d_in[6];
    const float* Ui        = (const float*)d_in[7];
    const float* bi        = (const float*)d_in[8];
    const float* q_emb     = (const float*)d_in[9];
    const float* Wq        = (const float*)d_in[10];
    const float* Uq        = (const float*)d_in[11];
    const float* bq        = (const float*)d_in[12];
    const float* Wm        = (const float*)d_in[13];
    const float* Um        = (const float*)d_in[14];
    const float* bm        = (const float*)d_in[15];
    const float* Wa        = (const float*)d_in[16];
    const float* Ua        = (const float*)d_in[17];
    const float* ba        = (const float*)d_in[18];
    float* out = (float*)d_out;

    float *tbl_i, *tbl_q, *hinfo, *hq, *prod, *xzm, *hidden, *xza, *rec, *hA, *hB;
    uint4 *uaPk, *hAHi, *hALo;
    cudaGetSymbolAddress((void**)&tbl_i, g_table_i);
    cudaGetSymbolAddress((void**)&tbl_q, g_table_q);
    cudaGetSymbolAddress((void**)&hinfo, g_hinfo);
    cudaGetSymbolAddress((void**)&hq, g_hq);
    cudaGetSymbolAddress((void**)&prod, g_prod);
    cudaGetSymbolAddress((void**)&xzm, g_xzm);
    cudaGetSymbolAddress((void**)&hidden, g_hidden);
    cudaGetSymbolAddress((void**)&xza, g_xza);
    cudaGetSymbolAddress((void**)&rec, g_rec);
    cudaGetSymbolAddress((void**)&hA, g_hA);
    cudaGetSymbolAddress((void**)&hB, g_hB);
    cudaGetSymbolAddress((void**)&uaPk, g_UaPk);
    cudaGetSymbolAddress((void**)&hAHi, g_hAHi);
    cudaGetSymbolAddress((void**)&hALo, g_hALo);

    const size_t smemR = ((size_t)RUN * 48 + (size_t)16 * RUN) * 8;
    const size_t smemM = ((size_t)MEM * 48 + (size_t)16 * MEM) * 8;

    static bool attr_set = false;
    if (!attr_set) {
        cudaFuncSetAttribute(gru_seq_kernel<RUN>,
                             cudaFuncAttributeMaxDynamicSharedMemorySize, (int)smemR);
        cudaFuncSetAttribute(gru_seq_kernel<MEM>,
                             cudaFuncAttributeMaxDynamicSharedMemorySize, (int)smemM);
        attr_set = true;
    }

    const dim3 blk(16, 4, 2);

    build_table_kernel<<<dim3((3 * RUN + 255) / 256, 1024), 256>>>(info_emb, Wi, bi, tbl_i, 3 * RUN);
    build_table_kernel<<<dim3((3 * RUN + 255) / 256, 64), 256>>>(q_emb, Wq, bq, tbl_q, 3 * RUN);

    // Ua -> packed bf16 fragments (runs concurrently with GRUs in spirit; ~3M threads)
    {
        size_t F = (size_t)NBLK * NCH * 32;
        prep_ua_frag<<<(unsigned)((F + 255) / 256), 256>>>(Ua, uaPk);
    }

    // info GRU (T=1024, H=400)
    gru_seq_kernel<RUN><<<dim3((RUN + 31) / 32, 8), blk, smemR>>>(
        tbl_i, info, Ui, bi + 3 * RUN, hA, hB, hinfo, nullptr, SLEN);

    // question GRU (T=64, H=400)
    gru_seq_kernel<RUN><<<dim3((RUN + 31) / 32, 8), blk, smemR>>>(
        tbl_q, question, Uq, bq + 3 * RUN, hA, hB, hq, nullptr, QLEN);

    prod_kernel<<<dim3(NSENT, BATCH), 128>>>(hinfo, hq, info_idx, num_sent, qidx, prod);

    gemm_bias_kernel<<<dim3((3 * MEM + 63) / 64, (BATCH * NSENT) / 64), 256>>>(
        prod, Wm, bm, xzm, BATCH * NSENT, RUN, 3 * MEM);

    // memory GRU (T=64, H=300)
    gru_seq_kernel<MEM><<<dim3((MEM + 31) / 32, 8), blk, smemM>>>(
        xzm, nullptr, Um, bm + 3 * MEM, hA, hB, hidden, num_sent, NSENT);

    gemm_bias_kernel<<<dim3((N3V + 63) / 64, (BATCH * NSENT) / 64), 256>>>(
        hidden, Wa, ba, xza, BATCH * NSENT, MEM, N3V);

    answer_kernel<<<ANS_G, 256>>>(xza, ba + N3V, rec, hA, hB, out, uaPk, hAHi, hALo);
}

// round 12
// speedup vs baseline: 1.3942x; 1.3942x over previous
#include <cuda_runtime.h>
#include <cuda_bf16.h>
#include <cstdint>

#define BATCH 128
#define SLEN  1024
#define NSENT 64
#define QLEN  64
#define EMB   50
#define RUN   400
#define MEM   300
#define VOC   2000
#define N3V   (3 * VOC)      // 6000
#define NCH   125            // k16 chunks (2000/16)
#define NBLK  750            // n8 blocks (6000/8)

typedef unsigned long long ull;

__device__ __forceinline__ ull pack2(float lo, float hi) {
    ull r; asm("mov.b64 %0, {%1, %2};" : "=l"(r) : "f"(lo), "f"(hi)); return r;
}
__device__ __forceinline__ ull pdup(float v) { return pack2(v, v); }
__device__ __forceinline__ void fma2(ull& d, ull a, ull b) {
    asm("fma.rn.f32x2 %0, %1, %2, %0;" : "+l"(d) : "l"(a), "l"(b));
}
__device__ __forceinline__ void add2(ull& d, ull a) {
    asm("add.rn.f32x2 %0, %0, %1;" : "+l"(d) : "l"(a));
}
__device__ __forceinline__ float2 unpack2(ull v) {
    float2 r; asm("mov.b64 {%0, %1}, %2;" : "=f"(r.x), "=f"(r.y) : "l"(v)); return r;
}

// bf16 HMMA m16n8k16, f32 accum
__device__ __forceinline__ void mma_bf16(float& c0, float& c1, float& c2, float& c3,
                                         uint32_t a0, uint32_t a1, uint32_t a2, uint32_t a3,
                                         uint32_t b0, uint32_t b1) {
    asm volatile(
        "mma.sync.aligned.m16n8k16.row.col.f32.bf16.bf16.f32 "
        "{%0,%1,%2,%3}, {%4,%5,%6,%7}, {%8,%9}, {%0,%1,%2,%3};"
        : "+f"(c0), "+f"(c1), "+f"(c2), "+f"(c3)
        : "r"(a0), "r"(a1), "r"(a2), "r"(a3), "r"(b0), "r"(b1));
}

__device__ __forceinline__ uint32_t pk_bf2(float x, float y) {
    __nv_bfloat162 h = __floats2bfloat162_rn(x, y);
    return *reinterpret_cast<uint32_t*>(&h);
}
__device__ __forceinline__ float bf_hi(float v) {
    __nv_bfloat16 h = __float2bfloat16(v);
    return __bfloat162float(h);
}

// ---------------------------------------------------------------------------
// Device scratch
// ---------------------------------------------------------------------------
__device__ float g_table_i[1024 * 3 * RUN];
__device__ float g_table_q[64 * 3 * RUN];
__device__ float g_hinfo[(size_t)BATCH * SLEN * RUN];
__device__ float g_hq[(size_t)BATCH * QLEN * RUN];
__device__ float g_prod[(size_t)BATCH * NSENT * RUN];
__device__ float g_xzm[(size_t)BATCH * NSENT * 3 * MEM];
__device__ float g_hidden[(size_t)BATCH * NSENT * MEM];
__device__ float g_xza[(size_t)BATCH * NSENT * N3V];
__device__ float g_rec[(size_t)BATCH * N3V];
__device__ float g_hA[(size_t)BATCH * VOC];
__device__ float g_hB[(size_t)BATCH * VOC];
// B fragments: [NBLK][NCH][32] x uint4 (hi b0,b1 + lo b0,b1)
__device__ uint4 g_UaPk[(size_t)NBLK * NCH * 32];
// A fragments: [8 mblk][NCH][32] x uint4, hi and lo separate
__device__ uint4 g_hAHi[(size_t)8 * NCH * 32];
__device__ uint4 g_hALo[(size_t)8 * NCH * 32];

__device__ unsigned g_cnt[16 * 32];
__device__ volatile unsigned g_sns[16 * 32];

__device__ __forceinline__ float sigmoidf_(float x) { return 1.f / (1.f + expf(-x)); }

__device__ __forceinline__ void group_barrier(int slot, unsigned G, unsigned& sense) {
    __syncthreads();
    sense ^= 1u;
    if (threadIdx.x == 0 && threadIdx.y == 0 && threadIdx.z == 0) {
        __threadfence();
        unsigned prev = atomicAdd(&g_cnt[slot * 32], 1u);
        if (prev == G - 1u) {
            g_cnt[slot * 32] = 0u;
            __threadfence();
            g_sns[slot * 32] = sense;
        } else {
            while (g_sns[slot * 32] != sense) { }
        }
        __threadfence();
    }
    __syncthreads();
}

// ---------------------------------------------------------------------------
// table[v, j] = sum_e emb[v,e] * W[e,j] + b0[j]
// ---------------------------------------------------------------------------
__global__ void build_table_kernel(const float* __restrict__ emb,
                                   const float* __restrict__ W,
                                   const float* __restrict__ b0,
                                   float* __restrict__ table,
                                   int N3) {
    int v = blockIdx.y;
    int j = blockIdx.x * blockDim.x + threadIdx.x;
    __shared__ float se[EMB];
    if (threadIdx.x < EMB) se[threadIdx.x] = emb[(size_t)v * EMB + threadIdx.x];
    __syncthreads();
    if (j < N3) {
        float acc = b0[j];
#pragma unroll 10
        for (int e = 0; e < EMB; ++e) acc += se[e] * W[(size_t)e * N3 + j];
        table[(size_t)v * N3 + j] = acc;
    }
}

// ---------------------------------------------------------------------------
// Ua [2000,6000] -> packed bf16 B fragments (hi/lo), fragment-major.
// ---------------------------------------------------------------------------
__global__ void prep_ua_frag(const float* __restrict__ Ua, uint4* __restrict__ dst) {
    size_t fp = (size_t)blockIdx.x * blockDim.x + threadIdx.x;
    if (fp >= (size_t)NBLK * NCH * 32) return;
    int l  = fp & 31;
    int kc = (int)((fp >> 5) % NCH);
    int nb = (int)((fp >> 5) / NCH);
    int n = nb * 8 + (l >> 2);
    int k = kc * 16 + 2 * (l & 3);
    float u0 = Ua[(size_t)k * N3V + n];
    float u1 = Ua[(size_t)(k + 1) * N3V + n];
    float u8 = Ua[(size_t)(k + 8) * N3V + n];
    float u9 = Ua[(size_t)(k + 9) * N3V + n];
    float h0 = bf_hi(u0), h1 = bf_hi(u1), h8 = bf_hi(u8), h9 = bf_hi(u9);
    uint4 v;
    v.x = pk_bf2(h0, h1);
    v.y = pk_bf2(h8, h9);
    v.z = pk_bf2(u0 - h0, u1 - h1);
    v.w = pk_bf2(u8 - h8, u9 - h9);
    dst[fp] = v;
}

// ---------------------------------------------------------------------------
// Persistent GRU (unchanged).
// ---------------------------------------------------------------------------
template <int H>
__global__ void __launch_bounds__(128, 1)
gru_seq_kernel(const float* __restrict__ xz,
               const int* __restrict__ tok,
               const float* __restrict__ U,
               const float* __restrict__ brec,
               float* __restrict__ hP, float* __restrict__ hQ,
               float* __restrict__ seq_out,
               const int* __restrict__ num_sent,
               int T) {
    extern __shared__ __align__(16) ull smu[];
    ull* su2 = smu;            // [H][48]
    ull* shd = smu + H * 48;   // [16][H]
    __shared__ ull sred[64 * 12];

    const int tx = threadIdx.x;
    const int ty = threadIdx.y;
    const int tz = threadIdx.z;
    const int tid64 = ty * 16 + tx;
    const int tid = tz * 64 + tid64;
    const int j0 = blockIdx.x * 32;
    const int b0 = blockIdx.y * 16;
    const int N3 = 3 * H;
    const int slot = blockIdx.y;
    const unsigned G = gridDim.x;
    unsigned sense = g_sns[slot * 32];

    for (int e = tid; e < H * 48; e += 128) {
        int k = e / 48, c = e - k * 48;
        int g = c >> 4, p = c & 15;
        int j = j0 + 2 * p;
        float lo = (j < H) ? U[(size_t)k * N3 + g * H + j] : 0.f;
        float hi = (j + 1 < H) ? U[(size_t)k * N3 + g * H + j + 1] : 0.f;
        su2[e] = pack2(lo, hi);
    }
    for (int e = tid; e < 16 * 32; e += 128) {
        int bb = e >> 5, jj = e & 31;
        if (j0 + jj < H) hP[(size_t)(b0 + bb) * H + j0 + jj] = 0.f;
    }
    group_barrier(slot, G, sense);

    float* hp = hP;
    float* hn = hQ;

    const int jA = j0 + 2 * tx;
    const int jB = jA + 1;
    float bzA = 0, brA = 0, bhA = 0, bzB = 0, brB = 0, bhB = 0;
    if (jA < H) { bzA = brec[jA]; brA = brec[H + jA]; bhA = brec[2 * H + jA]; }
    if (jB < H) { bzB = brec[jB]; brB = brec[H + jB]; bhB = brec[2 * H + jB]; }

    constexpr int Hh = H / 2;
    const int kBeg = tz * Hh;
    const ull* up = su2 + tx;

    for (int t = 0; t < T; ++t) {
        ull xzp[4], xrp[4], xhp[4];
        int padi[4];
        if (tz == 0 && jA < H) {
#pragma unroll
            for (int r = 0; r < 4; ++r) {
                const int b = b0 + 4 * ty + r;
                const float* xrow;
                if (tok) xrow = xz + (size_t)tok[(size_t)b * T + t] * N3;
                else     xrow = xz + ((size_t)b * T + t) * N3;
                xzp[r] = *reinterpret_cast<const ull*>(xrow + jA);
                xrp[r] = *reinterpret_cast<const ull*>(xrow + H + jA);
                xhp[r] = *reinterpret_cast<const ull*>(xrow + 2 * H + jA);
                padi[r] = num_sent ? num_sent[b] : 0x7fffffff;
            }
        }

        for (int e = tid; e < 16 * H; e += 128) {
            int row = e / H, k = e - row * H;
            shd[row * H + k] = pdup(hp[(size_t)(b0 + row) * H + k]);
        }
        __syncthreads();

        ull az[4] = {0,0,0,0}, ar[4] = {0,0,0,0}, ah[4] = {0,0,0,0};
        const ull* h0p = shd + (4 * ty + 0) * H + kBeg;
        const ull* h1p = shd + (4 * ty + 1) * H + kBeg;
        const ull* h2p = shd + (4 * ty + 2) * H + kBeg;
        const ull* h3p = shd + (4 * ty + 3) * H + kBeg;
        const ull* ub = up + kBeg * 48;
#pragma unroll 4
        for (int kk = 0; kk < Hh; ++kk) {
            ull uz = ub[kk * 48];
            ull ur = ub[kk * 48 + 16];
            ull uh = ub[kk * 48 + 32];
            ull h0 = h0p[kk], h1 = h1p[kk], h2 = h2p[kk], h3 = h3p[kk];
            fma2(az[0], h0, uz); fma2(az[1], h1, uz); fma2(az[2], h2, uz); fma2(az[3], h3, uz);
            fma2(ar[0], h0, ur); fma2(ar[1], h1, ur); fma2(ar[2], h2, ur); fma2(ar[3], h3, ur);
            fma2(ah[0], h0, uh); fma2(ah[1], h1, uh); fma2(ah[2], h2, uh); fma2(ah[3], h3, uh);
        }

        if (tz == 1) {
            ull* s = sred + tid64 * 12;
#pragma unroll
            for (int r = 0; r < 4; ++r) { s[r] = az[r]; s[4 + r] = ar[r]; s[8 + r] = ah[r]; }
        }
        __syncthreads();

        if (tz == 0) {
            const ull* s = sred + tid64 * 12;
#pragma unroll
            for (int r = 0; r < 4; ++r) { add2(az[r], s[r]); add2(ar[r], s[4 + r]); add2(ah[r], s[8 + r]); }

            if (jA < H) {
#pragma unroll
                for (int r = 0; r < 4; ++r) {
                    const int row = 4 * ty + r;
                    const int b = b0 + row;
                    float2 AZ = unpack2(az[r]);
                    float2 AR = unpack2(ar[r]);
                    float2 AH = unpack2(ah[r]);
                    float2 XZ = unpack2(xzp[r]);
                    float2 XR = unpack2(xrp[r]);
                    float2 XH = unpack2(xhp[r]);
                    float padv = (t <= padi[r]) ? 1.f : 0.f;
                    {
                        float z  = sigmoidf_(XZ.x + AZ.x + bzA);
                        float rr = sigmoidf_(XR.x + AR.x + brA);
                        float hh = tanhf(XH.x + rr * (AH.x + bhA));
                        float hprev = unpack2(shd[row * H + jA]).x;
                        float hnew = z * hprev + (1.f - z) * hh;
                        hn[(size_t)b * H + jA] = hnew;
                        seq_out[((size_t)b * T + t) * H + jA] = hnew * padv;
                    }
                    if (jB < H) {
                        float z  = sigmoidf_(XZ.y + AZ.y + bzB);
                        float rr = sigmoidf_(XR.y + AR.y + brB);
                        float hh = tanhf(XH.y + rr * (AH.y + bhB));
                        float hprev = unpack2(shd[row * H + jB]).x;
                        float hnew = z * hprev + (1.f - z) * hh;
                        hn[(size_t)b * H + jB] = hnew;
                        seq_out[((size_t)b * T + t) * H + jB] = hnew * padv;
                    }
                }
            }
        }
        group_barrier(slot, G, sense);
        float* tmp = hp; hp = hn; hn = tmp;
    }
}

// ---------------------------------------------------------------------------
// prod
// ---------------------------------------------------------------------------
__global__ void prod_kernel(const float* __restrict__ hinfo,
                            const float* __restrict__ hq,
                            const int* __restrict__ info_idx,
                            const int* __restrict__ num_sent,
                            const int* __restrict__ qidx,
                            float* __restrict__ prod) {
    const int nn = blockIdx.x;
    const int b  = blockIdx.y;
    const int si = info_idx[b * NSENT + nn];
    const int qi = qidx[b] - 1;
    const float padv = (nn <= num_sent[b]) ? 1.f : 0.f;
    const float* hi  = hinfo + ((size_t)b * SLEN + si) * RUN;
    const float* hqr = hq + ((size_t)b * QLEN + qi) * RUN;
    float* pr = prod + ((size_t)b * NSENT + nn) * RUN;
    for (int jj = threadIdx.x; jj < RUN; jj += blockDim.x)
        pr[jj] = hi[jj] * hqr[jj] * padv;
}

// ---------------------------------------------------------------------------
// Generic C = A@W + bias (xzm, xza)
// ---------------------------------------------------------------------------
__global__ void gemm_bias_kernel(const float* __restrict__ A,
                                 const float* __restrict__ W,
                                 const float* __restrict__ bias,
                                 float* __restrict__ C,
                                 int Mdim, int Kdim, int Ndim) {
    __shared__ __align__(16) float As[16][68];
    __shared__ __align__(16) float Bs[16][68];
    const int tid = threadIdx.x;
    const int tx = tid & 15;
    const int ty = tid >> 4;
    const int m0 = blockIdx.y * 64;
    const int n0 = blockIdx.x * 64;

    float acc[4][4];
#pragma unroll
    for (int i = 0; i < 4; ++i)
#pragma unroll
        for (int jj = 0; jj < 4; ++jj) acc[i][jj] = 0.f;

    for (int k0 = 0; k0 < Kdim; k0 += 16) {
        for (int e = tid; e < 1024; e += 256) {
            int mm = e >> 4, kk = e & 15;
            int m = m0 + mm, k = k0 + kk;
            As[kk][mm] = (m < Mdim && k < Kdim) ? A[(size_t)m * Kdim + k] : 0.f;
        }
        for (int e = tid; e < 1024; e += 256) {
            int kk = e >> 6, nn = e & 63;
            int k = k0 + kk, nv = n0 + nn;
            Bs[kk][nn] = (k < Kdim && nv < Ndim) ? W[(size_t)k * Ndim + nv] : 0.f;
        }
        __syncthreads();
#pragma unroll
        for (int kk = 0; kk < 16; ++kk) {
            float4 a4 = *reinterpret_cast<const float4*>(&As[kk][ty * 4]);
            float4 b4 = *reinterpret_cast<const float4*>(&Bs[kk][tx * 4]);
            float av[4] = {a4.x, a4.y, a4.z, a4.w};
            float bv[4] = {b4.x, b4.y, b4.z, b4.w};
#pragma unroll
            for (int i = 0; i < 4; ++i)
#pragma unroll
                for (int jj = 0; jj < 4; ++jj) acc[i][jj] += av[i] * bv[jj];
        }
        __syncthreads();
    }
#pragma unroll
    for (int i = 0; i < 4; ++i) {
        int m = m0 + ty * 4 + i;
        if (m >= Mdim) continue;
#pragma unroll
        for (int jj = 0; jj < 4; ++jj) {
            int nv = n0 + tx * 4 + jj;
            if (nv < Ndim) C[(size_t)m * Ndim + nv] = acc[i][jj] + bias[nv];
        }
    }
}

// ---------------------------------------------------------------------------
// Persistent answer GRU, HMMA bf16 hi/lo. grid = 128 CTAs x 256 thr.
// 125 gemm tiles (128m x 48n). B staged in SMEM (5 chunks of 25 kc, 76.8KB).
// A fragments built in phase B tail of the PREVIOUS step (2 barriers/step).
// ---------------------------------------------------------------------------
#define ANS_G     128
#define ANS_NT    125
#define ANS_SLOT  15
#define CHUNK_KC  25
#define NCHUNKS   5

__global__ void __launch_bounds__(256, 1)
answer_kernel(const float* __restrict__ xza,
              const float* __restrict__ ba1,
              float* __restrict__ rec,
              float* __restrict__ hP, float* __restrict__ hQ,
              float* __restrict__ out,
              const uint4* __restrict__ UaPk,
              uint4* __restrict__ hAHi,
              uint4* __restrict__ hALo) {
    extern __shared__ __align__(16) uint4 sB[];   // [CHUNK_KC*6*32] = 76800 B
    __shared__ float red[256];

    const int tid = threadIdx.x;
    const int wid = tid >> 5;
    const int lid = tid & 31;
    const unsigned G = gridDim.x;
    unsigned sense = g_sns[ANS_SLOT * 32];
    const bool gemm_cta = (blockIdx.x < ANS_NT);
    const int nbBase = blockIdx.x * 6;

    // init: zero h state and A fragments (h=0 -> frags 0)
    for (int e = blockIdx.x * 256 + tid; e < BATCH * VOC; e += G * 256)
        hP[e] = 0.f;
    {
        uint4 z4 = make_uint4(0, 0, 0, 0);
        for (int e = blockIdx.x * 256 + tid; e < 8 * NCH * 32; e += G * 256) {
            hAHi[e] = z4; hALo[e] = z4;
        }
    }
    group_barrier(ANS_SLOT, G, sense);

    float* hp = hP;
    float* hn = hQ;

    for (int n = 0; n < NSENT; ++n) {
        // ---- phase A: HMMA GEMM, B via SMEM, A frags from L2 ----
        if (gemm_cta) {
            const int mb = wid;
            float acc[6][4];
#pragma unroll
            for (int i = 0; i < 6; ++i)
#pragma unroll
                for (int c = 0; c < 4; ++c) acc[i][c] = 0.f;

            const uint4* AhBase = hAHi + (size_t)mb * NCH * 32 + lid;
            const uint4* AlBase = hALo + (size_t)mb * NCH * 32 + lid;

            for (int ch = 0; ch < NCHUNKS; ++ch) {
                const int kc0 = ch * CHUNK_KC;
                __syncthreads();
                // cooperative stage of B chunk: 25 kc x 6 nb x 32 lanes
                for (int e = tid; e < CHUNK_KC * 6 * 32; e += 256) {
                    int nb  = e / (CHUNK_KC * 32);
                    int rem = e - nb * (CHUNK_KC * 32);
                    int kc  = rem >> 5;
                    int l   = rem & 31;
                    sB[(kc * 6 + nb) * 32 + l] =
                        UaPk[((size_t)(nbBase + nb) * NCH + kc0 + kc) * 32 + l];
                }
                __syncthreads();

                uint4 a  = AhBase[(size_t)kc0 * 32];
                uint4 al = AlBase[(size_t)kc0 * 32];
                for (int kc = 0; kc < CHUNK_KC; ++kc) {
                    uint4 an, aln;
                    if (kc + 1 < CHUNK_KC) {
                        an  = AhBase[(size_t)(kc0 + kc + 1) * 32];
                        aln = AlBase[(size_t)(kc0 + kc + 1) * 32];
                    }
                    const uint4* bp = sB + kc * 192 + lid;
#pragma unroll
                    for (int nb = 0; nb < 6; ++nb) {
                        uint4 b = bp[nb * 32];
                        mma_bf16(acc[nb][0], acc[nb][1], acc[nb][2], acc[nb][3],
                                 a.x, a.y, a.z, a.w, b.x, b.y);       // Ahi*Bhi
                        mma_bf16(acc[nb][0], acc[nb][1], acc[nb][2], acc[nb][3],
                                 a.x, a.y, a.z, a.w, b.z, b.w);       // Ahi*Blo
                        mma_bf16(acc[nb][0], acc[nb][1], acc[nb][2], acc[nb][3],
                                 al.x, al.y, al.z, al.w, b.x, b.y);   // Alo*Bhi
                    }
                    if (kc + 1 < CHUNK_KC) { a = an; al = aln; }
                }
            }

            // epilogue: rec = acc + ba1
            const int r0 = mb * 16 + (lid >> 2);
#pragma unroll
            for (int nb = 0; nb < 6; ++nb) {
                int nc = (nbBase + nb) * 8 + 2 * (lid & 3);
                float b0 = ba1[nc], b1 = ba1[nc + 1];
                float2 v0 = { acc[nb][0] + b0, acc[nb][1] + b1 };
                float2 v1 = { acc[nb][2] + b0, acc[nb][3] + b1 };
                *reinterpret_cast<float2*>(rec + (size_t)r0 * N3V + nc) = v0;
                *reinterpret_cast<float2*>(rec + (size_t)(r0 + 8) * N3V + nc) = v1;
            }
        }
        group_barrier(ANS_SLOT, G, sense);

        // ---- phase B: gates + softmax + combine + A-frag build for next step ----
        {
            const int b = blockIdx.x;   // G == 128 == BATCH
            const float* xrow = xza + ((size_t)b * NSENT + n) * N3V;
            const float* rrow = rec + (size_t)b * N3V;
            float zv[8], tv[8];
            float m = -1e30f;
#pragma unroll
            for (int i = 0; i < 8; ++i) {
                int jj = tid + i * 256;
                if (jj < VOC) {
                    float z = sigmoidf_(xrow[jj] + rrow[jj]);
                    float r = sigmoidf_(xrow[VOC + jj] + rrow[VOC + jj]);
                    float t = xrow[2 * VOC + jj] + r * rrow[2 * VOC + jj];
                    zv[i] = z; tv[i] = t;
                    m = fmaxf(m, t);
                } else { zv[i] = 0.f; tv[i] = -1e30f; }
            }
            red[tid] = m; __syncthreads();
            for (int s = 128; s > 0; s >>= 1) {
                if (tid < s) red[tid] = fmaxf(red[tid], red[tid + s]);
                __syncthreads();
            }
            m = red[0]; __syncthreads();

            float ev[8];
            float sum = 0.f;
#pragma unroll
            for (int i = 0; i < 8; ++i) {
                int jj = tid + i * 256;
                if (jj < VOC) { ev[i] = expf(tv[i] - m); sum += ev[i]; }
                else ev[i] = 0.f;
            }
            red[tid] = sum; __syncthreads();
            for (int s = 128; s > 0; s >>= 1) {
                if (tid < s) red[tid] += red[tid + s];
                __syncthreads();
            }
            const float inv = 1.f / red[0];
            __syncthreads();

#pragma unroll
            for (int i = 0; i < 8; ++i) {
                int jj = tid + i * 256;
                if (jj < VOC) {
                    float hh = ev[i] * inv;
                    float z  = zv[i];
                    float hprev = hp[(size_t)b * VOC + jj];
                    float hnew = z * hprev + (1.f - z) * hh;
                    hn[(size_t)b * VOC + jj] = hnew;
                    out[((size_t)b * NSENT + n) * VOC + jj] = hnew;
                }
            }
            __syncthreads();   // hn[b,:] visible within CTA

            // A-frag build for next step: CTA b writes its row's components.
            // frag uint4 layout: .x=(r,c..c+1) .y=(r+8,c..c+1) .z=(r,c+8..c+9) .w=(r+8,...)
            {
                const int mb = b >> 4;
                const int rpos = b & 15;
                const int hiHalf = (rpos >> 3) & 1;   // 0: rows 0-7 (.x/.z), 1: rows 8-15 (.y/.w)
                const int rp = rpos & 7;
                const float* hrow = hn + (size_t)b * VOC;
                for (int e = tid; e < NCH * 8; e += 256) {   // 1000
                    int kc = e >> 3;
                    int rem = e & 7;
                    int j = rem >> 1;          // 0..3
                    int slot = rem & 1;        // 0: cols c, 1: cols c+8
                    int c = kc * 16 + 2 * j + 8 * slot;
                    float2 v = *reinterpret_cast<const float2*>(hrow + c);
                    float hx = bf_hi(v.x), hy = bf_hi(v.y);
                    uint32_t hiw = pk_bf2(hx, hy);
                    uint32_t low = pk_bf2(v.x - hx, v.y - hy);
                    size_t f = ((size_t)mb * NCH + kc) * 32 + 4 * rp + j;
                    int comp = (slot << 1) | hiHalf;
                    reinterpret_cast<uint32_t*>(&hAHi[f])[comp] = hiw;
                    reinterpret_cast<uint32_t*>(&hALo[f])[comp] = low;
                }
            }
        }
        group_barrier(ANS_SLOT, G, sense);
        float* tmp = hp; hp = hn; hn = tmp;
    }
}

// ---------------------------------------------------------------------------
// Host orchestration
// ---------------------------------------------------------------------------
extern "C" void kernel_launch(void* const* d_in, const int* in_sizes, int n_in,
                              void* d_out, int out_size) {
    const int*   info      = (const int*)d_in[0];
    const int*   info_idx  = (const int*)d_in[1];
    const int*   num_sent  = (const int*)d_in[2];
    const int*   question  = (const int*)d_in[3];
    const int*   qidx      = (const int*)d_in[4];
    const float* info_emb  = (const float*)d_in[5];
    const float* Wi        = (const float*)d_in[6];
    const float* Ui        = (const float*)d_in[7];
    const float* bi        = (const float*)d_in[8];
    const float* q_emb     = (const float*)d_in[9];
    const float* Wq        = (const float*)d_in[10];
    const float* Uq        = (const float*)d_in[11];
    const float* bq        = (const float*)d_in[12];
    const float* Wm        = (const float*)d_in[13];
    const float* Um        = (const float*)d_in[14];
    const float* bm        = (const float*)d_in[15];
    const float* Wa        = (const float*)d_in[16];
    const float* Ua        = (const float*)d_in[17];
    const float* ba        = (const float*)d_in[18];
    float* out = (float*)d_out;

    float *tbl_i, *tbl_q, *hinfo, *hq, *prod, *xzm, *hidden, *xza, *rec, *hA, *hB;
    uint4 *uaPk, *hAHi, *hALo;
    cudaGetSymbolAddress((void**)&tbl_i, g_table_i);
    cudaGetSymbolAddress((void**)&tbl_q, g_table_q);
    cudaGetSymbolAddress((void**)&hinfo, g_hinfo);
    cudaGetSymbolAddress((void**)&hq, g_hq);
    cudaGetSymbolAddress((void**)&prod, g_prod);
    cudaGetSymbolAddress((void**)&xzm, g_xzm);
    cudaGetSymbolAddress((void**)&hidden, g_hidden);
    cudaGetSymbolAddress((void**)&xza, g_xza);
    cudaGetSymbolAddress((void**)&rec, g_rec);
    cudaGetSymbolAddress((void**)&hA, g_hA);
    cudaGetSymbolAddress((void**)&hB, g_hB);
    cudaGetSymbolAddress((void**)&uaPk, g_UaPk);
    cudaGetSymbolAddress((void**)&hAHi, g_hAHi);
    cudaGetSymbolAddress((void**)&hALo, g_hALo);

    const size_t smemR = ((size_t)RUN * 48 + (size_t)16 * RUN) * 8;
    const size_t smemM = ((size_t)MEM * 48 + (size_t)16 * MEM) * 8;
    const size_t ansSmem = (size_t)CHUNK_KC * 6 * 32 * sizeof(uint4);   // 76800

    static bool attr_set = false;
    if (!attr_set) {
        cudaFuncSetAttribute(gru_seq_kernel<RUN>,
                             cudaFuncAttributeMaxDynamicSharedMemorySize, (int)smemR);
        cudaFuncSetAttribute(gru_seq_kernel<MEM>,
                             cudaFuncAttributeMaxDynamicSharedMemorySize, (int)smemM);
        cudaFuncSetAttribute(answer_kernel,
                             cudaFuncAttributeMaxDynamicSharedMemorySize, (int)ansSmem);
        attr_set = true;
    }

    const dim3 blk(16, 4, 2);

    build_table_kernel<<<dim3((3 * RUN + 255) / 256, 1024), 256>>>(info_emb, Wi, bi, tbl_i, 3 * RUN);
    build_table_kernel<<<dim3((3 * RUN + 255) / 256, 64), 256>>>(q_emb, Wq, bq, tbl_q, 3 * RUN);

    // Ua -> packed bf16 fragments
    {
        size_t F = (size_t)NBLK * NCH * 32;
        prep_ua_frag<<<(unsigned)((F + 255) / 256), 256>>>(Ua, uaPk);
    }

    // info GRU (T=1024, H=400)
    gru_seq_kernel<RUN><<<dim3((RUN + 31) / 32, 8), blk, smemR>>>(
        tbl_i, info, Ui, bi + 3 * RUN, hA, hB, hinfo, nullptr, SLEN);

    // question GRU (T=64, H=400)
    gru_seq_kernel<RUN><<<dim3((RUN + 31) / 32, 8), blk, smemR>>>(
        tbl_q, question, Uq, bq + 3 * RUN, hA, hB, hq, nullptr, QLEN);

    prod_kernel<<<dim3(NSENT, BATCH), 128>>>(hinfo, hq, info_idx, num_sent, qidx, prod);

    gemm_bias_kernel<<<dim3((3 * MEM + 63) / 64, (BATCH * NSENT) / 64), 256>>>(
        prod, Wm, bm, xzm, BATCH * NSENT, RUN, 3 * MEM);

    // memory GRU (T=64, H=300)
    gru_seq_kernel<MEM><<<dim3((MEM + 31) / 32, 8), blk, smemM>>>(
        xzm, nullptr, Um, bm + 3 * MEM, hA, hB, hidden, num_sent, NSENT);

    gemm_bias_kernel<<<dim3((N3V + 63) / 64, (BATCH * NSENT) / 64), 256>>>(
        hidden, Wa, ba, xza, BATCH * NSENT, MEM, N3V);

    answer_kernel<<<ANS_G, 256, ansSmem>>>(xza, ba + N3V, rec, hA, hB, out,
                                           uaPk, hAHi, hALo);
}

// round 13
// speedup vs baseline: 1.4342x; 1.0287x over previous
#include <cuda_runtime.h>
#include <cuda_bf16.h>
#include <cuda_fp16.h>
#include <cstdint>

#define BATCH 128
#define SLEN  1024
#define NSENT 64
#define QLEN  64
#define EMB   50
#define RUN   400
#define MEM   300
#define VOC   2000
#define N3V   (3 * VOC)      // 6000
#define NCH   125            // k16 chunks (2000/16)
#define NBLK  750            // n8 blocks (6000/8)

typedef unsigned long long ull;

__device__ __forceinline__ ull pack2(float lo, float hi) {
    ull r; asm("mov.b64 %0, {%1, %2};" : "=l"(r) : "f"(lo), "f"(hi)); return r;
}
__device__ __forceinline__ ull pdup(float v) { return pack2(v, v); }
__device__ __forceinline__ void fma2(ull& d, ull a, ull b) {
    asm("fma.rn.f32x2 %0, %1, %2, %0;" : "+l"(d) : "l"(a), "l"(b));
}
__device__ __forceinline__ void add2(ull& d, ull a) {
    asm("add.rn.f32x2 %0, %0, %1;" : "+l"(d) : "l"(a));
}
__device__ __forceinline__ float2 unpack2(ull v) {
    float2 r; asm("mov.b64 {%0, %1}, %2;" : "=f"(r.x), "=f"(r.y) : "l"(v)); return r;
}

// fp16 HMMA m16n8k16, f32 accum
__device__ __forceinline__ void mma_f16(float& c0, float& c1, float& c2, float& c3,
                                        uint32_t a0, uint32_t a1, uint32_t a2, uint32_t a3,
                                        uint32_t b0, uint32_t b1) {
    asm volatile(
        "mma.sync.aligned.m16n8k16.row.col.f32.f16.f16.f32 "
        "{%0,%1,%2,%3}, {%4,%5,%6,%7}, {%8,%9}, {%0,%1,%2,%3};"
        : "+f"(c0), "+f"(c1), "+f"(c2), "+f"(c3)
        : "r"(a0), "r"(a1), "r"(a2), "r"(a3), "r"(b0), "r"(b1));
}

__device__ __forceinline__ uint32_t pk_h2(float x, float y) {
    __half2 h = __floats2half2_rn(x, y);
    return *reinterpret_cast<uint32_t*>(&h);
}
__device__ __forceinline__ float h_hi(float v) {
    __half h = __float2half_rn(v);
    return __half2float(h);
}

// ---------------------------------------------------------------------------
// Device scratch
// ---------------------------------------------------------------------------
__device__ float g_table_i[1024 * 3 * RUN];
__device__ float g_table_q[64 * 3 * RUN];
__device__ float g_hinfo[(size_t)BATCH * SLEN * RUN];
__device__ float g_hq[(size_t)BATCH * QLEN * RUN];
__device__ float g_prod[(size_t)BATCH * NSENT * RUN];
__device__ float g_xzm[(size_t)BATCH * NSENT * 3 * MEM];
__device__ float g_hidden[(size_t)BATCH * NSENT * MEM];
__device__ float g_xza[(size_t)BATCH * NSENT * N3V];
__device__ float g_rec[(size_t)BATCH * N3V];
__device__ float g_hA[(size_t)BATCH * VOC];
__device__ float g_hB[(size_t)BATCH * VOC];
// B fragments: [NBLK][NCH][32] x uint4 (fp16: hi b0,b1 + lo b0,b1)
__device__ uint4 g_UaPk[(size_t)NBLK * NCH * 32];
// A fragments (fp16, single): [8 mblk][NCH][32] x uint4
__device__ uint4 g_hAPk[(size_t)8 * NCH * 32];

__device__ unsigned g_cnt[16 * 32];
__device__ volatile unsigned g_sns[16 * 32];

__device__ __forceinline__ float sigmoidf_(float x) { return 1.f / (1.f + expf(-x)); }

__device__ __forceinline__ void group_barrier(int slot, unsigned G, unsigned& sense) {
    __syncthreads();
    sense ^= 1u;
    if (threadIdx.x == 0 && threadIdx.y == 0 && threadIdx.z == 0) {
        __threadfence();
        unsigned prev = atomicAdd(&g_cnt[slot * 32], 1u);
        if (prev == G - 1u) {
            g_cnt[slot * 32] = 0u;
            __threadfence();
            g_sns[slot * 32] = sense;
        } else {
            while (g_sns[slot * 32] != sense) { }
        }
        __threadfence();
    }
    __syncthreads();
}

// ---------------------------------------------------------------------------
// table[v, j] = sum_e emb[v,e] * W[e,j] + b0[j]
// ---------------------------------------------------------------------------
__global__ void build_table_kernel(const float* __restrict__ emb,
                                   const float* __restrict__ W,
                                   const float* __restrict__ b0,
                                   float* __restrict__ table,
                                   int N3) {
    int v = blockIdx.y;
    int j = blockIdx.x * blockDim.x + threadIdx.x;
    __shared__ float se[EMB];
    if (threadIdx.x < EMB) se[threadIdx.x] = emb[(size_t)v * EMB + threadIdx.x];
    __syncthreads();
    if (j < N3) {
        float acc = b0[j];
#pragma unroll 10
        for (int e = 0; e < EMB; ++e) acc += se[e] * W[(size_t)e * N3 + j];
        table[(size_t)v * N3 + j] = acc;
    }
}

// ---------------------------------------------------------------------------
// Ua [2000,6000] -> packed fp16 B fragments (hi/lo), fragment-major.
// ---------------------------------------------------------------------------
__global__ void prep_ua_frag(const float* __restrict__ Ua, uint4* __restrict__ dst) {
    size_t fp = (size_t)blockIdx.x * blockDim.x + threadIdx.x;
    if (fp >= (size_t)NBLK * NCH * 32) return;
    int l  = fp & 31;
    int kc = (int)((fp >> 5) % NCH);
    int nb = (int)((fp >> 5) / NCH);
    int n = nb * 8 + (l >> 2);
    int k = kc * 16 + 2 * (l & 3);
    float u0 = Ua[(size_t)k * N3V + n];
    float u1 = Ua[(size_t)(k + 1) * N3V + n];
    float u8 = Ua[(size_t)(k + 8) * N3V + n];
    float u9 = Ua[(size_t)(k + 9) * N3V + n];
    float h0 = h_hi(u0), h1 = h_hi(u1), h8 = h_hi(u8), h9 = h_hi(u9);
    uint4 v;
    v.x = pk_h2(h0, h1);
    v.y = pk_h2(h8, h9);
    v.z = pk_h2(u0 - h0, u1 - h1);
    v.w = pk_h2(u8 - h8, u9 - h9);
    dst[fp] = v;
}

// ---------------------------------------------------------------------------
// Persistent GRU (unchanged).
// ---------------------------------------------------------------------------
template <int H>
__global__ void __launch_bounds__(128, 1)
gru_seq_kernel(const float* __restrict__ xz,
               const int* __restrict__ tok,
               const float* __restrict__ U,
               const float* __restrict__ brec,
               float* __restrict__ hP, float* __restrict__ hQ,
               float* __restrict__ seq_out,
               const int* __restrict__ num_sent,
               int T) {
    extern __shared__ __align__(16) ull smu[];
    ull* su2 = smu;            // [H][48]
    ull* shd = smu + H * 48;   // [16][H]
    __shared__ ull sred[64 * 12];

    const int tx = threadIdx.x;
    const int ty = threadIdx.y;
    const int tz = threadIdx.z;
    const int tid64 = ty * 16 + tx;
    const int tid = tz * 64 + tid64;
    const int j0 = blockIdx.x * 32;
    const int b0 = blockIdx.y * 16;
    const int N3 = 3 * H;
    const int slot = blockIdx.y;
    const unsigned G = gridDim.x;
    unsigned sense = g_sns[slot * 32];

    for (int e = tid; e < H * 48; e += 128) {
        int k = e / 48, c = e - k * 48;
        int g = c >> 4, p = c & 15;
        int j = j0 + 2 * p;
        float lo = (j < H) ? U[(size_t)k * N3 + g * H + j] : 0.f;
        float hi = (j + 1 < H) ? U[(size_t)k * N3 + g * H + j + 1] : 0.f;
        su2[e] = pack2(lo, hi);
    }
    for (int e = tid; e < 16 * 32; e += 128) {
        int bb = e >> 5, jj = e & 31;
        if (j0 + jj < H) hP[(size_t)(b0 + bb) * H + j0 + jj] = 0.f;
    }
    group_barrier(slot, G, sense);

    float* hp = hP;
    float* hn = hQ;

    const int jA = j0 + 2 * tx;
    const int jB = jA + 1;
    float bzA = 0, brA = 0, bhA = 0, bzB = 0, brB = 0, bhB = 0;
    if (jA < H) { bzA = brec[jA]; brA = brec[H + jA]; bhA = brec[2 * H + jA]; }
    if (jB < H) { bzB = brec[jB]; brB = brec[H + jB]; bhB = brec[2 * H + jB]; }

    constexpr int Hh = H / 2;
    const int kBeg = tz * Hh;
    const ull* up = su2 + tx;

    for (int t = 0; t < T; ++t) {
        ull xzp[4], xrp[4], xhp[4];
        int padi[4];
        if (tz == 0 && jA < H) {
#pragma unroll
            for (int r = 0; r < 4; ++r) {
                const int b = b0 + 4 * ty + r;
                const float* xrow;
                if (tok) xrow = xz + (size_t)tok[(size_t)b * T + t] * N3;
                else     xrow = xz + ((size_t)b * T + t) * N3;
                xzp[r] = *reinterpret_cast<const ull*>(xrow + jA);
                xrp[r] = *reinterpret_cast<const ull*>(xrow + H + jA);
                xhp[r] = *reinterpret_cast<const ull*>(xrow + 2 * H + jA);
                padi[r] = num_sent ? num_sent[b] : 0x7fffffff;
            }
        }

        for (int e = tid; e < 16 * H; e += 128) {
            int row = e / H, k = e - row * H;
            shd[row * H + k] = pdup(hp[(size_t)(b0 + row) * H + k]);
        }
        __syncthreads();

        ull az[4] = {0,0,0,0}, ar[4] = {0,0,0,0}, ah[4] = {0,0,0,0};
        const ull* h0p = shd + (4 * ty + 0) * H + kBeg;
        const ull* h1p = shd + (4 * ty + 1) * H + kBeg;
        const ull* h2p = shd + (4 * ty + 2) * H + kBeg;
        const ull* h3p = shd + (4 * ty + 3) * H + kBeg;
        const ull* ub = up + kBeg * 48;
#pragma unroll 4
        for (int kk = 0; kk < Hh; ++kk) {
            ull uz = ub[kk * 48];
            ull ur = ub[kk * 48 + 16];
            ull uh = ub[kk * 48 + 32];
            ull h0 = h0p[kk], h1 = h1p[kk], h2 = h2p[kk], h3 = h3p[kk];
            fma2(az[0], h0, uz); fma2(az[1], h1, uz); fma2(az[2], h2, uz); fma2(az[3], h3, uz);
            fma2(ar[0], h0, ur); fma2(ar[1], h1, ur); fma2(ar[2], h2, ur); fma2(ar[3], h3, ur);
            fma2(ah[0], h0, uh); fma2(ah[1], h1, uh); fma2(ah[2], h2, uh); fma2(ah[3], h3, uh);
        }

        if (tz == 1) {
            ull* s = sred + tid64 * 12;
#pragma unroll
            for (int r = 0; r < 4; ++r) { s[r] = az[r]; s[4 + r] = ar[r]; s[8 + r] = ah[r]; }
        }
        __syncthreads();

        if (tz == 0) {
            const ull* s = sred + tid64 * 12;
#pragma unroll
            for (int r = 0; r < 4; ++r) { add2(az[r], s[r]); add2(ar[r], s[4 + r]); add2(ah[r], s[8 + r]); }

            if (jA < H) {
#pragma unroll
                for (int r = 0; r < 4; ++r) {
                    const int row = 4 * ty + r;
                    const int b = b0 + row;
                    float2 AZ = unpack2(az[r]);
                    float2 AR = unpack2(ar[r]);
                    float2 AH = unpack2(ah[r]);
                    float2 XZ = unpack2(xzp[r]);
                    float2 XR = unpack2(xrp[r]);
                    float2 XH = unpack2(xhp[r]);
                    float padv = (t <= padi[r]) ? 1.f : 0.f;
                    {
                        float z  = sigmoidf_(XZ.x + AZ.x + bzA);
                        float rr = sigmoidf_(XR.x + AR.x + brA);
                        float hh = tanhf(XH.x + rr * (AH.x + bhA));
                        float hprev = unpack2(shd[row * H + jA]).x;
                        float hnew = z * hprev + (1.f - z) * hh;
                        hn[(size_t)b * H + jA] = hnew;
                        seq_out[((size_t)b * T + t) * H + jA] = hnew * padv;
                    }
                    if (jB < H) {
                        float z  = sigmoidf_(XZ.y + AZ.y + bzB);
                        float rr = sigmoidf_(XR.y + AR.y + brB);
                        float hh = tanhf(XH.y + rr * (AH.y + bhB));
                        float hprev = unpack2(shd[row * H + jB]).x;
                        float hnew = z * hprev + (1.f - z) * hh;
                        hn[(size_t)b * H + jB] = hnew;
                        seq_out[((size_t)b * T + t) * H + jB] = hnew * padv;
                    }
                }
            }
        }
        group_barrier(slot, G, sense);
        float* tmp = hp; hp = hn; hn = tmp;
    }
}

// ---------------------------------------------------------------------------
// prod
// ---------------------------------------------------------------------------
__global__ void prod_kernel(const float* __restrict__ hinfo,
                            const float* __restrict__ hq,
                            const int* __restrict__ info_idx,
                            const int* __restrict__ num_sent,
                            const int* __restrict__ qidx,
                            float* __restrict__ prod) {
    const int nn = blockIdx.x;
    const int b  = blockIdx.y;
    const int si = info_idx[b * NSENT + nn];
    const int qi = qidx[b] - 1;
    const float padv = (nn <= num_sent[b]) ? 1.f : 0.f;
    const float* hi  = hinfo + ((size_t)b * SLEN + si) * RUN;
    const float* hqr = hq + ((size_t)b * QLEN + qi) * RUN;
    float* pr = prod + ((size_t)b * NSENT + nn) * RUN;
    for (int jj = threadIdx.x; jj < RUN; jj += blockDim.x)
        pr[jj] = hi[jj] * hqr[jj] * padv;
}

// ---------------------------------------------------------------------------
// Generic C = A@W + bias (xzm, xza)
// ---------------------------------------------------------------------------
__global__ void gemm_bias_kernel(const float* __restrict__ A,
                                 const float* __restrict__ W,
                                 const float* __restrict__ bias,
                                 float* __restrict__ C,
                                 int Mdim, int Kdim, int Ndim) {
    __shared__ __align__(16) float As[16][68];
    __shared__ __align__(16) float Bs[16][68];
    const int tid = threadIdx.x;
    const int tx = tid & 15;
    const int ty = tid >> 4;
    const int m0 = blockIdx.y * 64;
    const int n0 = blockIdx.x * 64;

    float acc[4][4];
#pragma unroll
    for (int i = 0; i < 4; ++i)
#pragma unroll
        for (int jj = 0; jj < 4; ++jj) acc[i][jj] = 0.f;

    for (int k0 = 0; k0 < Kdim; k0 += 16) {
        for (int e = tid; e < 1024; e += 256) {
            int mm = e >> 4, kk = e & 15;
            int m = m0 + mm, k = k0 + kk;
            As[kk][mm] = (m < Mdim && k < Kdim) ? A[(size_t)m * Kdim + k] : 0.f;
        }
        for (int e = tid; e < 1024; e += 256) {
            int kk = e >> 6, nn = e & 63;
            int k = k0 + kk, nv = n0 + nn;
            Bs[kk][nn] = (k < Kdim && nv < Ndim) ? W[(size_t)k * Ndim + nv] : 0.f;
        }
        __syncthreads();
#pragma unroll
        for (int kk = 0; kk < 16; ++kk) {
            float4 a4 = *reinterpret_cast<const float4*>(&As[kk][ty * 4]);
            float4 b4 = *reinterpret_cast<const float4*>(&Bs[kk][tx * 4]);
            float av[4] = {a4.x, a4.y, a4.z, a4.w};
            float bv[4] = {b4.x, b4.y, b4.z, b4.w};
#pragma unroll
            for (int i = 0; i < 4; ++i)
#pragma unroll
                for (int jj = 0; jj < 4; ++jj) acc[i][jj] += av[i] * bv[jj];
        }
        __syncthreads();
    }
#pragma unroll
    for (int i = 0; i < 4; ++i) {
        int m = m0 + ty * 4 + i;
        if (m >= Mdim) continue;
#pragma unroll
        for (int jj = 0; jj < 4; ++jj) {
            int nv = n0 + tx * 4 + jj;
            if (nv < Ndim) C[(size_t)m * Ndim + nv] = acc[i][jj] + bias[nv];
        }
    }
}

// ---------------------------------------------------------------------------
// Persistent answer GRU, fp16 HMMA (A fp16, B fp16 hi/lo, 2 MMAs).
// grid = 128 CTAs x 256 thr. 125 gemm tiles (128m x 48n).
// B staged in SMEM (5 chunks of 25 kc). A frags built in phase B tail.
// ---------------------------------------------------------------------------
#define ANS_G     128
#define ANS_NT    125
#define ANS_SLOT  15
#define CHUNK_KC  25
#define NCHUNKS   5

__global__ void __launch_bounds__(256, 1)
answer_kernel(const float* __restrict__ xza,
              const float* __restrict__ ba1,
              float* __restrict__ rec,
              float* __restrict__ hP, float* __restrict__ hQ,
              float* __restrict__ out,
              const uint4* __restrict__ UaPk,
              uint4* __restrict__ hAPk) {
    extern __shared__ __align__(16) uint4 sB[];   // [CHUNK_KC*6*32] = 76800 B
    __shared__ float red[256];

    const int tid = threadIdx.x;
    const int wid = tid >> 5;
    const int lid = tid & 31;
    const unsigned G = gridDim.x;
    unsigned sense = g_sns[ANS_SLOT * 32];
    const bool gemm_cta = (blockIdx.x < ANS_NT);
    const int nbBase = blockIdx.x * 6;

    // init: zero h state and A fragments
    for (int e = blockIdx.x * 256 + tid; e < BATCH * VOC; e += G * 256)
        hP[e] = 0.f;
    {
        uint4 z4 = make_uint4(0, 0, 0, 0);
        for (int e = blockIdx.x * 256 + tid; e < 8 * NCH * 32; e += G * 256)
            hAPk[e] = z4;
    }
    group_barrier(ANS_SLOT, G, sense);

    float* hp = hP;
    float* hn = hQ;

    for (int n = 0; n < NSENT; ++n) {
        // ---- phase A: HMMA GEMM, B via SMEM, A frags from L2 (2-deep prefetch) ----
        if (gemm_cta) {
            const int mb = wid;
            float acc[6][4];
#pragma unroll
            for (int i = 0; i < 6; ++i)
#pragma unroll
                for (int c = 0; c < 4; ++c) acc[i][c] = 0.f;

            const uint4* ABase = hAPk + (size_t)mb * NCH * 32 + lid;

            for (int ch = 0; ch < NCHUNKS; ++ch) {
                const int kc0 = ch * CHUNK_KC;
                __syncthreads();
                // cooperative stage of B chunk: 25 kc x 6 nb x 32 lanes
                for (int e = tid; e < CHUNK_KC * 6 * 32; e += 256) {
                    int nb  = e / (CHUNK_KC * 32);
                    int rem = e - nb * (CHUNK_KC * 32);
                    int kc  = rem >> 5;
                    int l   = rem & 31;
                    sB[(kc * 6 + nb) * 32 + l] =
                        UaPk[((size_t)(nbBase + nb) * NCH + kc0 + kc) * 32 + l];
                }
                __syncthreads();

                // 2-deep A prefetch
                uint4 aq0 = ABase[(size_t)kc0 * 32];
                uint4 aq1 = ABase[(size_t)(kc0 + 1) * 32];
                for (int kc = 0; kc < CHUNK_KC; ++kc) {
                    uint4 a = aq0;
                    aq0 = aq1;
                    if (kc + 2 < CHUNK_KC)
                        aq1 = ABase[(size_t)(kc0 + kc + 2) * 32];
                    const uint4* bp = sB + kc * 192 + lid;
#pragma unroll
                    for (int nb = 0; nb < 6; ++nb) {
                        uint4 b = bp[nb * 32];
                        mma_f16(acc[nb][0], acc[nb][1], acc[nb][2], acc[nb][3],
                                a.x, a.y, a.z, a.w, b.x, b.y);       // A*Bhi
                        mma_f16(acc[nb][0], acc[nb][1], acc[nb][2], acc[nb][3],
                                a.x, a.y, a.z, a.w, b.z, b.w);       // A*Blo
                    }
                }
            }

            // epilogue: rec = acc + ba1
            const int r0 = mb * 16 + (lid >> 2);
#pragma unroll
            for (int nb = 0; nb < 6; ++nb) {
                int nc = (nbBase + nb) * 8 + 2 * (lid & 3);
                float b0 = ba1[nc], b1 = ba1[nc + 1];
                float2 v0 = { acc[nb][0] + b0, acc[nb][1] + b1 };
                float2 v1 = { acc[nb][2] + b0, acc[nb][3] + b1 };
                *reinterpret_cast<float2*>(rec + (size_t)r0 * N3V + nc) = v0;
                *reinterpret_cast<float2*>(rec + (size_t)(r0 + 8) * N3V + nc) = v1;
            }
        }
        group_barrier(ANS_SLOT, G, sense);

        // ---- phase B: gates + softmax + combine + A-frag build for next step ----
        {
            const int b = blockIdx.x;   // G == 128 == BATCH
            const float* xrow = xza + ((size_t)b * NSENT + n) * N3V;
            const float* rrow = rec + (size_t)b * N3V;
            float zv[8], tv[8];
            float m = -1e30f;
#pragma unroll
            for (int i = 0; i < 8; ++i) {
                int jj = tid + i * 256;
                if (jj < VOC) {
                    float z = sigmoidf_(xrow[jj] + rrow[jj]);
                    float r = sigmoidf_(xrow[VOC + jj] + rrow[VOC + jj]);
                    float t = xrow[2 * VOC + jj] + r * rrow[2 * VOC + jj];
                    zv[i] = z; tv[i] = t;
                    m = fmaxf(m, t);
                } else { zv[i] = 0.f; tv[i] = -1e30f; }
            }
            red[tid] = m; __syncthreads();
            for (int s = 128; s > 0; s >>= 1) {
                if (tid < s) red[tid] = fmaxf(red[tid], red[tid + s]);
                __syncthreads();
            }
            m = red[0]; __syncthreads();

            float ev[8];
            float sum = 0.f;
#pragma unroll
            for (int i = 0; i < 8; ++i) {
                int jj = tid + i * 256;
                if (jj < VOC) { ev[i] = expf(tv[i] - m); sum += ev[i]; }
                else ev[i] = 0.f;
            }
            red[tid] = sum; __syncthreads();
            for (int s = 128; s > 0; s >>= 1) {
                if (tid < s) red[tid] += red[tid + s];
                __syncthreads();
            }
            const float inv = 1.f / red[0];
            __syncthreads();

#pragma unroll
            for (int i = 0; i < 8; ++i) {
                int jj = tid + i * 256;
                if (jj < VOC) {
                    float hh = ev[i] * inv;
                    float z  = zv[i];
                    float hprev = hp[(size_t)b * VOC + jj];
                    float hnew = z * hprev + (1.f - z) * hh;
                    hn[(size_t)b * VOC + jj] = hnew;
                    out[((size_t)b * NSENT + n) * VOC + jj] = hnew;
                }
            }
            __syncthreads();   // hn[b,:] visible within CTA

            // A-frag build (fp16 single) for next step: CTA b writes its row.
            // frag uint4: .x=(r,c..c+1) .y=(r+8,c..c+1) .z=(r,c+8..c+9) .w=(r+8,...)
            {
                const int mb = b >> 4;
                const int rpos = b & 15;
                const int hiHalf = (rpos >> 3) & 1;
                const int rp = rpos & 7;
                const float* hrow = hn + (size_t)b * VOC;
                for (int e = tid; e < NCH * 8; e += 256) {   // 1000
                    int kc = e >> 3;
                    int rem = e & 7;
                    int j = rem >> 1;
                    int slot = rem & 1;
                    int c = kc * 16 + 2 * j + 8 * slot;
                    float2 v = *reinterpret_cast<const float2*>(hrow + c);
                    uint32_t w = pk_h2(v.x, v.y);
                    size_t f = ((size_t)mb * NCH + kc) * 32 + 4 * rp + j;
                    int comp = (slot << 1) | hiHalf;
                    reinterpret_cast<uint32_t*>(&hAPk[f])[comp] = w;
                }
            }
        }
        group_barrier(ANS_SLOT, G, sense);
        float* tmp = hp; hp = hn; hn = tmp;
    }
}

// ---------------------------------------------------------------------------
// Host orchestration
// ---------------------------------------------------------------------------
extern "C" void kernel_launch(void* const* d_in, const int* in_sizes, int n_in,
                              void* d_out, int out_size) {
    const int*   info      = (const int*)d_in[0];
    const int*   info_idx  = (const int*)d_in[1];
    const int*   num_sent  = (const int*)d_in[2];
    const int*   question  = (const int*)d_in[3];
    const int*   qidx      = (const int*)d_in[4];
    const float* info_emb  = (const float*)d_in[5];
    const float* Wi        = (const float*)d_in[6];
    const float* Ui        = (const float*)d_in[7];
    const float* bi        = (const float*)d_in[8];
    const float* q_emb     = (const float*)d_in[9];
    const float* Wq        = (const float*)d_in[10];
    const float* Uq        = (const float*)d_in[11];
    const float* bq        = (const float*)d_in[12];
    const float* Wm        = (const float*)d_in[13];
    const float* Um        = (const float*)d_in[14];
    const float* bm        = (const float*)d_in[15];
    const float* Wa        = (const float*)d_in[16];
    const float* Ua        = (const float*)d_in[17];
    const float* ba        = (const float*)d_in[18];
    float* out = (float*)d_out;

    float *tbl_i, *tbl_q, *hinfo, *hq, *prod, *xzm, *hidden, *xza, *rec, *hA, *hB;
    uint4 *uaPk, *hAPk;
    cudaGetSymbolAddress((void**)&tbl_i, g_table_i);
    cudaGetSymbolAddress((void**)&tbl_q, g_table_q);
    cudaGetSymbolAddress((void**)&hinfo, g_hinfo);
    cudaGetSymbolAddress((void**)&hq, g_hq);
    cudaGetSymbolAddress((void**)&prod, g_prod);
    cudaGetSymbolAddress((void**)&xzm, g_xzm);
    cudaGetSymbolAddress((void**)&hidden, g_hidden);
    cudaGetSymbolAddress((void**)&xza, g_xza);
    cudaGetSymbolAddress((void**)&rec, g_rec);
    cudaGetSymbolAddress((void**)&hA, g_hA);
    cudaGetSymbolAddress((void**)&hB, g_hB);
    cudaGetSymbolAddress((void**)&uaPk, g_UaPk);
    cudaGetSymbolAddress((void**)&hAPk, g_hAPk);

    const size_t smemR = ((size_t)RUN * 48 + (size_t)16 * RUN) * 8;
    const size_t smemM = ((size_t)MEM * 48 + (size_t)16 * MEM) * 8;
    const size_t ansSmem = (size_t)CHUNK_KC * 6 * 32 * sizeof(uint4);   // 76800

    static bool attr_set = false;
    if (!attr_set) {
        cudaFuncSetAttribute(gru_seq_kernel<RUN>,
                             cudaFuncAttributeMaxDynamicSharedMemorySize, (int)smemR);
        cudaFuncSetAttribute(gru_seq_kernel<MEM>,
                             cudaFuncAttributeMaxDynamicSharedMemorySize, (int)smemM);
        cudaFuncSetAttribute(answer_kernel,
                             cudaFuncAttributeMaxDynamicSharedMemorySize, (int)ansSmem);
        attr_set = true;
    }

    const dim3 blk(16, 4, 2);

    build_table_kernel<<<dim3((3 * RUN + 255) / 256, 1024), 256>>>(info_emb, Wi, bi, tbl_i, 3 * RUN);
    build_table_kernel<<<dim3((3 * RUN + 255) / 256, 64), 256>>>(q_emb, Wq, bq, tbl_q, 3 * RUN);

    // Ua -> packed fp16 fragments
    {
        size_t F = (size_t)NBLK * NCH * 32;
        prep_ua_frag<<<(unsigned)((F + 255) / 256), 256>>>(Ua, uaPk);
    }

    // info GRU (T=1024, H=400)
    gru_seq_kernel<RUN><<<dim3((RUN + 31) / 32, 8), blk, smemR>>>(
        tbl_i, info, Ui, bi + 3 * RUN, hA, hB, hinfo, nullptr, SLEN);

    // question GRU (T=64, H=400)
    gru_seq_kernel<RUN><<<dim3((RUN + 31) / 32, 8), blk, smemR>>>(
        tbl_q, question, Uq, bq + 3 * RUN, hA, hB, hq, nullptr, QLEN);

    prod_kernel<<<dim3(NSENT, BATCH), 128>>>(hinfo, hq, info_idx, num_sent, qidx, prod);

    gemm_bias_kernel<<<dim3((3 * MEM + 63) / 64, (BATCH * NSENT) / 64), 256>>>(
        prod, Wm, bm, xzm, BATCH * NSENT, RUN, 3 * MEM);

    // memory GRU (T=64, H=300)
    gru_seq_kernel<MEM><<<dim3((MEM + 31) / 32, 8), blk, smemM>>>(
        xzm, nullptr, Um, bm + 3 * MEM, hA, hB, hidden, num_sent, NSENT);

    gemm_bias_kernel<<<dim3((N3V + 63) / 64, (BATCH * NSENT) / 64), 256>>>(
        hidden, Wa, ba, xza, BATCH * NSENT, MEM, N3V);

    answer_kernel<<<ANS_G, 256, ansSmem>>>(xza, ba + N3V, rec, hA, hB, out,
                                           uaPk, hAPk);
}

// round 14
// speedup vs baseline: 1.4437x; 1.0066x over previous
#include <cuda_runtime.h>
#include <cuda_bf16.h>
#include <cuda_fp16.h>
#include <cstdint>

#define BATCH 128
#define SLEN  1024
#define NSENT 64
#define QLEN  64
#define EMB   50
#define RUN   400
#define MEM   300
#define VOC   2000
#define N3V   (3 * VOC)      // 6000
#define NCH   125            // k16 chunks (2000/16)
#define NBLK  750            // n8 blocks (6000/8)

typedef unsigned long long ull;

__device__ __forceinline__ ull pack2(float lo, float hi) {
    ull r; asm("mov.b64 %0, {%1, %2};" : "=l"(r) : "f"(lo), "f"(hi)); return r;
}
__device__ __forceinline__ ull pdup(float v) { return pack2(v, v); }
__device__ __forceinline__ void fma2(ull& d, ull a, ull b) {
    asm("fma.rn.f32x2 %0, %1, %2, %0;" : "+l"(d) : "l"(a), "l"(b));
}
__device__ __forceinline__ void add2(ull& d, ull a) {
    asm("add.rn.f32x2 %0, %0, %1;" : "+l"(d) : "l"(a));
}
__device__ __forceinline__ float2 unpack2(ull v) {
    float2 r; asm("mov.b64 {%0, %1}, %2;" : "=f"(r.x), "=f"(r.y) : "l"(v)); return r;
}

// fp16 HMMA m16n8k16, f32 accum
__device__ __forceinline__ void mma_f16(float& c0, float& c1, float& c2, float& c3,
                                        uint32_t a0, uint32_t a1, uint32_t a2, uint32_t a3,
                                        uint32_t b0, uint32_t b1) {
    asm volatile(
        "mma.sync.aligned.m16n8k16.row.col.f32.f16.f16.f32 "
        "{%0,%1,%2,%3}, {%4,%5,%6,%7}, {%8,%9}, {%0,%1,%2,%3};"
        : "+f"(c0), "+f"(c1), "+f"(c2), "+f"(c3)
        : "r"(a0), "r"(a1), "r"(a2), "r"(a3), "r"(b0), "r"(b1));
}

__device__ __forceinline__ uint32_t pk_h2(float x, float y) {
    __half2 h = __floats2half2_rn(x, y);
    return *reinterpret_cast<uint32_t*>(&h);
}
__device__ __forceinline__ float h_hi(float v) {
    __half h = __float2half_rn(v);
    return __half2float(h);
}

// ---------------------------------------------------------------------------
// Device scratch
// ---------------------------------------------------------------------------
__device__ float g_table_i[1024 * 3 * RUN];
__device__ float g_table_q[64 * 3 * RUN];
__device__ float g_hinfo[(size_t)BATCH * SLEN * RUN];
__device__ float g_hq[(size_t)BATCH * QLEN * RUN];
__device__ float g_prod[(size_t)BATCH * NSENT * RUN];
__device__ float g_xzm[(size_t)BATCH * NSENT * 3 * MEM];
__device__ float g_hidden[(size_t)BATCH * NSENT * MEM];
__device__ float g_xza[(size_t)BATCH * NSENT * N3V];
__device__ float g_rec[(size_t)BATCH * N3V];
__device__ float g_hA[(size_t)BATCH * VOC];
__device__ float g_hB[(size_t)BATCH * VOC];
// B fragments: [NBLK][NCH][32] x uint4 (fp16: hi b0,b1 + lo b0,b1)
__device__ uint4 g_UaPk[(size_t)NBLK * NCH * 32];
// A fragments (fp16): [8 mblk][NCH][32] x uint4
__device__ uint4 g_hAPk[(size_t)8 * NCH * 32];

__device__ unsigned g_cnt[16 * 32];
__device__ volatile unsigned g_sns[16 * 32];

__device__ __forceinline__ float sigmoidf_(float x) { return 1.f / (1.f + expf(-x)); }

__device__ __forceinline__ void group_barrier(int slot, unsigned G, unsigned& sense) {
    __syncthreads();
    sense ^= 1u;
    if (threadIdx.x == 0 && threadIdx.y == 0 && threadIdx.z == 0) {
        __threadfence();
        unsigned prev = atomicAdd(&g_cnt[slot * 32], 1u);
        if (prev == G - 1u) {
            g_cnt[slot * 32] = 0u;
            __threadfence();
            g_sns[slot * 32] = sense;
        } else {
            while (g_sns[slot * 32] != sense) { }
        }
        __threadfence();
    }
    __syncthreads();
}

// ---------------------------------------------------------------------------
// table build
// ---------------------------------------------------------------------------
__global__ void build_table_kernel(const float* __restrict__ emb,
                                   const float* __restrict__ W,
                                   const float* __restrict__ b0,
                                   float* __restrict__ table,
                                   int N3) {
    int v = blockIdx.y;
    int j = blockIdx.x * blockDim.x + threadIdx.x;
    __shared__ float se[EMB];
    if (threadIdx.x < EMB) se[threadIdx.x] = emb[(size_t)v * EMB + threadIdx.x];
    __syncthreads();
    if (j < N3) {
        float acc = b0[j];
#pragma unroll 10
        for (int e = 0; e < EMB; ++e) acc += se[e] * W[(size_t)e * N3 + j];
        table[(size_t)v * N3 + j] = acc;
    }
}

// ---------------------------------------------------------------------------
// Ua -> packed fp16 B fragments (hi/lo), fragment-major.
// ---------------------------------------------------------------------------
__global__ void prep_ua_frag(const float* __restrict__ Ua, uint4* __restrict__ dst) {
    size_t fp = (size_t)blockIdx.x * blockDim.x + threadIdx.x;
    if (fp >= (size_t)NBLK * NCH * 32) return;
    int l  = fp & 31;
    int kc = (int)((fp >> 5) % NCH);
    int nb = (int)((fp >> 5) / NCH);
    int n = nb * 8 + (l >> 2);
    int k = kc * 16 + 2 * (l & 3);
    float u0 = Ua[(size_t)k * N3V + n];
    float u1 = Ua[(size_t)(k + 1) * N3V + n];
    float u8 = Ua[(size_t)(k + 8) * N3V + n];
    float u9 = Ua[(size_t)(k + 9) * N3V + n];
    float h0 = h_hi(u0), h1 = h_hi(u1), h8 = h_hi(u8), h9 = h_hi(u9);
    uint4 v;
    v.x = pk_h2(h0, h1);
    v.y = pk_h2(h8, h9);
    v.z = pk_h2(u0 - h0, u1 - h1);
    v.w = pk_h2(u8 - h8, u9 - h9);
    dst[fp] = v;
}

// ---------------------------------------------------------------------------
// Persistent GRU (unchanged).
// ---------------------------------------------------------------------------
template <int H>
__global__ void __launch_bounds__(128, 1)
gru_seq_kernel(const float* __restrict__ xz,
               const int* __restrict__ tok,
               const float* __restrict__ U,
               const float* __restrict__ brec,
               float* __restrict__ hP, float* __restrict__ hQ,
               float* __restrict__ seq_out,
               const int* __restrict__ num_sent,
               int T) {
    extern __shared__ __align__(16) ull smu[];
    ull* su2 = smu;            // [H][48]
    ull* shd = smu + H * 48;   // [16][H]
    __shared__ ull sred[64 * 12];

    const int tx = threadIdx.x;
    const int ty = threadIdx.y;
    const int tz = threadIdx.z;
    const int tid64 = ty * 16 + tx;
    const int tid = tz * 64 + tid64;
    const int j0 = blockIdx.x * 32;
    const int b0 = blockIdx.y * 16;
    const int N3 = 3 * H;
    const int slot = blockIdx.y;
    const unsigned G = gridDim.x;
    unsigned sense = g_sns[slot * 32];

    for (int e = tid; e < H * 48; e += 128) {
        int k = e / 48, c = e - k * 48;
        int g = c >> 4, p = c & 15;
        int j = j0 + 2 * p;
        float lo = (j < H) ? U[(size_t)k * N3 + g * H + j] : 0.f;
        float hi = (j + 1 < H) ? U[(size_t)k * N3 + g * H + j + 1] : 0.f;
        su2[e] = pack2(lo, hi);
    }
    for (int e = tid; e < 16 * 32; e += 128) {
        int bb = e >> 5, jj = e & 31;
        if (j0 + jj < H) hP[(size_t)(b0 + bb) * H + j0 + jj] = 0.f;
    }
    group_barrier(slot, G, sense);

    float* hp = hP;
    float* hn = hQ;

    const int jA = j0 + 2 * tx;
    const int jB = jA + 1;
    float bzA = 0, brA = 0, bhA = 0, bzB = 0, brB = 0, bhB = 0;
    if (jA < H) { bzA = brec[jA]; brA = brec[H + jA]; bhA = brec[2 * H + jA]; }
    if (jB < H) { bzB = brec[jB]; brB = brec[H + jB]; bhB = brec[2 * H + jB]; }

    constexpr int Hh = H / 2;
    const int kBeg = tz * Hh;
    const ull* up = su2 + tx;

    for (int t = 0; t < T; ++t) {
        ull xzp[4], xrp[4], xhp[4];
        int padi[4];
        if (tz == 0 && jA < H) {
#pragma unroll
            for (int r = 0; r < 4; ++r) {
                const int b = b0 + 4 * ty + r;
                const float* xrow;
                if (tok) xrow = xz + (size_t)tok[(size_t)b * T + t] * N3;
                else     xrow = xz + ((size_t)b * T + t) * N3;
                xzp[r] = *reinterpret_cast<const ull*>(xrow + jA);
                xrp[r] = *reinterpret_cast<const ull*>(xrow + H + jA);
                xhp[r] = *reinterpret_cast<const ull*>(xrow + 2 * H + jA);
                padi[r] = num_sent ? num_sent[b] : 0x7fffffff;
            }
        }

        for (int e = tid; e < 16 * H; e += 128) {
            int row = e / H, k = e - row * H;
            shd[row * H + k] = pdup(hp[(size_t)(b0 + row) * H + k]);
        }
        __syncthreads();

        ull az[4] = {0,0,0,0}, ar[4] = {0,0,0,0}, ah[4] = {0,0,0,0};
        const ull* h0p = shd + (4 * ty + 0) * H + kBeg;
        const ull* h1p = shd + (4 * ty + 1) * H + kBeg;
        const ull* h2p = shd + (4 * ty + 2) * H + kBeg;
        const ull* h3p = shd + (4 * ty + 3) * H + kBeg;
        const ull* ub = up + kBeg * 48;
#pragma unroll 4
        for (int kk = 0; kk < Hh; ++kk) {
            ull uz = ub[kk * 48];
            ull ur = ub[kk * 48 + 16];
            ull uh = ub[kk * 48 + 32];
            ull h0 = h0p[kk], h1 = h1p[kk], h2 = h2p[kk], h3 = h3p[kk];
            fma2(az[0], h0, uz); fma2(az[1], h1, uz); fma2(az[2], h2, uz); fma2(az[3], h3, uz);
            fma2(ar[0], h0, ur); fma2(ar[1], h1, ur); fma2(ar[2], h2, ur); fma2(ar[3], h3, ur);
            fma2(ah[0], h0, uh); fma2(ah[1], h1, uh); fma2(ah[2], h2, uh); fma2(ah[3], h3, uh);
        }

        if (tz == 1) {
            ull* s = sred + tid64 * 12;
#pragma unroll
            for (int r = 0; r < 4; ++r) { s[r] = az[r]; s[4 + r] = ar[r]; s[8 + r] = ah[r]; }
        }
        __syncthreads();

        if (tz == 0) {
            const ull* s = sred + tid64 * 12;
#pragma unroll
            for (int r = 0; r < 4; ++r) { add2(az[r], s[r]); add2(ar[r], s[4 + r]); add2(ah[r], s[8 + r]); }

            if (jA < H) {
#pragma unroll
                for (int r = 0; r < 4; ++r) {
                    const int row = 4 * ty + r;
                    const int b = b0 + row;
                    float2 AZ = unpack2(az[r]);
                    float2 AR = unpack2(ar[r]);
                    float2 AH = unpack2(ah[r]);
                    float2 XZ = unpack2(xzp[r]);
                    float2 XR = unpack2(xrp[r]);
                    float2 XH = unpack2(xhp[r]);
                    float padv = (t <= padi[r]) ? 1.f : 0.f;
                    {
                        float z  = sigmoidf_(XZ.x + AZ.x + bzA);
                        float rr = sigmoidf_(XR.x + AR.x + brA);
                        float hh = tanhf(XH.x + rr * (AH.x + bhA));
                        float hprev = unpack2(shd[row * H + jA]).x;
                        float hnew = z * hprev + (1.f - z) * hh;
                        hn[(size_t)b * H + jA] = hnew;
                        seq_out[((size_t)b * T + t) * H + jA] = hnew * padv;
                    }
                    if (jB < H) {
                        float z  = sigmoidf_(XZ.y + AZ.y + bzB);
                        float rr = sigmoidf_(XR.y + AR.y + brB);
                        float hh = tanhf(XH.y + rr * (AH.y + bhB));
                        float hprev = unpack2(shd[row * H + jB]).x;
                        float hnew = z * hprev + (1.f - z) * hh;
                        hn[(size_t)b * H + jB] = hnew;
                        seq_out[((size_t)b * T + t) * H + jB] = hnew * padv;
                    }
                }
            }
        }
        group_barrier(slot, G, sense);
        float* tmp = hp; hp = hn; hn = tmp;
    }
}

// ---------------------------------------------------------------------------
// prod
// ---------------------------------------------------------------------------
__global__ void prod_kernel(const float* __restrict__ hinfo,
                            const float* __restrict__ hq,
                            const int* __restrict__ info_idx,
                            const int* __restrict__ num_sent,
                            const int* __restrict__ qidx,
                            float* __restrict__ prod) {
    const int nn = blockIdx.x;
    const int b  = blockIdx.y;
    const int si = info_idx[b * NSENT + nn];
    const int qi = qidx[b] - 1;
    const float padv = (nn <= num_sent[b]) ? 1.f : 0.f;
    const float* hi  = hinfo + ((size_t)b * SLEN + si) * RUN;
    const float* hqr = hq + ((size_t)b * QLEN + qi) * RUN;
    float* pr = prod + ((size_t)b * NSENT + nn) * RUN;
    for (int jj = threadIdx.x; jj < RUN; jj += blockDim.x)
        pr[jj] = hi[jj] * hqr[jj] * padv;
}

// ---------------------------------------------------------------------------
// Generic C = A@W + bias (xzm, xza)
// ---------------------------------------------------------------------------
__global__ void gemm_bias_kernel(const float* __restrict__ A,
                                 const float* __restrict__ W,
                                 const float* __restrict__ bias,
                                 float* __restrict__ C,
                                 int Mdim, int Kdim, int Ndim) {
    __shared__ __align__(16) float As[16][68];
    __shared__ __align__(16) float Bs[16][68];
    const int tid = threadIdx.x;
    const int tx = tid & 15;
    const int ty = tid >> 4;
    const int m0 = blockIdx.y * 64;
    const int n0 = blockIdx.x * 64;

    float acc[4][4];
#pragma unroll
    for (int i = 0; i < 4; ++i)
#pragma unroll
        for (int jj = 0; jj < 4; ++jj) acc[i][jj] = 0.f;

    for (int k0 = 0; k0 < Kdim; k0 += 16) {
        for (int e = tid; e < 1024; e += 256) {
            int mm = e >> 4, kk = e & 15;
            int m = m0 + mm, k = k0 + kk;
            As[kk][mm] = (m < Mdim && k < Kdim) ? A[(size_t)m * Kdim + k] : 0.f;
        }
        for (int e = tid; e < 1024; e += 256) {
            int kk = e >> 6, nn = e & 63;
            int k = k0 + kk, nv = n0 + nn;
            Bs[kk][nn] = (k < Kdim && nv < Ndim) ? W[(size_t)k * Ndim + nv] : 0.f;
        }
        __syncthreads();
#pragma unroll
        for (int kk = 0; kk < 16; ++kk) {
            float4 a4 = *reinterpret_cast<const float4*>(&As[kk][ty * 4]);
            float4 b4 = *reinterpret_cast<const float4*>(&Bs[kk][tx * 4]);
            float av[4] = {a4.x, a4.y, a4.z, a4.w};
            float bv[4] = {b4.x, b4.y, b4.z, b4.w};
#pragma unroll
            for (int i = 0; i < 4; ++i)
#pragma unroll
                for (int jj = 0; jj < 4; ++jj) acc[i][jj] += av[i] * bv[jj];
        }
        __syncthreads();
    }
#pragma unroll
    for (int i = 0; i < 4; ++i) {
        int m = m0 + ty * 4 + i;
        if (m >= Mdim) continue;
#pragma unroll
        for (int jj = 0; jj < 4; ++jj) {
            int nv = n0 + tx * 4 + jj;
            if (nv < Ndim) C[(size_t)m * Ndim + nv] = acc[i][jj] + bias[nv];
        }
    }
}

// ---------------------------------------------------------------------------
// Answer step kernels (de-persisted; graph edges give ordering).
// ---------------------------------------------------------------------------
#define ANS_NT    125
#define CHUNK_KC  25
#define NCHUNKS   5

__global__ void ans_init_kernel(float* __restrict__ hP, uint4* __restrict__ hAPk) {
    int e = blockIdx.x * 256 + threadIdx.x;
    for (int i = e; i < BATCH * VOC; i += gridDim.x * 256) hP[i] = 0.f;
    uint4 z4 = make_uint4(0, 0, 0, 0);
    for (int i = e; i < 8 * NCH * 32; i += gridDim.x * 256) hAPk[i] = z4;
}

// GEMM step: rec = h @ Ua + ba1 (via fp16 frags). grid = 125 CTAs.
__global__ void __launch_bounds__(256, 1)
ans_gemm_kernel(const float* __restrict__ ba1,
                float* __restrict__ rec,
                const uint4* __restrict__ UaPk,
                const uint4* __restrict__ hAPk) {
    extern __shared__ __align__(16) uint4 sB[];   // [CHUNK_KC*6*32] = 76800 B
    const int tid = threadIdx.x;
    const int wid = tid >> 5;
    const int lid = tid & 31;
    const int nbBase = blockIdx.x * 6;
    const int mb = wid;

    float acc[6][4];
#pragma unroll
    for (int i = 0; i < 6; ++i)
#pragma unroll
        for (int c = 0; c < 4; ++c) acc[i][c] = 0.f;

    const uint4* ABase = hAPk + (size_t)mb * NCH * 32 + lid;

    for (int ch = 0; ch < NCHUNKS; ++ch) {
        const int kc0 = ch * CHUNK_KC;
        __syncthreads();
        for (int e = tid; e < CHUNK_KC * 6 * 32; e += 256) {
            int nb  = e / (CHUNK_KC * 32);
            int rem = e - nb * (CHUNK_KC * 32);
            int kc  = rem >> 5;
            int l   = rem & 31;
            sB[(kc * 6 + nb) * 32 + l] =
                UaPk[((size_t)(nbBase + nb) * NCH + kc0 + kc) * 32 + l];
        }
        __syncthreads();

        uint4 aq0 = ABase[(size_t)kc0 * 32];
        uint4 aq1 = ABase[(size_t)(kc0 + 1) * 32];
        for (int kc = 0; kc < CHUNK_KC; ++kc) {
            uint4 a = aq0;
            aq0 = aq1;
            if (kc + 2 < CHUNK_KC)
                aq1 = ABase[(size_t)(kc0 + kc + 2) * 32];
            const uint4* bp = sB + kc * 192 + lid;
#pragma unroll
            for (int nb = 0; nb < 6; ++nb) {
                uint4 b = bp[nb * 32];
                mma_f16(acc[nb][0], acc[nb][1], acc[nb][2], acc[nb][3],
                        a.x, a.y, a.z, a.w, b.x, b.y);
                mma_f16(acc[nb][0], acc[nb][1], acc[nb][2], acc[nb][3],
                        a.x, a.y, a.z, a.w, b.z, b.w);
            }
        }
    }

    const int r0 = mb * 16 + (lid >> 2);
#pragma unroll
    for (int nb = 0; nb < 6; ++nb) {
        int nc = (nbBase + nb) * 8 + 2 * (lid & 3);
        float b0 = ba1[nc], b1 = ba1[nc + 1];
        float2 v0 = { acc[nb][0] + b0, acc[nb][1] + b1 };
        float2 v1 = { acc[nb][2] + b0, acc[nb][3] + b1 };
        *reinterpret_cast<float2*>(rec + (size_t)r0 * N3V + nc) = v0;
        *reinterpret_cast<float2*>(rec + (size_t)(r0 + 8) * N3V + nc) = v1;
    }
}

// Update step: gates + softmax + combine + next-step A frags. grid = 128.
__global__ void __launch_bounds__(256, 1)
ans_update_kernel(const float* __restrict__ xza,
                  const float* __restrict__ rec,
                  const float* __restrict__ hp,
                  float* __restrict__ hn,
                  float* __restrict__ out,
                  uint4* __restrict__ hAPk,
                  int n) {
    __shared__ float red[256];
    const int tid = threadIdx.x;
    const int b = blockIdx.x;

    const float* xrow = xza + ((size_t)b * NSENT + n) * N3V;
    const float* rrow = rec + (size_t)b * N3V;
    float zv[8], tv[8];
    float m = -1e30f;
#pragma unroll
    for (int i = 0; i < 8; ++i) {
        int jj = tid + i * 256;
        if (jj < VOC) {
            float z = sigmoidf_(xrow[jj] + rrow[jj]);
            float r = sigmoidf_(xrow[VOC + jj] + rrow[VOC + jj]);
            float t = xrow[2 * VOC + jj] + r * rrow[2 * VOC + jj];
            zv[i] = z; tv[i] = t;
            m = fmaxf(m, t);
        } else { zv[i] = 0.f; tv[i] = -1e30f; }
    }
    red[tid] = m; __syncthreads();
    for (int s = 128; s > 0; s >>= 1) {
        if (tid < s) red[tid] = fmaxf(red[tid], red[tid + s]);
        __syncthreads();
    }
    m = red[0]; __syncthreads();

    float ev[8];
    float sum = 0.f;
#pragma unroll
    for (int i = 0; i < 8; ++i) {
        int jj = tid + i * 256;
        if (jj < VOC) { ev[i] = expf(tv[i] - m); sum += ev[i]; }
        else ev[i] = 0.f;
    }
    red[tid] = sum; __syncthreads();
    for (int s = 128; s > 0; s >>= 1) {
        if (tid < s) red[tid] += red[tid + s];
        __syncthreads();
    }
    const float inv = 1.f / red[0];
    __syncthreads();

#pragma unroll
    for (int i = 0; i < 8; ++i) {
        int jj = tid + i * 256;
        if (jj < VOC) {
            float hh = ev[i] * inv;
            float z  = zv[i];
            float hprev = hp[(size_t)b * VOC + jj];
            float hnew = z * hprev + (1.f - z) * hh;
            hn[(size_t)b * VOC + jj] = hnew;
            out[((size_t)b * NSENT + n) * VOC + jj] = hnew;
        }
    }
    __syncthreads();

    // A-frag build (fp16) for next step: CTA b writes its row's components.
    {
        const int mb = b >> 4;
        const int rpos = b & 15;
        const int hiHalf = (rpos >> 3) & 1;
        const int rp = rpos & 7;
        const float* hrow = hn + (size_t)b * VOC;
        for (int e = tid; e < NCH * 8; e += 256) {
            int kc = e >> 3;
            int rem = e & 7;
            int j = rem >> 1;
            int slot = rem & 1;
            int c = kc * 16 + 2 * j + 8 * slot;
            float2 v = *reinterpret_cast<const float2*>(hrow + c);
            uint32_t w = pk_h2(v.x, v.y);
            size_t f = ((size_t)mb * NCH + kc) * 32 + 4 * rp + j;
            int comp = (slot << 1) | hiHalf;
            reinterpret_cast<uint32_t*>(&hAPk[f])[comp] = w;
        }
    }
}

// ---------------------------------------------------------------------------
// Host orchestration: ~139 graph nodes.
// ---------------------------------------------------------------------------
extern "C" void kernel_launch(void* const* d_in, const int* in_sizes, int n_in,
                              void* d_out, int out_size) {
    const int*   info      = (const int*)d_in[0];
    const int*   info_idx  = (const int*)d_in[1];
    const int*   num_sent  = (const int*)d_in[2];
    const int*   question  = (const int*)d_in[3];
    const int*   qidx      = (const int*)d_in[4];
    const float* info_emb  = (const float*)d_in[5];
    const float* Wi        = (const float*)d_in[6];
    const float* Ui        = (const float*)d_in[7];
    const float* bi        = (const float*)d_in[8];
    const float* q_emb     = (const float*)d_in[9];
    const float* Wq        = (const float*)d_in[10];
    const float* Uq        = (const float*)d_in[11];
    const float* bq        = (const float*)d_in[12];
    const float* Wm        = (const float*)d_in[13];
    const float* Um        = (const float*)d_in[14];
    const float* bm        = (const float*)d_in[15];
    const float* Wa        = (const float*)d_in[16];
    const float* Ua        = (const float*)d_in[17];
    const float* ba        = (const float*)d_in[18];
    float* out = (float*)d_out;

    float *tbl_i, *tbl_q, *hinfo, *hq, *prod, *xzm, *hidden, *xza, *rec, *hA, *hB;
    uint4 *uaPk, *hAPk;
    cudaGetSymbolAddress((void**)&tbl_i, g_table_i);
    cudaGetSymbolAddress((void**)&tbl_q, g_table_q);
    cudaGetSymbolAddress((void**)&hinfo, g_hinfo);
    cudaGetSymbolAddress((void**)&hq, g_hq);
    cudaGetSymbolAddress((void**)&prod, g_prod);
    cudaGetSymbolAddress((void**)&xzm, g_xzm);
    cudaGetSymbolAddress((void**)&hidden, g_hidden);
    cudaGetSymbolAddress((void**)&xza, g_xza);
    cudaGetSymbolAddress((void**)&rec, g_rec);
    cudaGetSymbolAddress((void**)&hA, g_hA);
    cudaGetSymbolAddress((void**)&hB, g_hB);
    cudaGetSymbolAddress((void**)&uaPk, g_UaPk);
    cudaGetSymbolAddress((void**)&hAPk, g_hAPk);

    const size_t smemR = ((size_t)RUN * 48 + (size_t)16 * RUN) * 8;
    const size_t smemM = ((size_t)MEM * 48 + (size_t)16 * MEM) * 8;
    const size_t ansSmem = (size_t)CHUNK_KC * 6 * 32 * sizeof(uint4);   // 76800

    static bool attr_set = false;
    if (!attr_set) {
        cudaFuncSetAttribute(gru_seq_kernel<RUN>,
                             cudaFuncAttributeMaxDynamicSharedMemorySize, (int)smemR);
        cudaFuncSetAttribute(gru_seq_kernel<MEM>,
                             cudaFuncAttributeMaxDynamicSharedMemorySize, (int)smemM);
        cudaFuncSetAttribute(ans_gemm_kernel,
                             cudaFuncAttributeMaxDynamicSharedMemorySize, (int)ansSmem);
        attr_set = true;
    }

    const dim3 blk(16, 4, 2);

    build_table_kernel<<<dim3((3 * RUN + 255) / 256, 1024), 256>>>(info_emb, Wi, bi, tbl_i, 3 * RUN);
    build_table_kernel<<<dim3((3 * RUN + 255) / 256, 64), 256>>>(q_emb, Wq, bq, tbl_q, 3 * RUN);

    {
        size_t F = (size_t)NBLK * NCH * 32;
        prep_ua_frag<<<(unsigned)((F + 255) / 256), 256>>>(Ua, uaPk);
    }

    // info GRU (T=1024, H=400)
    gru_seq_kernel<RUN><<<dim3((RUN + 31) / 32, 8), blk, smemR>>>(
        tbl_i, info, Ui, bi + 3 * RUN, hA, hB, hinfo, nullptr, SLEN);

    // question GRU (T=64, H=400)
    gru_seq_kernel<RUN><<<dim3((RUN + 31) / 32, 8), blk, smemR>>>(
        tbl_q, question, Uq, bq + 3 * RUN, hA, hB, hq, nullptr, QLEN);

    prod_kernel<<<dim3(NSENT, BATCH), 128>>>(hinfo, hq, info_idx, num_sent, qidx, prod);

    gemm_bias_kernel<<<dim3((3 * MEM + 63) / 64, (BATCH * NSENT) / 64), 256>>>(
        prod, Wm, bm, xzm, BATCH * NSENT, RUN, 3 * MEM);

    // memory GRU (T=64, H=300)
    gru_seq_kernel<MEM><<<dim3((MEM + 31) / 32, 8), blk, smemM>>>(
        xzm, nullptr, Um, bm + 3 * MEM, hA, hB, hidden, num_sent, NSENT);

    gemm_bias_kernel<<<dim3((N3V + 63) / 64, (BATCH * NSENT) / 64), 256>>>(
        hidden, Wa, ba, xza, BATCH * NSENT, MEM, N3V);

    // --- answer loop: 2 kernels per step, graph-ordered ---
    ans_init_kernel<<<148, 256>>>(hA, hAPk);
    {
        float* hp = hA;
        float* hn = hB;
        for (int n = 0; n < NSENT; ++n) {
            ans_gemm_kernel<<<ANS_NT, 256, ansSmem>>>(ba + N3V, rec, uaPk, hAPk);
            ans_update_kernel<<<BATCH, 256>>>(xza, rec, hp, hn, out, hAPk, n);
            float* tmp = hp; hp = hn; hn = tmp;
        }
    }
}

// round 15
// speedup vs baseline: 1.7950x; 1.2433x over previous
#include <cuda_runtime.h>
#include <cuda_bf16.h>
#include <cuda_fp16.h>
#include <cstdint>

#define BATCH 128
#define SLEN  1024
#define NSENT 64
#define QLEN  64
#define EMB   50
#define RUN   400
#define MEM   300
#define VOC   2000
#define N3V   (3 * VOC)      // 6000
#define NCH   125            // k16 chunks (2000/16)
#define NBLK  750            // n8 blocks (6000/8)

typedef unsigned long long ull;

__device__ __forceinline__ ull pack2(float lo, float hi) {
    ull r; asm("mov.b64 %0, {%1, %2};" : "=l"(r) : "f"(lo), "f"(hi)); return r;
}
__device__ __forceinline__ ull pdup(float v) { return pack2(v, v); }
__device__ __forceinline__ void fma2(ull& d, ull a, ull b) {
    asm("fma.rn.f32x2 %0, %1, %2, %0;" : "+l"(d) : "l"(a), "l"(b));
}
__device__ __forceinline__ void add2(ull& d, ull a) {
    asm("add.rn.f32x2 %0, %0, %1;" : "+l"(d) : "l"(a));
}
__device__ __forceinline__ float2 unpack2(ull v) {
    float2 r; asm("mov.b64 {%0, %1}, %2;" : "=f"(r.x), "=f"(r.y) : "l"(v)); return r;
}

// fp16 HMMA m16n8k16, f32 accum
__device__ __forceinline__ void mma_f16(float& c0, float& c1, float& c2, float& c3,
                                        uint32_t a0, uint32_t a1, uint32_t a2, uint32_t a3,
                                        uint32_t b0, uint32_t b1) {
    asm volatile(
        "mma.sync.aligned.m16n8k16.row.col.f32.f16.f16.f32 "
        "{%0,%1,%2,%3}, {%4,%5,%6,%7}, {%8,%9}, {%0,%1,%2,%3};"
        : "+f"(c0), "+f"(c1), "+f"(c2), "+f"(c3)
        : "r"(a0), "r"(a1), "r"(a2), "r"(a3), "r"(b0), "r"(b1));
}

__device__ __forceinline__ uint32_t pk_h2(float x, float y) {
    __half2 h = __floats2half2_rn(x, y);
    return *reinterpret_cast<uint32_t*>(&h);
}
__device__ __forceinline__ float h_hi(float v) {
    __half h = __float2half_rn(v);
    return __half2float(h);
}

// ---------------------------------------------------------------------------
// Device scratch
// ---------------------------------------------------------------------------
__device__ float g_table_i[1024 * 3 * RUN];
__device__ float g_table_q[64 * 3 * RUN];
__device__ float g_hinfo[(size_t)BATCH * SLEN * RUN];
__device__ float g_hq[(size_t)BATCH * QLEN * RUN];
__device__ float g_prod[(size_t)BATCH * NSENT * RUN];
__device__ float g_xzm[(size_t)BATCH * NSENT * 3 * MEM];
__device__ float g_hidden[(size_t)BATCH * NSENT * MEM];
__device__ float g_xza[(size_t)BATCH * NSENT * N3V];
__device__ float g_rec[(size_t)BATCH * N3V];
__device__ float g_hA[(size_t)BATCH * VOC];
__device__ float g_hB[(size_t)BATCH * VOC];
__device__ uint4 g_UaPk[(size_t)NBLK * NCH * 32];
__device__ uint4 g_hAPk[(size_t)8 * NCH * 32];

__device__ unsigned g_cnt[16 * 32];
__device__ volatile unsigned g_sns[16 * 32];

__device__ __forceinline__ float sigmoidf_(float x) { return 1.f / (1.f + expf(-x)); }

__device__ __forceinline__ void group_barrier(int slot, unsigned G, unsigned& sense) {
    __syncthreads();
    sense ^= 1u;
    if (threadIdx.x == 0 && threadIdx.y == 0 && threadIdx.z == 0) {
        __threadfence();
        unsigned prev = atomicAdd(&g_cnt[slot * 32], 1u);
        if (prev == G - 1u) {
            g_cnt[slot * 32] = 0u;
            __threadfence();
            g_sns[slot * 32] = sense;
        } else {
            while (g_sns[slot * 32] != sense) { }
        }
        __threadfence();
    }
    __syncthreads();
}

// ---------------------------------------------------------------------------
// table build
// ---------------------------------------------------------------------------
__global__ void build_table_kernel(const float* __restrict__ emb,
                                   const float* __restrict__ W,
                                   const float* __restrict__ b0,
                                   float* __restrict__ table,
                                   int N3) {
    int v = blockIdx.y;
    int j = blockIdx.x * blockDim.x + threadIdx.x;
    __shared__ float se[EMB];
    if (threadIdx.x < EMB) se[threadIdx.x] = emb[(size_t)v * EMB + threadIdx.x];
    __syncthreads();
    if (j < N3) {
        float acc = b0[j];
#pragma unroll 10
        for (int e = 0; e < EMB; ++e) acc += se[e] * W[(size_t)e * N3 + j];
        table[(size_t)v * N3 + j] = acc;
    }
}

// ---------------------------------------------------------------------------
// Ua -> packed fp16 B fragments (hi/lo), fragment-major.
// ---------------------------------------------------------------------------
__global__ void prep_ua_frag(const float* __restrict__ Ua, uint4* __restrict__ dst) {
    size_t fp = (size_t)blockIdx.x * blockDim.x + threadIdx.x;
    if (fp >= (size_t)NBLK * NCH * 32) return;
    int l  = fp & 31;
    int kc = (int)((fp >> 5) % NCH);
    int nb = (int)((fp >> 5) / NCH);
    int n = nb * 8 + (l >> 2);
    int k = kc * 16 + 2 * (l & 3);
    float u0 = Ua[(size_t)k * N3V + n];
    float u1 = Ua[(size_t)(k + 1) * N3V + n];
    float u8 = Ua[(size_t)(k + 8) * N3V + n];
    float u9 = Ua[(size_t)(k + 9) * N3V + n];
    float h0 = h_hi(u0), h1 = h_hi(u1), h8 = h_hi(u8), h9 = h_hi(u9);
    uint4 v;
    v.x = pk_h2(h0, h1);
    v.y = pk_h2(h8, h9);
    v.z = pk_h2(u0 - h0, u1 - h1);
    v.w = pk_h2(u8 - h8, u9 - h9);
    dst[fp] = v;
}

// ---------------------------------------------------------------------------
// Persistent GRU. Staging via float4 loads (latency-optimized).
// ---------------------------------------------------------------------------
template <int H>
__global__ void __launch_bounds__(128, 1)
gru_seq_kernel(const float* __restrict__ xz,
               const int* __restrict__ tok,
               const float* __restrict__ U,
               const float* __restrict__ brec,
               float* __restrict__ hP, float* __restrict__ hQ,
               float* __restrict__ seq_out,
               const int* __restrict__ num_sent,
               int T) {
    extern __shared__ __align__(16) ull smu[];
    ull* su2 = smu;            // [H][48]
    ull* shd = smu + H * 48;   // [16][H]
    __shared__ ull sred[64 * 12];

    const int tx = threadIdx.x;
    const int ty = threadIdx.y;
    const int tz = threadIdx.z;
    const int tid64 = ty * 16 + tx;
    const int tid = tz * 64 + tid64;
    const int j0 = blockIdx.x * 32;
    const int b0 = blockIdx.y * 16;
    const int N3 = 3 * H;
    const int slot = blockIdx.y;
    const unsigned G = gridDim.x;
    unsigned sense = g_sns[slot * 32];

    for (int e = tid; e < H * 48; e += 128) {
        int k = e / 48, c = e - k * 48;
        int g = c >> 4, p = c & 15;
        int j = j0 + 2 * p;
        float lo = (j < H) ? U[(size_t)k * N3 + g * H + j] : 0.f;
        float hi = (j + 1 < H) ? U[(size_t)k * N3 + g * H + j + 1] : 0.f;
        su2[e] = pack2(lo, hi);
    }
    for (int e = tid; e < 16 * 32; e += 128) {
        int bb = e >> 5, jj = e & 31;
        if (j0 + jj < H) hP[(size_t)(b0 + bb) * H + j0 + jj] = 0.f;
    }
    group_barrier(slot, G, sense);

    float* hp = hP;
    float* hn = hQ;

    const int jA = j0 + 2 * tx;
    const int jB = jA + 1;
    float bzA = 0, brA = 0, bhA = 0, bzB = 0, brB = 0, bhB = 0;
    if (jA < H) { bzA = brec[jA]; brA = brec[H + jA]; bhA = brec[2 * H + jA]; }
    if (jB < H) { bzB = brec[jB]; brB = brec[H + jB]; bhB = brec[2 * H + jB]; }

    constexpr int Hh = H / 2;
    constexpr int Hq = H / 4;
    const int kBeg = tz * Hh;
    const ull* up = su2 + tx;

    for (int t = 0; t < T; ++t) {
        ull xzp[4], xrp[4], xhp[4];
        int padi[4];
        if (tz == 0 && jA < H) {
#pragma unroll
            for (int r = 0; r < 4; ++r) {
                const int b = b0 + 4 * ty + r;
                const float* xrow;
                if (tok) xrow = xz + (size_t)tok[(size_t)b * T + t] * N3;
                else     xrow = xz + ((size_t)b * T + t) * N3;
                xzp[r] = *reinterpret_cast<const ull*>(xrow + jA);
                xrp[r] = *reinterpret_cast<const ull*>(xrow + H + jA);
                xhp[r] = *reinterpret_cast<const ull*>(xrow + 2 * H + jA);
                padi[r] = num_sent ? num_sent[b] : 0x7fffffff;
            }
        }

        // stage h_prev rows via float4 loads, dup-pack on store
        for (int e = tid; e < 16 * Hq; e += 128) {
            int row = e / Hq, q = e - row * Hq;
            float4 v = *reinterpret_cast<const float4*>(hp + (size_t)(b0 + row) * H + 4 * q);
            ull* d = shd + row * H + 4 * q;
            d[0] = pdup(v.x); d[1] = pdup(v.y); d[2] = pdup(v.z); d[3] = pdup(v.w);
        }
        __syncthreads();

        ull az[4] = {0,0,0,0}, ar[4] = {0,0,0,0}, ah[4] = {0,0,0,0};
        const ull* h0p = shd + (4 * ty + 0) * H + kBeg;
        const ull* h1p = shd + (4 * ty + 1) * H + kBeg;
        const ull* h2p = shd + (4 * ty + 2) * H + kBeg;
        const ull* h3p = shd + (4 * ty + 3) * H + kBeg;
        const ull* ub = up + kBeg * 48;
#pragma unroll 4
        for (int kk = 0; kk < Hh; ++kk) {
            ull uz = ub[kk * 48];
            ull ur = ub[kk * 48 + 16];
            ull uh = ub[kk * 48 + 32];
            ull h0 = h0p[kk], h1 = h1p[kk], h2 = h2p[kk], h3 = h3p[kk];
            fma2(az[0], h0, uz); fma2(az[1], h1, uz); fma2(az[2], h2, uz); fma2(az[3], h3, uz);
            fma2(ar[0], h0, ur); fma2(ar[1], h1, ur); fma2(ar[2], h2, ur); fma2(ar[3], h3, ur);
            fma2(ah[0], h0, uh); fma2(ah[1], h1, uh); fma2(ah[2], h2, uh); fma2(ah[3], h3, uh);
        }

        if (tz == 1) {
            ull* s = sred + tid64 * 12;
#pragma unroll
            for (int r = 0; r < 4; ++r) { s[r] = az[r]; s[4 + r] = ar[r]; s[8 + r] = ah[r]; }
        }
        __syncthreads();

        if (tz == 0) {
            const ull* s = sred + tid64 * 12;
#pragma unroll
            for (int r = 0; r < 4; ++r) { add2(az[r], s[r]); add2(ar[r], s[4 + r]); add2(ah[r], s[8 + r]); }

            if (jA < H) {
#pragma unroll
                for (int r = 0; r < 4; ++r) {
                    const int row = 4 * ty + r;
                    const int b = b0 + row;
                    float2 AZ = unpack2(az[r]);
                    float2 AR = unpack2(ar[r]);
                    float2 AH = unpack2(ah[r]);
                    float2 XZ = unpack2(xzp[r]);
                    float2 XR = unpack2(xrp[r]);
                    float2 XH = unpack2(xhp[r]);
                    float padv = (t <= padi[r]) ? 1.f : 0.f;
                    {
                        float z  = sigmoidf_(XZ.x + AZ.x + bzA);
                        float rr = sigmoidf_(XR.x + AR.x + brA);
                        float hh = tanhf(XH.x + rr * (AH.x + bhA));
                        float hprev = unpack2(shd[row * H + jA]).x;
                        float hnew = z * hprev + (1.f - z) * hh;
                        hn[(size_t)b * H + jA] = hnew;
                        seq_out[((size_t)b * T + t) * H + jA] = hnew * padv;
                    }
                    if (jB < H) {
                        float z  = sigmoidf_(XZ.y + AZ.y + bzB);
                        float rr = sigmoidf_(XR.y + AR.y + brB);
                        float hh = tanhf(XH.y + rr * (AH.y + bhB));
                        float hprev = unpack2(shd[row * H + jB]).x;
                        float hnew = z * hprev + (1.f - z) * hh;
                        hn[(size_t)b * H + jB] = hnew;
                        seq_out[((size_t)b * T + t) * H + jB] = hnew * padv;
                    }
                }
            }
        }
        group_barrier(slot, G, sense);
        float* tmp = hp; hp = hn; hn = tmp;
    }
}

// ---------------------------------------------------------------------------
// prod
// ---------------------------------------------------------------------------
__global__ void prod_kernel(const float* __restrict__ hinfo,
                            const float* __restrict__ hq,
                            const int* __restrict__ info_idx,
                            const int* __restrict__ num_sent,
                            const int* __restrict__ qidx,
                            float* __restrict__ prod) {
    const int nn = blockIdx.x;
    const int b  = blockIdx.y;
    const int si = info_idx[b * NSENT + nn];
    const int qi = qidx[b] - 1;
    const float padv = (nn <= num_sent[b]) ? 1.f : 0.f;
    const float* hi  = hinfo + ((size_t)b * SLEN + si) * RUN;
    const float* hqr = hq + ((size_t)b * QLEN + qi) * RUN;
    float* pr = prod + ((size_t)b * NSENT + nn) * RUN;
    for (int jj = threadIdx.x; jj < RUN; jj += blockDim.x)
        pr[jj] = hi[jj] * hqr[jj] * padv;
}

// ---------------------------------------------------------------------------
// Generic C = A@W + bias (xzm, xza)
// ---------------------------------------------------------------------------
__global__ void gemm_bias_kernel(const float* __restrict__ A,
                                 const float* __restrict__ W,
                                 const float* __restrict__ bias,
                                 float* __restrict__ C,
                                 int Mdim, int Kdim, int Ndim) {
    __shared__ __align__(16) float As[16][68];
    __shared__ __align__(16) float Bs[16][68];
    const int tid = threadIdx.x;
    const int tx = tid & 15;
    const int ty = tid >> 4;
    const int m0 = blockIdx.y * 64;
    const int n0 = blockIdx.x * 64;

    float acc[4][4];
#pragma unroll
    for (int i = 0; i < 4; ++i)
#pragma unroll
        for (int jj = 0; jj < 4; ++jj) acc[i][jj] = 0.f;

    for (int k0 = 0; k0 < Kdim; k0 += 16) {
        for (int e = tid; e < 1024; e += 256) {
            int mm = e >> 4, kk = e & 15;
            int m = m0 + mm, k = k0 + kk;
            As[kk][mm] = (m < Mdim && k < Kdim) ? A[(size_t)m * Kdim + k] : 0.f;
        }
        for (int e = tid; e < 1024; e += 256) {
            int kk = e >> 6, nn = e & 63;
            int k = k0 + kk, nv = n0 + nn;
            Bs[kk][nn] = (k < Kdim && nv < Ndim) ? W[(size_t)k * Ndim + nv] : 0.f;
        }
        __syncthreads();
#pragma unroll
        for (int kk = 0; kk < 16; ++kk) {
            float4 a4 = *reinterpret_cast<const float4*>(&As[kk][ty * 4]);
            float4 b4 = *reinterpret_cast<const float4*>(&Bs[kk][tx * 4]);
            float av[4] = {a4.x, a4.y, a4.z, a4.w};
            float bv[4] = {b4.x, b4.y, b4.z, b4.w};
#pragma unroll
            for (int i = 0; i < 4; ++i)
#pragma unroll
                for (int jj = 0; jj < 4; ++jj) acc[i][jj] += av[i] * bv[jj];
        }
        __syncthreads();
    }
#pragma unroll
    for (int i = 0; i < 4; ++i) {
        int m = m0 + ty * 4 + i;
        if (m >= Mdim) continue;
#pragma unroll
        for (int jj = 0; jj < 4; ++jj) {
            int nv = n0 + tx * 4 + jj;
            if (nv < Ndim) C[(size_t)m * Ndim + nv] = acc[i][jj] + bias[nv];
        }
    }
}

// ---------------------------------------------------------------------------
// Answer step kernels (de-persisted, graph-ordered).
// ---------------------------------------------------------------------------
#define ANS_NT    125
#define CHUNK_KC  25
#define NCHUNKS   5
#define PF_N      19          // ceil(25*6*32 / 256)

__global__ void ans_init_kernel(float* __restrict__ hP, uint4* __restrict__ hAPk) {
    int e = blockIdx.x * 256 + threadIdx.x;
    for (int i = e; i < BATCH * VOC; i += gridDim.x * 256) hP[i] = 0.f;
    uint4 z4 = make_uint4(0, 0, 0, 0);
    for (int i = e; i < 8 * NCH * 32; i += gridDim.x * 256) hAPk[i] = z4;
}

// GEMM step with register-prefetch pipelined B staging. grid = 125 CTAs.
__global__ void __launch_bounds__(256, 1)
ans_gemm_kernel(const float* __restrict__ ba1,
                float* __restrict__ rec,
                const uint4* __restrict__ UaPk,
                const uint4* __restrict__ hAPk) {
    extern __shared__ __align__(16) uint4 sB[];   // [CHUNK_KC*6*32] = 76800 B
    const int tid = threadIdx.x;
    const int wid = tid >> 5;
    const int lid = tid & 31;
    const int nbBase = blockIdx.x * 6;
    const int mb = wid;

    float acc[6][4];
#pragma unroll
    for (int i = 0; i < 6; ++i)
#pragma unroll
        for (int c = 0; c < 4; ++c) acc[i][c] = 0.f;

    const uint4* ABase = hAPk + (size_t)mb * NCH * 32 + lid;

    // per-thread staging coords (19 elements, last predicated)
    int sIdx[PF_N];     // smem dst index
    size_t gOff[PF_N];  // UaPk src offset (without kc0 chunk shift)
#pragma unroll
    for (int p = 0; p < PF_N; ++p) {
        int e = p * 256 + tid;
        if (e < CHUNK_KC * 6 * 32) {
            int nb  = e / (CHUNK_KC * 32);
            int rem = e - nb * (CHUNK_KC * 32);
            int kc  = rem >> 5;
            int l   = rem & 31;
            sIdx[p] = (kc * 6 + nb) * 32 + l;
            gOff[p] = ((size_t)(nbBase + nb) * NCH + kc) * 32 + l;
        } else { sIdx[p] = -1; gOff[p] = 0; }
    }

    // stage chunk 0 directly
#pragma unroll
    for (int p = 0; p < PF_N; ++p)
        if (sIdx[p] >= 0) sB[sIdx[p]] = UaPk[gOff[p]];

    for (int ch = 0; ch < NCHUNKS; ++ch) {
        __syncthreads();    // sB chunk ch visible / previous compute done

        // issue prefetch LDGs for chunk ch+1 into registers
        uint4 pf[PF_N];
        if (ch + 1 < NCHUNKS) {
            const size_t shift = (size_t)(ch + 1) * CHUNK_KC * 32;
#pragma unroll
            for (int p = 0; p < PF_N; ++p)
                if (sIdx[p] >= 0) pf[p] = UaPk[gOff[p] + shift];
        }

        // compute current chunk (hides prefetch latency)
        const int kc0 = ch * CHUNK_KC;
        uint4 aq0 = ABase[(size_t)kc0 * 32];
        uint4 aq1 = ABase[(size_t)(kc0 + 1) * 32];
        for (int kc = 0; kc < CHUNK_KC; ++kc) {
            uint4 a = aq0;
            aq0 = aq1;
            if (kc + 2 < CHUNK_KC)
                aq1 = ABase[(size_t)(kc0 + kc + 2) * 32];
            const uint4* bp = sB + kc * 192 + lid;
#pragma unroll
            for (int nb = 0; nb < 6; ++nb) {
                uint4 b = bp[nb * 32];
                mma_f16(acc[nb][0], acc[nb][1], acc[nb][2], acc[nb][3],
                        a.x, a.y, a.z, a.w, b.x, b.y);
                mma_f16(acc[nb][0], acc[nb][1], acc[nb][2], acc[nb][3],
                        a.x, a.y, a.z, a.w, b.z, b.w);
            }
        }

        __syncthreads();    // all reads of sB done before overwrite
        if (ch + 1 < NCHUNKS) {
#pragma unroll
            for (int p = 0; p < PF_N; ++p)
                if (sIdx[p] >= 0) sB[sIdx[p]] = pf[p];
        }
    }

    const int r0 = mb * 16 + (lid >> 2);
#pragma unroll
    for (int nb = 0; nb < 6; ++nb) {
        int nc = (nbBase + nb) * 8 + 2 * (lid & 3);
        float b0 = ba1[nc], b1 = ba1[nc + 1];
        float2 v0 = { acc[nb][0] + b0, acc[nb][1] + b1 };
        float2 v1 = { acc[nb][2] + b0, acc[nb][3] + b1 };
        *reinterpret_cast<float2*>(rec + (size_t)r0 * N3V + nc) = v0;
        *reinterpret_cast<float2*>(rec + (size_t)(r0 + 8) * N3V + nc) = v1;
    }
}

// Update step: gates + softmax + combine + next-step A frags. grid = 128.
__global__ void __launch_bounds__(256, 1)
ans_update_kernel(const float* __restrict__ xza,
                  const float* __restrict__ rec,
                  const float* __restrict__ hp,
                  float* __restrict__ hn,
                  float* __restrict__ out,
                  uint4* __restrict__ hAPk,
                  int n) {
    __shared__ float red[256];
    const int tid = threadIdx.x;
    const int b = blockIdx.x;

    const float* xrow = xza + ((size_t)b * NSENT + n) * N3V;
    const float* rrow = rec + (size_t)b * N3V;
    float zv[8], tv[8];
    float m = -1e30f;
#pragma unroll
    for (int i = 0; i < 8; ++i) {
        int jj = tid + i * 256;
        if (jj < VOC) {
            float z = sigmoidf_(xrow[jj] + rrow[jj]);
            float r = sigmoidf_(xrow[VOC + jj] + rrow[VOC + jj]);
            float t = xrow[2 * VOC + jj] + r * rrow[2 * VOC + jj];
            zv[i] = z; tv[i] = t;
            m = fmaxf(m, t);
        } else { zv[i] = 0.f; tv[i] = -1e30f; }
    }
    red[tid] = m; __syncthreads();
    for (int s = 128; s > 0; s >>= 1) {
        if (tid < s) red[tid] = fmaxf(red[tid], red[tid + s]);
        __syncthreads();
    }
    m = red[0]; __syncthreads();

    float ev[8];
    float sum = 0.f;
#pragma unroll
    for (int i = 0; i < 8; ++i) {
        int jj = tid + i * 256;
        if (jj < VOC) { ev[i] = expf(tv[i] - m); sum += ev[i]; }
        else ev[i] = 0.f;
    }
    red[tid] = sum; __syncthreads();
    for (int s = 128; s > 0; s >>= 1) {
        if (tid < s) red[tid] += red[tid + s];
        __syncthreads();
    }
    const float inv = 1.f / red[0];
    __syncthreads();

#pragma unroll
    for (int i = 0; i < 8; ++i) {
        int jj = tid + i * 256;
        if (jj < VOC) {
            float hh = ev[i] * inv;
            float z  = zv[i];
            float hprev = hp[(size_t)b * VOC + jj];
            float hnew = z * hprev + (1.f - z) * hh;
            hn[(size_t)b * VOC + jj] = hnew;
            out[((size_t)b * NSENT + n) * VOC + jj] = hnew;
        }
    }
    __syncthreads();

    // A-frag build (fp16) for next step: CTA b writes its row's components.
    {
        const int mb = b >> 4;
        const int rpos = b & 15;
        const int hiHalf = (rpos >> 3) & 1;
        const int rp = rpos & 7;
        const float* hrow = hn + (size_t)b * VOC;
        for (int e = tid; e < NCH * 8; e += 256) {
            int kc = e >> 3;
            int rem = e & 7;
            int j = rem >> 1;
            int slot = rem & 1;
            int c = kc * 16 + 2 * j + 8 * slot;
            float2 v = *reinterpret_cast<const float2*>(hrow + c);
            uint32_t w = pk_h2(v.x, v.y);
            size_t f = ((size_t)mb * NCH + kc) * 32 + 4 * rp + j;
            int comp = (slot << 1) | hiHalf;
            reinterpret_cast<uint32_t*>(&hAPk[f])[comp] = w;
        }
    }
}

// ---------------------------------------------------------------------------
// Host orchestration
// ---------------------------------------------------------------------------
extern "C" void kernel_launch(void* const* d_in, const int* in_sizes, int n_in,
                              void* d_out, int out_size) {
    const int*   info      = (const int*)d_in[0];
    const int*   info_idx  = (const int*)d_in[1];
    const int*   num_sent  = (const int*)d_in[2];
    const int*   question  = (const int*)d_in[3];
    const int*   qidx      = (const int*)d_in[4];
    const float* info_emb  = (const float*)d_in[5];
    const float* Wi        = (const float*)d_in[6];
    const float* Ui        = (const float*)d_in[7];
    const float* bi        = (const float*)d_in[8];
    const float* q_emb     = (const float*)d_in[9];
    const float* Wq        = (const float*)d_in[10];
    const float* Uq        = (const float*)d_in[11];
    const float* bq        = (const float*)d_in[12];
    const float* Wm        = (const float*)d_in[13];
    const float* Um        = (const float*)d_in[14];
    const float* bm        = (const float*)d_in[15];
    const float* Wa        = (const float*)d_in[16];
    const float* Ua        = (const float*)d_in[17];
    const float* ba        = (const float*)d_in[18];
    float* out = (float*)d_out;

    float *tbl_i, *tbl_q, *hinfo, *hq, *prod, *xzm, *hidden, *xza, *rec, *hA, *hB;
    uint4 *uaPk, *hAPk;
    cudaGetSymbolAddress((void**)&tbl_i, g_table_i);
    cudaGetSymbolAddress((void**)&tbl_q, g_table_q);
    cudaGetSymbolAddress((void**)&hinfo, g_hinfo);
    cudaGetSymbolAddress((void**)&hq, g_hq);
    cudaGetSymbolAddress((void**)&prod, g_prod);
    cudaGetSymbolAddress((void**)&xzm, g_xzm);
    cudaGetSymbolAddress((void**)&hidden, g_hidden);
    cudaGetSymbolAddress((void**)&xza, g_xza);
    cudaGetSymbolAddress((void**)&rec, g_rec);
    cudaGetSymbolAddress((void**)&hA, g_hA);
    cudaGetSymbolAddress((void**)&hB, g_hB);
    cudaGetSymbolAddress((void**)&uaPk, g_UaPk);
    cudaGetSymbolAddress((void**)&hAPk, g_hAPk);

    const size_t smemR = ((size_t)RUN * 48 + (size_t)16 * RUN) * 8;
    const size_t smemM = ((size_t)MEM * 48 + (size_t)16 * MEM) * 8;
    const size_t ansSmem = (size_t)CHUNK_KC * 6 * 32 * sizeof(uint4);   // 76800

    static bool attr_set = false;
    if (!attr_set) {
        cudaFuncSetAttribute(gru_seq_kernel<RUN>,
                             cudaFuncAttributeMaxDynamicSharedMemorySize, (int)smemR);
        cudaFuncSetAttribute(gru_seq_kernel<MEM>,
                             cudaFuncAttributeMaxDynamicSharedMemorySize, (int)smemM);
        cudaFuncSetAttribute(ans_gemm_kernel,
                             cudaFuncAttributeMaxDynamicSharedMemorySize, (int)ansSmem);
        attr_set = true;
    }

    const dim3 blk(16, 4, 2);

    build_table_kernel<<<dim3((3 * RUN + 255) / 256, 1024), 256>>>(info_emb, Wi, bi, tbl_i, 3 * RUN);
    build_table_kernel<<<dim3((3 * RUN + 255) / 256, 64), 256>>>(q_emb, Wq, bq, tbl_q, 3 * RUN);

    {
        size_t F = (size_t)NBLK * NCH * 32;
        prep_ua_frag<<<(unsigned)((F + 255) / 256), 256>>>(Ua, uaPk);
    }

    // info GRU (T=1024, H=400)
    gru_seq_kernel<RUN><<<dim3((RUN + 31) / 32, 8), blk, smemR>>>(
        tbl_i, info, Ui, bi + 3 * RUN, hA, hB, hinfo, nullptr, SLEN);

    // question GRU (T=64, H=400)
    gru_seq_kernel<RUN><<<dim3((RUN + 31) / 32, 8), blk, smemR>>>(
        tbl_q, question, Uq, bq + 3 * RUN, hA, hB, hq, nullptr, QLEN);

    prod_kernel<<<dim3(NSENT, BATCH), 128>>>(hinfo, hq, info_idx, num_sent, qidx, prod);

    gemm_bias_kernel<<<dim3((3 * MEM + 63) / 64, (BATCH * NSENT) / 64), 256>>>(
        prod, Wm, bm, xzm, BATCH * NSENT, RUN, 3 * MEM);

    // memory GRU (T=64, H=300)
    gru_seq_kernel<MEM><<<dim3((MEM + 31) / 32, 8), blk, smemM>>>(
        xzm, nullptr, Um, bm + 3 * MEM, hA, hB, hidden, num_sent, NSENT);

    gemm_bias_kernel<<<dim3((N3V + 63) / 64, (BATCH * NSENT) / 64), 256>>>(
        hidden, Wa, ba, xza, BATCH * NSENT, MEM, N3V);

    // --- answer loop: 2 kernels per step, graph-ordered ---
    ans_init_kernel<<<148, 256>>>(hA, hAPk);
    {
        float* hp = hA;
        float* hn = hB;
        for (int n = 0; n < NSENT; ++n) {
            ans_gemm_kernel<<<ANS_NT, 256, ansSmem>>>(ba + N3V, rec, uaPk, hAPk);
            ans_update_kernel<<<BATCH, 256>>>(xza, rec, hp, hn, out, hAPk, n);
            float* tmp = hp; hp = hn; hn = tmp;
        }
    }
}

// round 16
// speedup vs baseline: 1.8909x; 1.0535x over previous
#include <cuda_runtime.h>
#include <cuda_bf16.h>
#include <cuda_fp16.h>
#include <cstdint>

#define BATCH 128
#define SLEN  1024
#define NSENT 64
#define QLEN  64
#define EMB   50
#define RUN   400
#define MEM   300
#define VOC   2000
#define N3V   (3 * VOC)      // 6000
#define NCH   125            // k16 chunks (2000/16)
#define NBLK  750            // n8 blocks (6000/8)

typedef unsigned long long ull;

__device__ __forceinline__ ull pack2(float lo, float hi) {
    ull r; asm("mov.b64 %0, {%1, %2};" : "=l"(r) : "f"(lo), "f"(hi)); return r;
}
__device__ __forceinline__ ull pdup(float v) { return pack2(v, v); }
__device__ __forceinline__ void fma2(ull& d, ull a, ull b) {
    asm("fma.rn.f32x2 %0, %1, %2, %0;" : "+l"(d) : "l"(a), "l"(b));
}
__device__ __forceinline__ void add2(ull& d, ull a) {
    asm("add.rn.f32x2 %0, %0, %1;" : "+l"(d) : "l"(a));
}
__device__ __forceinline__ float2 unpack2(ull v) {
    float2 r; asm("mov.b64 {%0, %1}, %2;" : "=f"(r.x), "=f"(r.y) : "l"(v)); return r;
}

// fp16 HMMA m16n8k16, f32 accum
__device__ __forceinline__ void mma_f16(float& c0, float& c1, float& c2, float& c3,
                                        uint32_t a0, uint32_t a1, uint32_t a2, uint32_t a3,
                                        uint32_t b0, uint32_t b1) {
    asm volatile(
        "mma.sync.aligned.m16n8k16.row.col.f32.f16.f16.f32 "
        "{%0,%1,%2,%3}, {%4,%5,%6,%7}, {%8,%9}, {%0,%1,%2,%3};"
        : "+f"(c0), "+f"(c1), "+f"(c2), "+f"(c3)
        : "r"(a0), "r"(a1), "r"(a2), "r"(a3), "r"(b0), "r"(b1));
}

__device__ __forceinline__ uint32_t pk_h2(float x, float y) {
    __half2 h = __floats2half2_rn(x, y);
    return *reinterpret_cast<uint32_t*>(&h);
}
__device__ __forceinline__ float h_hi(float v) {
    __half h = __float2half_rn(v);
    return __half2float(h);
}

// ---------------------------------------------------------------------------
// Device scratch
// ---------------------------------------------------------------------------
__device__ float g_table_i[1024 * 3 * RUN];
__device__ float g_table_q[64 * 3 * RUN];
__device__ float g_hinfo[(size_t)BATCH * SLEN * RUN];
__device__ float g_hq[(size_t)BATCH * QLEN * RUN];
__device__ float g_prod[(size_t)BATCH * NSENT * RUN];
__device__ float g_xzm[(size_t)BATCH * NSENT * 3 * MEM];
__device__ float g_hidden[(size_t)BATCH * NSENT * MEM];
__device__ float g_xza[(size_t)BATCH * NSENT * N3V];
__device__ float g_rec[(size_t)BATCH * N3V];
__device__ float g_hA[(size_t)BATCH * VOC];
__device__ float g_hB[(size_t)BATCH * VOC];
__device__ uint4 g_UaPk[(size_t)NBLK * NCH * 32];
__device__ uint4 g_hAPk[(size_t)8 * NCH * 32];

__device__ unsigned g_cnt[16 * 32];
__device__ volatile unsigned g_sns[16 * 32];

__device__ __forceinline__ float sigmoidf_(float x) { return 1.f / (1.f + expf(-x)); }

__device__ __forceinline__ void group_barrier(int slot, unsigned G, unsigned& sense) {
    __syncthreads();
    sense ^= 1u;
    if (threadIdx.x == 0 && threadIdx.y == 0 && threadIdx.z == 0) {
        __threadfence();
        unsigned prev = atomicAdd(&g_cnt[slot * 32], 1u);
        if (prev == G - 1u) {
            g_cnt[slot * 32] = 0u;
            __threadfence();
            g_sns[slot * 32] = sense;
        } else {
            while (g_sns[slot * 32] != sense) { }
        }
        __threadfence();
    }
    __syncthreads();
}

// ---------------------------------------------------------------------------
// table build
// ---------------------------------------------------------------------------
__global__ void build_table_kernel(const float* __restrict__ emb,
                                   const float* __restrict__ W,
                                   const float* __restrict__ b0,
                                   float* __restrict__ table,
                                   int N3) {
    int v = blockIdx.y;
    int j = blockIdx.x * blockDim.x + threadIdx.x;
    __shared__ float se[EMB];
    if (threadIdx.x < EMB) se[threadIdx.x] = emb[(size_t)v * EMB + threadIdx.x];
    __syncthreads();
    if (j < N3) {
        float acc = b0[j];
#pragma unroll 10
        for (int e = 0; e < EMB; ++e) acc += se[e] * W[(size_t)e * N3 + j];
        table[(size_t)v * N3 + j] = acc;
    }
}

// ---------------------------------------------------------------------------
// Ua -> packed fp16 B fragments (hi/lo), fragment-major.
// ---------------------------------------------------------------------------
__global__ void prep_ua_frag(const float* __restrict__ Ua, uint4* __restrict__ dst) {
    size_t fp = (size_t)blockIdx.x * blockDim.x + threadIdx.x;
    if (fp >= (size_t)NBLK * NCH * 32) return;
    int l  = fp & 31;
    int kc = (int)((fp >> 5) % NCH);
    int nb = (int)((fp >> 5) / NCH);
    int n = nb * 8 + (l >> 2);
    int k = kc * 16 + 2 * (l & 3);
    float u0 = Ua[(size_t)k * N3V + n];
    float u1 = Ua[(size_t)(k + 1) * N3V + n];
    float u8 = Ua[(size_t)(k + 8) * N3V + n];
    float u9 = Ua[(size_t)(k + 9) * N3V + n];
    float h0 = h_hi(u0), h1 = h_hi(u1), h8 = h_hi(u8), h9 = h_hi(u9);
    uint4 v;
    v.x = pk_h2(h0, h1);
    v.y = pk_h2(h8, h9);
    v.z = pk_h2(u0 - h0, u1 - h1);
    v.w = pk_h2(u8 - h8, u9 - h9);
    dst[fp] = v;
}

// ---------------------------------------------------------------------------
// Persistent GRU (r15 form).
// ---------------------------------------------------------------------------
template <int H>
__global__ void __launch_bounds__(128, 1)
gru_seq_kernel(const float* __restrict__ xz,
               const int* __restrict__ tok,
               const float* __restrict__ U,
               const float* __restrict__ brec,
               float* __restrict__ hP, float* __restrict__ hQ,
               float* __restrict__ seq_out,
               const int* __restrict__ num_sent,
               int T) {
    extern __shared__ __align__(16) ull smu[];
    ull* su2 = smu;            // [H][48]
    ull* shd = smu + H * 48;   // [16][H]
    __shared__ ull sred[64 * 12];

    const int tx = threadIdx.x;
    const int ty = threadIdx.y;
    const int tz = threadIdx.z;
    const int tid64 = ty * 16 + tx;
    const int tid = tz * 64 + tid64;
    const int j0 = blockIdx.x * 32;
    const int b0 = blockIdx.y * 16;
    const int N3 = 3 * H;
    const int slot = blockIdx.y;
    const unsigned G = gridDim.x;
    unsigned sense = g_sns[slot * 32];

    for (int e = tid; e < H * 48; e += 128) {
        int k = e / 48, c = e - k * 48;
        int g = c >> 4, p = c & 15;
        int j = j0 + 2 * p;
        float lo = (j < H) ? U[(size_t)k * N3 + g * H + j] : 0.f;
        float hi = (j + 1 < H) ? U[(size_t)k * N3 + g * H + j + 1] : 0.f;
        su2[e] = pack2(lo, hi);
    }
    for (int e = tid; e < 16 * 32; e += 128) {
        int bb = e >> 5, jj = e & 31;
        if (j0 + jj < H) hP[(size_t)(b0 + bb) * H + j0 + jj] = 0.f;
    }
    group_barrier(slot, G, sense);

    float* hp = hP;
    float* hn = hQ;

    const int jA = j0 + 2 * tx;
    const int jB = jA + 1;
    float bzA = 0, brA = 0, bhA = 0, bzB = 0, brB = 0, bhB = 0;
    if (jA < H) { bzA = brec[jA]; brA = brec[H + jA]; bhA = brec[2 * H + jA]; }
    if (jB < H) { bzB = brec[jB]; brB = brec[H + jB]; bhB = brec[2 * H + jB]; }

    constexpr int Hh = H / 2;
    constexpr int Hq = H / 4;
    const int kBeg = tz * Hh;
    const ull* up = su2 + tx;

    for (int t = 0; t < T; ++t) {
        ull xzp[4], xrp[4], xhp[4];
        int padi[4];
        if (tz == 0 && jA < H) {
#pragma unroll
            for (int r = 0; r < 4; ++r) {
                const int b = b0 + 4 * ty + r;
                const float* xrow;
                if (tok) xrow = xz + (size_t)tok[(size_t)b * T + t] * N3;
                else     xrow = xz + ((size_t)b * T + t) * N3;
                xzp[r] = *reinterpret_cast<const ull*>(xrow + jA);
                xrp[r] = *reinterpret_cast<const ull*>(xrow + H + jA);
                xhp[r] = *reinterpret_cast<const ull*>(xrow + 2 * H + jA);
                padi[r] = num_sent ? num_sent[b] : 0x7fffffff;
            }
        }

        for (int e = tid; e < 16 * Hq; e += 128) {
            int row = e / Hq, q = e - row * Hq;
            float4 v = *reinterpret_cast<const float4*>(hp + (size_t)(b0 + row) * H + 4 * q);
            ull* d = shd + row * H + 4 * q;
            d[0] = pdup(v.x); d[1] = pdup(v.y); d[2] = pdup(v.z); d[3] = pdup(v.w);
        }
        __syncthreads();

        ull az[4] = {0,0,0,0}, ar[4] = {0,0,0,0}, ah[4] = {0,0,0,0};
        const ull* h0p = shd + (4 * ty + 0) * H + kBeg;
        const ull* h1p = shd + (4 * ty + 1) * H + kBeg;
        const ull* h2p = shd + (4 * ty + 2) * H + kBeg;
        const ull* h3p = shd + (4 * ty + 3) * H + kBeg;
        const ull* ub = up + kBeg * 48;
#pragma unroll 4
        for (int kk = 0; kk < Hh; ++kk) {
            ull uz = ub[kk * 48];
            ull ur = ub[kk * 48 + 16];
            ull uh = ub[kk * 48 + 32];
            ull h0 = h0p[kk], h1 = h1p[kk], h2 = h2p[kk], h3 = h3p[kk];
            fma2(az[0], h0, uz); fma2(az[1], h1, uz); fma2(az[2], h2, uz); fma2(az[3], h3, uz);
            fma2(ar[0], h0, ur); fma2(ar[1], h1, ur); fma2(ar[2], h2, ur); fma2(ar[3], h3, ur);
            fma2(ah[0], h0, uh); fma2(ah[1], h1, uh); fma2(ah[2], h2, uh); fma2(ah[3], h3, uh);
        }

        if (tz == 1) {
            ull* s = sred + tid64 * 12;
#pragma unroll
            for (int r = 0; r < 4; ++r) { s[r] = az[r]; s[4 + r] = ar[r]; s[8 + r] = ah[r]; }
        }
        __syncthreads();

        if (tz == 0) {
            const ull* s = sred + tid64 * 12;
#pragma unroll
            for (int r = 0; r < 4; ++r) { add2(az[r], s[r]); add2(ar[r], s[4 + r]); add2(ah[r], s[8 + r]); }

            if (jA < H) {
#pragma unroll
                for (int r = 0; r < 4; ++r) {
                    const int row = 4 * ty + r;
                    const int b = b0 + row;
                    float2 AZ = unpack2(az[r]);
                    float2 AR = unpack2(ar[r]);
                    float2 AH = unpack2(ah[r]);
                    float2 XZ = unpack2(xzp[r]);
                    float2 XR = unpack2(xrp[r]);
                    float2 XH = unpack2(xhp[r]);
                    float padv = (t <= padi[r]) ? 1.f : 0.f;
                    {
                        float z  = sigmoidf_(XZ.x + AZ.x + bzA);
                        float rr = sigmoidf_(XR.x + AR.x + brA);
                        float hh = tanhf(XH.x + rr * (AH.x + bhA));
                        float hprev = unpack2(shd[row * H + jA]).x;
                        float hnew = z * hprev + (1.f - z) * hh;
                        hn[(size_t)b * H + jA] = hnew;
                        seq_out[((size_t)b * T + t) * H + jA] = hnew * padv;
                    }
                    if (jB < H) {
                        float z  = sigmoidf_(XZ.y + AZ.y + bzB);
                        float rr = sigmoidf_(XR.y + AR.y + brB);
                        float hh = tanhf(XH.y + rr * (AH.y + bhB));
                        float hprev = unpack2(shd[row * H + jB]).x;
                        float hnew = z * hprev + (1.f - z) * hh;
                        hn[(size_t)b * H + jB] = hnew;
                        seq_out[((size_t)b * T + t) * H + jB] = hnew * padv;
                    }
                }
            }
        }
        group_barrier(slot, G, sense);
        float* tmp = hp; hp = hn; hn = tmp;
    }
}

// ---------------------------------------------------------------------------
// prod
// ---------------------------------------------------------------------------
__global__ void prod_kernel(const float* __restrict__ hinfo,
                            const float* __restrict__ hq,
                            const int* __restrict__ info_idx,
                            const int* __restrict__ num_sent,
                            const int* __restrict__ qidx,
                            float* __restrict__ prod) {
    const int nn = blockIdx.x;
    const int b  = blockIdx.y;
    const int si = info_idx[b * NSENT + nn];
    const int qi = qidx[b] - 1;
    const float padv = (nn <= num_sent[b]) ? 1.f : 0.f;
    const float* hi  = hinfo + ((size_t)b * SLEN + si) * RUN;
    const float* hqr = hq + ((size_t)b * QLEN + qi) * RUN;
    float* pr = prod + ((size_t)b * NSENT + nn) * RUN;
    for (int jj = threadIdx.x; jj < RUN; jj += blockDim.x)
        pr[jj] = hi[jj] * hqr[jj] * padv;
}

// ---------------------------------------------------------------------------
// Generic C = A@W + bias (xzm, xza)
// ---------------------------------------------------------------------------
__global__ void gemm_bias_kernel(const float* __restrict__ A,
                                 const float* __restrict__ W,
                                 const float* __restrict__ bias,
                                 float* __restrict__ C,
                                 int Mdim, int Kdim, int Ndim) {
    __shared__ __align__(16) float As[16][68];
    __shared__ __align__(16) float Bs[16][68];
    const int tid = threadIdx.x;
    const int tx = tid & 15;
    const int ty = tid >> 4;
    const int m0 = blockIdx.y * 64;
    const int n0 = blockIdx.x * 64;

    float acc[4][4];
#pragma unroll
    for (int i = 0; i < 4; ++i)
#pragma unroll
        for (int jj = 0; jj < 4; ++jj) acc[i][jj] = 0.f;

    for (int k0 = 0; k0 < Kdim; k0 += 16) {
        for (int e = tid; e < 1024; e += 256) {
            int mm = e >> 4, kk = e & 15;
            int m = m0 + mm, k = k0 + kk;
            As[kk][mm] = (m < Mdim && k < Kdim) ? A[(size_t)m * Kdim + k] : 0.f;
        }
        for (int e = tid; e < 1024; e += 256) {
            int kk = e >> 6, nn = e & 63;
            int k = k0 + kk, nv = n0 + nn;
            Bs[kk][nn] = (k < Kdim && nv < Ndim) ? W[(size_t)k * Ndim + nv] : 0.f;
        }
        __syncthreads();
#pragma unroll
        for (int kk = 0; kk < 16; ++kk) {
            float4 a4 = *reinterpret_cast<const float4*>(&As[kk][ty * 4]);
            float4 b4 = *reinterpret_cast<const float4*>(&Bs[kk][tx * 4]);
            float av[4] = {a4.x, a4.y, a4.z, a4.w};
            float bv[4] = {b4.x, b4.y, b4.z, b4.w};
#pragma unroll
            for (int i = 0; i < 4; ++i)
#pragma unroll
                for (int jj = 0; jj < 4; ++jj) acc[i][jj] += av[i] * bv[jj];
        }
        __syncthreads();
    }
#pragma unroll
    for (int i = 0; i < 4; ++i) {
        int m = m0 + ty * 4 + i;
        if (m >= Mdim) continue;
#pragma unroll
        for (int jj = 0; jj < 4; ++jj) {
            int nv = n0 + tx * 4 + jj;
            if (nv < Ndim) C[(size_t)m * Ndim + nv] = acc[i][jj] + bias[nv];
        }
    }
}

// ---------------------------------------------------------------------------
// Answer step kernels (de-persisted, graph-ordered).
// ---------------------------------------------------------------------------
#define ANS_NT    125
#define CHUNK_KC  25
#define NCHUNKS   5
#define ANS_THR   512
#define PF_N      10          // ceil(25*6*32 / 512)

__global__ void ans_init_kernel(float* __restrict__ hP, uint4* __restrict__ hAPk) {
    int e = blockIdx.x * 256 + threadIdx.x;
    for (int i = e; i < BATCH * VOC; i += gridDim.x * 256) hP[i] = 0.f;
    uint4 z4 = make_uint4(0, 0, 0, 0);
    for (int i = e; i < 8 * NCH * 32; i += gridDim.x * 256) hAPk[i] = z4;
}

// GEMM step: 512 thr = 16 warps; warps {w, w+8} share m-block (w&7) with
// even/odd kc split. B staged via register-prefetch pipeline. grid = 125.
__global__ void __launch_bounds__(ANS_THR, 1)
ans_gemm_kernel(const float* __restrict__ ba1,
                float* __restrict__ rec,
                const uint4* __restrict__ UaPk,
                const uint4* __restrict__ hAPk) {
    extern __shared__ __align__(16) char dyn[];
    uint4* sB   = (uint4*)dyn;                               // 4800 uint4 = 76800 B
    float* sAcc = (float*)(dyn + CHUNK_KC * 6 * 32 * 16);    // 8*32*24 = 24576 B

    const int tid = threadIdx.x;
    const int wid = tid >> 5;
    const int lid = tid & 31;
    const int nbBase = blockIdx.x * 6;
    const int mb = wid & 7;
    const int half = wid >> 3;      // 0: even kc, 1: odd kc

    float acc[6][4];
#pragma unroll
    for (int i = 0; i < 6; ++i)
#pragma unroll
        for (int c = 0; c < 4; ++c) acc[i][c] = 0.f;

    const uint4* ABase = hAPk + (size_t)mb * NCH * 32 + lid;

    // per-thread staging coords
    int sIdx[PF_N];
    size_t gOff[PF_N];
#pragma unroll
    for (int p = 0; p < PF_N; ++p) {
        int e = p * ANS_THR + tid;
        if (e < CHUNK_KC * 6 * 32) {
            int nb  = e / (CHUNK_KC * 32);
            int rem = e - nb * (CHUNK_KC * 32);
            int kc  = rem >> 5;
            int l   = rem & 31;
            sIdx[p] = (kc * 6 + nb) * 32 + l;
            gOff[p] = ((size_t)(nbBase + nb) * NCH + kc) * 32 + l;
        } else { sIdx[p] = -1; gOff[p] = 0; }
    }

    // stage chunk 0
#pragma unroll
    for (int p = 0; p < PF_N; ++p)
        if (sIdx[p] >= 0) sB[sIdx[p]] = UaPk[gOff[p]];

    for (int ch = 0; ch < NCHUNKS; ++ch) {
        __syncthreads();

        // prefetch next chunk into registers
        uint4 pf[PF_N];
        if (ch + 1 < NCHUNKS) {
            const size_t shift = (size_t)(ch + 1) * CHUNK_KC * 32;
#pragma unroll
            for (int p = 0; p < PF_N; ++p)
                if (sIdx[p] >= 0) pf[p] = UaPk[gOff[p] + shift];
        }

        // compute current chunk, kc stride 2 by warp-half
        const int kc0 = ch * CHUNK_KC;
        uint4 aq0 = ABase[(size_t)(kc0 + half) * 32];
        uint4 aq1 = ABase[(size_t)(kc0 + half + 2) * 32];   // may over-read within array (kc<127) OK
        for (int kc = half; kc < CHUNK_KC; kc += 2) {
            uint4 a = aq0;
            aq0 = aq1;
            if (kc + 4 < CHUNK_KC)
                aq1 = ABase[(size_t)(kc0 + kc + 4) * 32];
            const uint4* bp = sB + kc * 192 + lid;
#pragma unroll
            for (int nb = 0; nb < 6; ++nb) {
                uint4 b = bp[nb * 32];
                mma_f16(acc[nb][0], acc[nb][1], acc[nb][2], acc[nb][3],
                        a.x, a.y, a.z, a.w, b.x, b.y);
                mma_f16(acc[nb][0], acc[nb][1], acc[nb][2], acc[nb][3],
                        a.x, a.y, a.z, a.w, b.z, b.w);
            }
        }

        __syncthreads();
        if (ch + 1 < NCHUNKS) {
#pragma unroll
            for (int p = 0; p < PF_N; ++p)
                if (sIdx[p] >= 0) sB[sIdx[p]] = pf[p];
        }
    }

    // merge halves: half 1 dumps, half 0 adds + epilogue
    __syncthreads();
    if (half == 1) {
        float* s = sAcc + (mb * 32 + lid) * 24;
#pragma unroll
        for (int nb = 0; nb < 6; ++nb)
#pragma unroll
            for (int c = 0; c < 4; ++c) s[nb * 4 + c] = acc[nb][c];
    }
    __syncthreads();
    if (half == 0) {
        const float* s = sAcc + (mb * 32 + lid) * 24;
#pragma unroll
        for (int nb = 0; nb < 6; ++nb)
#pragma unroll
            for (int c = 0; c < 4; ++c) acc[nb][c] += s[nb * 4 + c];

        const int r0 = mb * 16 + (lid >> 2);
#pragma unroll
        for (int nb = 0; nb < 6; ++nb) {
            int nc = (nbBase + nb) * 8 + 2 * (lid & 3);
            float b0 = ba1[nc], b1 = ba1[nc + 1];
            float2 v0 = { acc[nb][0] + b0, acc[nb][1] + b1 };
            float2 v1 = { acc[nb][2] + b0, acc[nb][3] + b1 };
            *reinterpret_cast<float2*>(rec + (size_t)r0 * N3V + nc) = v0;
            *reinterpret_cast<float2*>(rec + (size_t)(r0 + 8) * N3V + nc) = v1;
        }
    }
}

// Update step: gates + softmax + combine + next-step A frags. grid = 128.
__global__ void __launch_bounds__(256, 1)
ans_update_kernel(const float* __restrict__ xza,
                  const float* __restrict__ rec,
                  const float* __restrict__ hp,
                  float* __restrict__ hn,
                  float* __restrict__ out,
                  uint4* __restrict__ hAPk,
                  int n) {
    __shared__ float red[256];
    const int tid = threadIdx.x;
    const int b = blockIdx.x;

    const float* xrow = xza + ((size_t)b * NSENT + n) * N3V;
    const float* rrow = rec + (size_t)b * N3V;
    float zv[8], tv[8];
    float m = -1e30f;
#pragma unroll
    for (int i = 0; i < 8; ++i) {
        int jj = tid + i * 256;
        if (jj < VOC) {
            float z = sigmoidf_(xrow[jj] + rrow[jj]);
            float r = sigmoidf_(xrow[VOC + jj] + rrow[VOC + jj]);
            float t = xrow[2 * VOC + jj] + r * rrow[2 * VOC + jj];
            zv[i] = z; tv[i] = t;
            m = fmaxf(m, t);
        } else { zv[i] = 0.f; tv[i] = -1e30f; }
    }
    red[tid] = m; __syncthreads();
    for (int s = 128; s > 0; s >>= 1) {
        if (tid < s) red[tid] = fmaxf(red[tid], red[tid + s]);
        __syncthreads();
    }
    m = red[0]; __syncthreads();

    float ev[8];
    float sum = 0.f;
#pragma unroll
    for (int i = 0; i < 8; ++i) {
        int jj = tid + i * 256;
        if (jj < VOC) { ev[i] = expf(tv[i] - m); sum += ev[i]; }
        else ev[i] = 0.f;
    }
    red[tid] = sum; __syncthreads();
    for (int s = 128; s > 0; s >>= 1) {
        if (tid < s) red[tid] += red[tid + s];
        __syncthreads();
    }
    const float inv = 1.f / red[0];
    __syncthreads();

#pragma unroll
    for (int i = 0; i < 8; ++i) {
        int jj = tid + i * 256;
        if (jj < VOC) {
            float hh = ev[i] * inv;
            float z  = zv[i];
            float hprev = hp[(size_t)b * VOC + jj];
            float hnew = z * hprev + (1.f - z) * hh;
            hn[(size_t)b * VOC + jj] = hnew;
            out[((size_t)b * NSENT + n) * VOC + jj] = hnew;
        }
    }
    __syncthreads();

    // A-frag build (fp16) for next step: CTA b writes its row's components.
    {
        const int mb = b >> 4;
        const int rpos = b & 15;
        const int hiHalf = (rpos >> 3) & 1;
        const int rp = rpos & 7;
        const float* hrow = hn + (size_t)b * VOC;
        for (int e = tid; e < NCH * 8; e += 256) {
            int kc = e >> 3;
            int rem = e & 7;
            int j = rem >> 1;
            int slot = rem & 1;
            int c = kc * 16 + 2 * j + 8 * slot;
            float2 v = *reinterpret_cast<const float2*>(hrow + c);
            uint32_t w = pk_h2(v.x, v.y);
            size_t f = ((size_t)mb * NCH + kc) * 32 + 4 * rp + j;
            int comp = (slot << 1) | hiHalf;
            reinterpret_cast<uint32_t*>(&hAPk[f])[comp] = w;
        }
    }
}

// ---------------------------------------------------------------------------
// Host orchestration
// ---------------------------------------------------------------------------
extern "C" void kernel_launch(void* const* d_in, const int* in_sizes, int n_in,
                              void* d_out, int out_size) {
    const int*   info      = (const int*)d_in[0];
    const int*   info_idx  = (const int*)d_in[1];
    const int*   num_sent  = (const int*)d_in[2];
    const int*   question  = (const int*)d_in[3];
    const int*   qidx      = (const int*)d_in[4];
    const float* info_emb  = (const float*)d_in[5];
    const float* Wi        = (const float*)d_in[6];
    const float* Ui        = (const float*)d_in[7];
    const float* bi        = (const float*)d_in[8];
    const float* q_emb     = (const float*)d_in[9];
    const float* Wq        = (const float*)d_in[10];
    const float* Uq        = (const float*)d_in[11];
    const float* bq        = (const float*)d_in[12];
    const float* Wm        = (const float*)d_in[13];
    const float* Um        = (const float*)d_in[14];
    const float* bm        = (const float*)d_in[15];
    const float* Wa        = (const float*)d_in[16];
    const float* Ua        = (const float*)d_in[17];
    const float* ba        = (const float*)d_in[18];
    float* out = (float*)d_out;

    float *tbl_i, *tbl_q, *hinfo, *hq, *prod, *xzm, *hidden, *xza, *rec, *hA, *hB;
    uint4 *uaPk, *hAPk;
    cudaGetSymbolAddress((void**)&tbl_i, g_table_i);
    cudaGetSymbolAddress((void**)&tbl_q, g_table_q);
    cudaGetSymbolAddress((void**)&hinfo, g_hinfo);
    cudaGetSymbolAddress((void**)&hq, g_hq);
    cudaGetSymbolAddress((void**)&prod, g_prod);
    cudaGetSymbolAddress((void**)&xzm, g_xzm);
    cudaGetSymbolAddress((void**)&hidden, g_hidden);
    cudaGetSymbolAddress((void**)&xza, g_xza);
    cudaGetSymbolAddress((void**)&rec, g_rec);
    cudaGetSymbolAddress((void**)&hA, g_hA);
    cudaGetSymbolAddress((void**)&hB, g_hB);
    cudaGetSymbolAddress((void**)&uaPk, g_UaPk);
    cudaGetSymbolAddress((void**)&hAPk, g_hAPk);

    const size_t smemR = ((size_t)RUN * 48 + (size_t)16 * RUN) * 8;
    const size_t smemM = ((size_t)MEM * 48 + (size_t)16 * MEM) * 8;
    const size_t ansSmem = (size_t)CHUNK_KC * 6 * 32 * 16 + 8 * 32 * 24 * 4;   // 101376

    static bool attr_set = false;
    if (!attr_set) {
        cudaFuncSetAttribute(gru_seq_kernel<RUN>,
                             cudaFuncAttributeMaxDynamicSharedMemorySize, (int)smemR);
        cudaFuncSetAttribute(gru_seq_kernel<MEM>,
                             cudaFuncAttributeMaxDynamicSharedMemorySize, (int)smemM);
        cudaFuncSetAttribute(ans_gemm_kernel,
                             cudaFuncAttributeMaxDynamicSharedMemorySize, (int)ansSmem);
        attr_set = true;
    }

    const dim3 blk(16, 4, 2);

    build_table_kernel<<<dim3((3 * RUN + 255) / 256, 1024), 256>>>(info_emb, Wi, bi, tbl_i, 3 * RUN);
    build_table_kernel<<<dim3((3 * RUN + 255) / 256, 64), 256>>>(q_emb, Wq, bq, tbl_q, 3 * RUN);

    {
        size_t F = (size_t)NBLK * NCH * 32;
        prep_ua_frag<<<(unsigned)((F + 255) / 256), 256>>>(Ua, uaPk);
    }

    // info GRU (T=1024, H=400)
    gru_seq_kernel<RUN><<<dim3((RUN + 31) / 32, 8), blk, smemR>>>(
        tbl_i, info, Ui, bi + 3 * RUN, hA, hB, hinfo, nullptr, SLEN);

    // question GRU (T=64, H=400)
    gru_seq_kernel<RUN><<<dim3((RUN + 31) / 32, 8), blk, smemR>>>(
        tbl_q, question, Uq, bq + 3 * RUN, hA, hB, hq, nullptr, QLEN);

    prod_kernel<<<dim3(NSENT, BATCH), 128>>>(hinfo, hq, info_idx, num_sent, qidx, prod);

    gemm_bias_kernel<<<dim3((3 * MEM + 63) / 64, (BATCH * NSENT) / 64), 256>>>(
        prod, Wm, bm, xzm, BATCH * NSENT, RUN, 3 * MEM);

    // memory GRU (T=64, H=300)
    gru_seq_kernel<MEM><<<dim3((MEM + 31) / 32, 8), blk, smemM>>>(
        xzm, nullptr, Um, bm + 3 * MEM, hA, hB, hidden, num_sent, NSENT);

    gemm_bias_kernel<<<dim3((N3V + 63) / 64, (BATCH * NSENT) / 64), 256>>>(
        hidden, Wa, ba, xza, BATCH * NSENT, MEM, N3V);

    // --- answer loop: 2 kernels per step, graph-ordered ---
    ans_init_kernel<<<148, 256>>>(hA, hAPk);
    {
        float* hp = hA;
        float* hn = hB;
        for (int n = 0; n < NSENT; ++n) {
            ans_gemm_kernel<<<ANS_NT, ANS_THR, ansSmem>>>(ba + N3V, rec, uaPk, hAPk);
            ans_update_kernel<<<BATCH, 256>>>(xza, rec, hp, hn, out, hAPk, n);
            float* tmp = hp; hp = hn; hn = tmp;
        }
    }
}

// round 17
// speedup vs baseline: 1.9734x; 1.0436x over previous
#include <cuda_runtime.h>
#include <cuda_bf16.h>
#include <cuda_fp16.h>
#include <cstdint>

#define BATCH 128
#define SLEN  1024
#define NSENT 64
#define QLEN  64
#define EMB   50
#define RUN   400
#define MEM   300
#define VOC   2000
#define N3V   (3 * VOC)      // 6000
#define NCH   125            // answer k16 chunks (2000/16)
#define NBLK  750            // n8 blocks (6000/8)
#define KCH2  19             // xza k16 chunks (ceil(300/16))
#define MB2   512            // xza m-blocks (8192/16)

typedef unsigned long long ull;

__device__ __forceinline__ ull pack2(float lo, float hi) {
    ull r; asm("mov.b64 %0, {%1, %2};" : "=l"(r) : "f"(lo), "f"(hi)); return r;
}
__device__ __forceinline__ ull pdup(float v) { return pack2(v, v); }
__device__ __forceinline__ void fma2(ull& d, ull a, ull b) {
    asm("fma.rn.f32x2 %0, %1, %2, %0;" : "+l"(d) : "l"(a), "l"(b));
}
__device__ __forceinline__ void add2(ull& d, ull a) {
    asm("add.rn.f32x2 %0, %0, %1;" : "+l"(d) : "l"(a));
}
__device__ __forceinline__ float2 unpack2(ull v) {
    float2 r; asm("mov.b64 {%0, %1}, %2;" : "=f"(r.x), "=f"(r.y) : "l"(v)); return r;
}

// fp16 HMMA m16n8k16, f32 accum
__device__ __forceinline__ void mma_f16(float& c0, float& c1, float& c2, float& c3,
                                        uint32_t a0, uint32_t a1, uint32_t a2, uint32_t a3,
                                        uint32_t b0, uint32_t b1) {
    asm volatile(
        "mma.sync.aligned.m16n8k16.row.col.f32.f16.f16.f32 "
        "{%0,%1,%2,%3}, {%4,%5,%6,%7}, {%8,%9}, {%0,%1,%2,%3};"
        : "+f"(c0), "+f"(c1), "+f"(c2), "+f"(c3)
        : "r"(a0), "r"(a1), "r"(a2), "r"(a3), "r"(b0), "r"(b1));
}

__device__ __forceinline__ uint32_t pk_h2(float x, float y) {
    __half2 h = __floats2half2_rn(x, y);
    return *reinterpret_cast<uint32_t*>(&h);
}
__device__ __forceinline__ float h_hi(float v) {
    __half h = __float2half_rn(v);
    return __half2float(h);
}

// ---------------------------------------------------------------------------
// Device scratch
// ---------------------------------------------------------------------------
__device__ float g_table_i[1024 * 3 * RUN];
__device__ float g_table_q[64 * 3 * RUN];
__device__ float g_hinfo[(size_t)BATCH * SLEN * RUN];
__device__ float g_hq[(size_t)BATCH * QLEN * RUN];
__device__ float g_prod[(size_t)BATCH * NSENT * RUN];
__device__ float g_xzm[(size_t)BATCH * NSENT * 3 * MEM];
__device__ float g_hidden[(size_t)BATCH * NSENT * MEM];
__device__ float g_xza[(size_t)BATCH * NSENT * N3V];
__device__ float g_rec[(size_t)BATCH * N3V];
__device__ float g_hA[(size_t)BATCH * VOC];
__device__ float g_hB[(size_t)BATCH * VOC];
__device__ uint4 g_UaPk[(size_t)NBLK * NCH * 32];
__device__ uint4 g_hAPk[(size_t)8 * NCH * 32];
// xza HMMA scratch
__device__ uint4 g_WaPk[(size_t)NBLK * KCH2 * 32];
__device__ uint4 g_hHi[(size_t)MB2 * KCH2 * 32];
__device__ uint4 g_hLo[(size_t)MB2 * KCH2 * 32];

__device__ unsigned g_cnt[16 * 32];
__device__ volatile unsigned g_sns[16 * 32];

__device__ __forceinline__ float sigmoidf_(float x) { return 1.f / (1.f + expf(-x)); }

__device__ __forceinline__ void group_barrier(int slot, unsigned G, unsigned& sense) {
    __syncthreads();
    sense ^= 1u;
    if (threadIdx.x == 0 && threadIdx.y == 0 && threadIdx.z == 0) {
        __threadfence();
        unsigned prev = atomicAdd(&g_cnt[slot * 32], 1u);
        if (prev == G - 1u) {
            g_cnt[slot * 32] = 0u;
            __threadfence();
            g_sns[slot * 32] = sense;
        } else {
            while (g_sns[slot * 32] != sense) { }
        }
        __threadfence();
    }
    __syncthreads();
}

// ---------------------------------------------------------------------------
// table build
// ---------------------------------------------------------------------------
__global__ void build_table_kernel(const float* __restrict__ emb,
                                   const float* __restrict__ W,
                                   const float* __restrict__ b0,
                                   float* __restrict__ table,
                                   int N3) {
    int v = blockIdx.y;
    int j = blockIdx.x * blockDim.x + threadIdx.x;
    __shared__ float se[EMB];
    if (threadIdx.x < EMB) se[threadIdx.x] = emb[(size_t)v * EMB + threadIdx.x];
    __syncthreads();
    if (j < N3) {
        float acc = b0[j];
#pragma unroll 10
        for (int e = 0; e < EMB; ++e) acc += se[e] * W[(size_t)e * N3 + j];
        table[(size_t)v * N3 + j] = acc;
    }
}

// ---------------------------------------------------------------------------
// Ua -> packed fp16 B fragments (hi/lo), fragment-major. (answer, K=2000)
// ---------------------------------------------------------------------------
__global__ void prep_ua_frag(const float* __restrict__ Ua, uint4* __restrict__ dst) {
    size_t fp = (size_t)blockIdx.x * blockDim.x + threadIdx.x;
    if (fp >= (size_t)NBLK * NCH * 32) return;
    int l  = fp & 31;
    int kc = (int)((fp >> 5) % NCH);
    int nb = (int)((fp >> 5) / NCH);
    int n = nb * 8 + (l >> 2);
    int k = kc * 16 + 2 * (l & 3);
    float u0 = Ua[(size_t)k * N3V + n];
    float u1 = Ua[(size_t)(k + 1) * N3V + n];
    float u8 = Ua[(size_t)(k + 8) * N3V + n];
    float u9 = Ua[(size_t)(k + 9) * N3V + n];
    float h0 = h_hi(u0), h1 = h_hi(u1), h8 = h_hi(u8), h9 = h_hi(u9);
    uint4 v;
    v.x = pk_h2(h0, h1);
    v.y = pk_h2(h8, h9);
    v.z = pk_h2(u0 - h0, u1 - h1);
    v.w = pk_h2(u8 - h8, u9 - h9);
    dst[fp] = v;
}

// ---------------------------------------------------------------------------
// Wa [300,6000] -> packed fp16 B fragments (hi/lo), K padded to 304.
// ---------------------------------------------------------------------------
__global__ void prep_wa_frag(const float* __restrict__ Wa, uint4* __restrict__ dst) {
    size_t fp = (size_t)blockIdx.x * blockDim.x + threadIdx.x;
    if (fp >= (size_t)NBLK * KCH2 * 32) return;
    int l  = fp & 31;
    int kc = (int)((fp >> 5) % KCH2);
    int nb = (int)((fp >> 5) / KCH2);
    int n = nb * 8 + (l >> 2);
    int k = kc * 16 + 2 * (l & 3);
    float u0 = (k     < MEM) ? Wa[(size_t)k * N3V + n] : 0.f;
    float u1 = (k + 1 < MEM) ? Wa[(size_t)(k + 1) * N3V + n] : 0.f;
    float u8 = (k + 8 < MEM) ? Wa[(size_t)(k + 8) * N3V + n] : 0.f;
    float u9 = (k + 9 < MEM) ? Wa[(size_t)(k + 9) * N3V + n] : 0.f;
    float h0 = h_hi(u0), h1 = h_hi(u1), h8 = h_hi(u8), h9 = h_hi(u9);
    uint4 v;
    v.x = pk_h2(h0, h1);
    v.y = pk_h2(h8, h9);
    v.z = pk_h2(u0 - h0, u1 - h1);
    v.w = pk_h2(u8 - h8, u9 - h9);
    dst[fp] = v;
}

// ---------------------------------------------------------------------------
// hidden [8192,300] -> A fragments hi/lo [512 mb][19 kc][32].
// frag uint4: .x=(r, c..c+1) .y=(r+8, c..c+1) .z=(r, c+8..c+9) .w=(r+8, ...)
// ---------------------------------------------------------------------------
__global__ void prep_h_frag(const float* __restrict__ hidden,
                            uint4* __restrict__ hi4, uint4* __restrict__ lo4) {
    size_t fp = (size_t)blockIdx.x * blockDim.x + threadIdx.x;
    if (fp >= (size_t)MB2 * KCH2 * 32) return;
    int l  = fp & 31;
    int kc = (int)((fp >> 5) % KCH2);
    int mb = (int)((fp >> 5) / KCH2);
    int r = mb * 16 + (l >> 2);
    int c = kc * 16 + 2 * (l & 3);
    const float* h0r = hidden + (size_t)r * MEM;
    const float* h1r = hidden + (size_t)(r + 8) * MEM;
    float v00 = (c     < MEM) ? h0r[c]     : 0.f;
    float v01 = (c + 1 < MEM) ? h0r[c + 1] : 0.f;
    float v10 = (c     < MEM) ? h1r[c]     : 0.f;
    float v11 = (c + 1 < MEM) ? h1r[c + 1] : 0.f;
    float w00 = (c + 8 < MEM) ? h0r[c + 8] : 0.f;
    float w01 = (c + 9 < MEM) ? h0r[c + 9] : 0.f;
    float w10 = (c + 8 < MEM) ? h1r[c + 8] : 0.f;
    float w11 = (c + 9 < MEM) ? h1r[c + 9] : 0.f;
    float a = h_hi(v00), b = h_hi(v01), cc0 = h_hi(v10), d = h_hi(v11);
    float e = h_hi(w00), f = h_hi(w01), g = h_hi(w10), hh = h_hi(w11);
    uint4 H, L;
    H.x = pk_h2(a, b);   L.x = pk_h2(v00 - a, v01 - b);
    H.y = pk_h2(cc0, d); L.y = pk_h2(v10 - cc0, v11 - d);
    H.z = pk_h2(e, f);   L.z = pk_h2(w00 - e, w01 - f);
    H.w = pk_h2(g, hh);  L.w = pk_h2(w10 - g, w11 - hh);
    hi4[fp] = H;
    lo4[fp] = L;
}

// ---------------------------------------------------------------------------
// xza HMMA GEMM: xza[8192,6000] = hidden @ Wa + ba0 (3-MMA hi/lo).
// grid (125 n-tiles, 64 m-tiles), 256 thr. B tile staged once in smem.
// ---------------------------------------------------------------------------
__global__ void __launch_bounds__(256, 2)
xza_gemm_kernel(const float* __restrict__ ba0,
                float* __restrict__ xza,
                const uint4* __restrict__ WaPk,
                const uint4* __restrict__ hHi,
                const uint4* __restrict__ hLo) {
    extern __shared__ __align__(16) uint4 sB[];   // [KCH2*6*32] = 58368 B
    const int tid = threadIdx.x;
    const int wid = tid >> 5;
    const int lid = tid & 31;
    const int nbBase = blockIdx.x * 6;
    const int mbG = blockIdx.y * 8 + wid;

    for (int e = tid; e < KCH2 * 6 * 32; e += 256) {
        int nb  = e / (KCH2 * 32);
        int rem = e - nb * (KCH2 * 32);
        int kc  = rem >> 5;
        int l   = rem & 31;
        sB[(kc * 6 + nb) * 32 + l] =
            WaPk[((size_t)(nbBase + nb) * KCH2 + kc) * 32 + l];
    }
    __syncthreads();

    float acc[6][4];
#pragma unroll
    for (int i = 0; i < 6; ++i)
#pragma unroll
        for (int c = 0; c < 4; ++c) acc[i][c] = 0.f;

    const uint4* Ah = hHi + (size_t)mbG * KCH2 * 32 + lid;
    const uint4* Al = hLo + (size_t)mbG * KCH2 * 32 + lid;

    uint4 a  = Ah[0];
    uint4 al = Al[0];
    for (int kc = 0; kc < KCH2; ++kc) {
        uint4 an, aln;
        if (kc + 1 < KCH2) { an = Ah[(kc + 1) * 32]; aln = Al[(kc + 1) * 32]; }
        const uint4* bp = sB + kc * 192 + lid;
#pragma unroll
        for (int nb = 0; nb < 6; ++nb) {
            uint4 b = bp[nb * 32];
            mma_f16(acc[nb][0], acc[nb][1], acc[nb][2], acc[nb][3],
                    a.x, a.y, a.z, a.w, b.x, b.y);       // Ahi*Bhi
            mma_f16(acc[nb][0], acc[nb][1], acc[nb][2], acc[nb][3],
                    a.x, a.y, a.z, a.w, b.z, b.w);       // Ahi*Blo
            mma_f16(acc[nb][0], acc[nb][1], acc[nb][2], acc[nb][3],
                    al.x, al.y, al.z, al.w, b.x, b.y);   // Alo*Bhi
        }
        if (kc + 1 < KCH2) { a = an; al = aln; }
    }

    const int r0 = mbG * 16 + (lid >> 2);
#pragma unroll
    for (int nb = 0; nb < 6; ++nb) {
        int nc = (nbBase + nb) * 8 + 2 * (lid & 3);
        float b0 = ba0[nc], b1 = ba0[nc + 1];
        float2 v0 = { acc[nb][0] + b0, acc[nb][1] + b1 };
        float2 v1 = { acc[nb][2] + b0, acc[nb][3] + b1 };
        *reinterpret_cast<float2*>(xza + (size_t)r0 * N3V + nc) = v0;
        *reinterpret_cast<float2*>(xza + (size_t)(r0 + 8) * N3V + nc) = v1;
    }
}

// ---------------------------------------------------------------------------
// Persistent GRU (r15 form, unchanged).
// ---------------------------------------------------------------------------
template <int H>
__global__ void __launch_bounds__(128, 1)
gru_seq_kernel(const float* __restrict__ xz,
               const int* __restrict__ tok,
               const float* __restrict__ U,
               const float* __restrict__ brec,
               float* __restrict__ hP, float* __restrict__ hQ,
               float* __restrict__ seq_out,
               const int* __restrict__ num_sent,
               int T) {
    extern __shared__ __align__(16) ull smu[];
    ull* su2 = smu;            // [H][48]
    ull* shd = smu + H * 48;   // [16][H]
    __shared__ ull sred[64 * 12];

    const int tx = threadIdx.x;
    const int ty = threadIdx.y;
    const int tz = threadIdx.z;
    const int tid64 = ty * 16 + tx;
    const int tid = tz * 64 + tid64;
    const int j0 = blockIdx.x * 32;
    const int b0 = blockIdx.y * 16;
    const int N3 = 3 * H;
    const int slot = blockIdx.y;
    const unsigned G = gridDim.x;
    unsigned sense = g_sns[slot * 32];

    for (int e = tid; e < H * 48; e += 128) {
        int k = e / 48, c = e - k * 48;
        int g = c >> 4, p = c & 15;
        int j = j0 + 2 * p;
        float lo = (j < H) ? U[(size_t)k * N3 + g * H + j] : 0.f;
        float hi = (j + 1 < H) ? U[(size_t)k * N3 + g * H + j + 1] : 0.f;
        su2[e] = pack2(lo, hi);
    }
    for (int e = tid; e < 16 * 32; e += 128) {
        int bb = e >> 5, jj = e & 31;
        if (j0 + jj < H) hP[(size_t)(b0 + bb) * H + j0 + jj] = 0.f;
    }
    group_barrier(slot, G, sense);

    float* hp = hP;
    float* hn = hQ;

    const int jA = j0 + 2 * tx;
    const int jB = jA + 1;
    float bzA = 0, brA = 0, bhA = 0, bzB = 0, brB = 0, bhB = 0;
    if (jA < H) { bzA = brec[jA]; brA = brec[H + jA]; bhA = brec[2 * H + jA]; }
    if (jB < H) { bzB = brec[jB]; brB = brec[H + jB]; bhB = brec[2 * H + jB]; }

    constexpr int Hh = H / 2;
    constexpr int Hq = H / 4;
    const int kBeg = tz * Hh;
    const ull* up = su2 + tx;

    for (int t = 0; t < T; ++t) {
        ull xzp[4], xrp[4], xhp[4];
        int padi[4];
        if (tz == 0 && jA < H) {
#pragma unroll
            for (int r = 0; r < 4; ++r) {
                const int b = b0 + 4 * ty + r;
                const float* xrow;
                if (tok) xrow = xz + (size_t)tok[(size_t)b * T + t] * N3;
                else     xrow = xz + ((size_t)b * T + t) * N3;
                xzp[r] = *reinterpret_cast<const ull*>(xrow + jA);
                xrp[r] = *reinterpret_cast<const ull*>(xrow + H + jA);
                xhp[r] = *reinterpret_cast<const ull*>(xrow + 2 * H + jA);
                padi[r] = num_sent ? num_sent[b] : 0x7fffffff;
            }
        }

        for (int e = tid; e < 16 * Hq; e += 128) {
            int row = e / Hq, q = e - row * Hq;
            float4 v = *reinterpret_cast<const float4*>(hp + (size_t)(b0 + row) * H + 4 * q);
            ull* d = shd + row * H + 4 * q;
            d[0] = pdup(v.x); d[1] = pdup(v.y); d[2] = pdup(v.z); d[3] = pdup(v.w);
        }
        __syncthreads();

        ull az[4] = {0,0,0,0}, ar[4] = {0,0,0,0}, ah[4] = {0,0,0,0};
        const ull* h0p = shd + (4 * ty + 0) * H + kBeg;
        const ull* h1p = shd + (4 * ty + 1) * H + kBeg;
        const ull* h2p = shd + (4 * ty + 2) * H + kBeg;
        const ull* h3p = shd + (4 * ty + 3) * H + kBeg;
        const ull* ub = up + kBeg * 48;
#pragma unroll 4
        for (int kk = 0; kk < Hh; ++kk) {
            ull uz = ub[kk * 48];
            ull ur = ub[kk * 48 + 16];
            ull uh = ub[kk * 48 + 32];
            ull h0 = h0p[kk], h1 = h1p[kk], h2 = h2p[kk], h3 = h3p[kk];
            fma2(az[0], h0, uz); fma2(az[1], h1, uz); fma2(az[2], h2, uz); fma2(az[3], h3, uz);
            fma2(ar[0], h0, ur); fma2(ar[1], h1, ur); fma2(ar[2], h2, ur); fma2(ar[3], h3, ur);
            fma2(ah[0], h0, uh); fma2(ah[1], h1, uh); fma2(ah[2], h2, uh); fma2(ah[3], h3, uh);
        }

        if (tz == 1) {
            ull* s = sred + tid64 * 12;
#pragma unroll
            for (int r = 0; r < 4; ++r) { s[r] = az[r]; s[4 + r] = ar[r]; s[8 + r] = ah[r]; }
        }
        __syncthreads();

        if (tz == 0) {
            const ull* s = sred + tid64 * 12;
#pragma unroll
            for (int r = 0; r < 4; ++r) { add2(az[r], s[r]); add2(ar[r], s[4 + r]); add2(ah[r], s[8 + r]); }

            if (jA < H) {
#pragma unroll
                for (int r = 0; r < 4; ++r) {
                    const int row = 4 * ty + r;
                    const int b = b0 + row;
                    float2 AZ = unpack2(az[r]);
                    float2 AR = unpack2(ar[r]);
                    float2 AH = unpack2(ah[r]);
                    float2 XZ = unpack2(xzp[r]);
                    float2 XR = unpack2(xrp[r]);
                    float2 XH = unpack2(xhp[r]);
                    float padv = (t <= padi[r]) ? 1.f : 0.f;
                    {
                        float z  = sigmoidf_(XZ.x + AZ.x + bzA);
                        float rr = sigmoidf_(XR.x + AR.x + brA);
                        float hh = tanhf(XH.x + rr * (AH.x + bhA));
                        float hprev = unpack2(shd[row * H + jA]).x;
                        float hnew = z * hprev + (1.f - z) * hh;
                        hn[(size_t)b * H + jA] = hnew;
                        seq_out[((size_t)b * T + t) * H + jA] = hnew * padv;
                    }
                    if (jB < H) {
                        float z  = sigmoidf_(XZ.y + AZ.y + bzB);
                        float rr = sigmoidf_(XR.y + AR.y + brB);
                        float hh = tanhf(XH.y + rr * (AH.y + bhB));
                        float hprev = unpack2(shd[row * H + jB]).x;
                        float hnew = z * hprev + (1.f - z) * hh;
                        hn[(size_t)b * H + jB] = hnew;
                        seq_out[((size_t)b * T + t) * H + jB] = hnew * padv;
                    }
                }
            }
        }
        group_barrier(slot, G, sense);
        float* tmp = hp; hp = hn; hn = tmp;
    }
}

// ---------------------------------------------------------------------------
// prod
// ---------------------------------------------------------------------------
__global__ void prod_kernel(const float* __restrict__ hinfo,
                            const float* __restrict__ hq,
                            const int* __restrict__ info_idx,
                            const int* __restrict__ num_sent,
                            const int* __restrict__ qidx,
                            float* __restrict__ prod) {
    const int nn = blockIdx.x;
    const int b  = blockIdx.y;
    const int si = info_idx[b * NSENT + nn];
    const int qi = qidx[b] - 1;
    const float padv = (nn <= num_sent[b]) ? 1.f : 0.f;
    const float* hi  = hinfo + ((size_t)b * SLEN + si) * RUN;
    const float* hqr = hq + ((size_t)b * QLEN + qi) * RUN;
    float* pr = prod + ((size_t)b * NSENT + nn) * RUN;
    for (int jj = threadIdx.x; jj < RUN; jj += blockDim.x)
        pr[jj] = hi[jj] * hqr[jj] * padv;
}

// ---------------------------------------------------------------------------
// Generic C = A@W + bias (xzm only now)
// ---------------------------------------------------------------------------
__global__ void gemm_bias_kernel(const float* __restrict__ A,
                                 const float* __restrict__ W,
                                 const float* __restrict__ bias,
                                 float* __restrict__ C,
                                 int Mdim, int Kdim, int Ndim) {
    __shared__ __align__(16) float As[16][68];
    __shared__ __align__(16) float Bs[16][68];
    const int tid = threadIdx.x;
    const int tx = tid & 15;
    const int ty = tid >> 4;
    const int m0 = blockIdx.y * 64;
    const int n0 = blockIdx.x * 64;

    float acc[4][4];
#pragma unroll
    for (int i = 0; i < 4; ++i)
#pragma unroll
        for (int jj = 0; jj < 4; ++jj) acc[i][jj] = 0.f;

    for (int k0 = 0; k0 < Kdim; k0 += 16) {
        for (int e = tid; e < 1024; e += 256) {
            int mm = e >> 4, kk = e & 15;
            int m = m0 + mm, k = k0 + kk;
            As[kk][mm] = (m < Mdim && k < Kdim) ? A[(size_t)m * Kdim + k] : 0.f;
        }
        for (int e = tid; e < 1024; e += 256) {
            int kk = e >> 6, nn = e & 63;
            int k = k0 + kk, nv = n0 + nn;
            Bs[kk][nn] = (k < Kdim && nv < Ndim) ? W[(size_t)k * Ndim + nv] : 0.f;
        }
        __syncthreads();
#pragma unroll
        for (int kk = 0; kk < 16; ++kk) {
            float4 a4 = *reinterpret_cast<const float4*>(&As[kk][ty * 4]);
            float4 b4 = *reinterpret_cast<const float4*>(&Bs[kk][tx * 4]);
            float av[4] = {a4.x, a4.y, a4.z, a4.w};
            float bv[4] = {b4.x, b4.y, b4.z, b4.w};
#pragma unroll
            for (int i = 0; i < 4; ++i)
#pragma unroll
                for (int jj = 0; jj < 4; ++jj) acc[i][jj] += av[i] * bv[jj];
        }
        __syncthreads();
    }
#pragma unroll
    for (int i = 0; i < 4; ++i) {
        int m = m0 + ty * 4 + i;
        if (m >= Mdim) continue;
#pragma unroll
        for (int jj = 0; jj < 4; ++jj) {
            int nv = n0 + tx * 4 + jj;
            if (nv < Ndim) C[(size_t)m * Ndim + nv] = acc[i][jj] + bias[nv];
        }
    }
}

// ---------------------------------------------------------------------------
// Answer step kernels (r16 form).
// ---------------------------------------------------------------------------
#define ANS_NT    125
#define CHUNK_KC  25
#define NCHUNKS   5
#define ANS_THR   512
#define PF_N      10

__global__ void ans_init_kernel(float* __restrict__ hP, uint4* __restrict__ hAPk) {
    int e = blockIdx.x * 256 + threadIdx.x;
    for (int i = e; i < BATCH * VOC; i += gridDim.x * 256) hP[i] = 0.f;
    uint4 z4 = make_uint4(0, 0, 0, 0);
    for (int i = e; i < 8 * NCH * 32; i += gridDim.x * 256) hAPk[i] = z4;
}

__global__ void __launch_bounds__(ANS_THR, 1)
ans_gemm_kernel(const float* __restrict__ ba1,
                float* __restrict__ rec,
                const uint4* __restrict__ UaPk,
                const uint4* __restrict__ hAPk) {
    extern __shared__ __align__(16) char dyn[];
    uint4* sB   = (uint4*)dyn;
    float* sAcc = (float*)(dyn + CHUNK_KC * 6 * 32 * 16);

    const int tid = threadIdx.x;
    const int wid = tid >> 5;
    const int lid = tid & 31;
    const int nbBase = blockIdx.x * 6;
    const int mb = wid & 7;
    const int half = wid >> 3;

    float acc[6][4];
#pragma unroll
    for (int i = 0; i < 6; ++i)
#pragma unroll
        for (int c = 0; c < 4; ++c) acc[i][c] = 0.f;

    const uint4* ABase = hAPk + (size_t)mb * NCH * 32 + lid;

    int sIdx[PF_N];
    size_t gOff[PF_N];
#pragma unroll
    for (int p = 0; p < PF_N; ++p) {
        int e = p * ANS_THR + tid;
        if (e < CHUNK_KC * 6 * 32) {
            int nb  = e / (CHUNK_KC * 32);
            int rem = e - nb * (CHUNK_KC * 32);
            int kc  = rem >> 5;
            int l   = rem & 31;
            sIdx[p] = (kc * 6 + nb) * 32 + l;
            gOff[p] = ((size_t)(nbBase + nb) * NCH + kc) * 32 + l;
        } else { sIdx[p] = -1; gOff[p] = 0; }
    }

#pragma unroll
    for (int p = 0; p < PF_N; ++p)
        if (sIdx[p] >= 0) sB[sIdx[p]] = UaPk[gOff[p]];

    for (int ch = 0; ch < NCHUNKS; ++ch) {
        __syncthreads();

        uint4 pf[PF_N];
        if (ch + 1 < NCHUNKS) {
            const size_t shift = (size_t)(ch + 1) * CHUNK_KC * 32;
#pragma unroll
            for (int p = 0; p < PF_N; ++p)
                if (sIdx[p] >= 0) pf[p] = UaPk[gOff[p] + shift];
        }

        const int kc0 = ch * CHUNK_KC;
        uint4 aq0 = ABase[(size_t)(kc0 + half) * 32];
        uint4 aq1 = ABase[(size_t)(kc0 + half + 2) * 32];
        for (int kc = half; kc < CHUNK_KC; kc += 2) {
            uint4 a = aq0;
            aq0 = aq1;
            if (kc + 4 < CHUNK_KC)
                aq1 = ABase[(size_t)(kc0 + kc + 4) * 32];
            const uint4* bp = sB + kc * 192 + lid;
#pragma unroll
            for (int nb = 0; nb < 6; ++nb) {
                uint4 b = bp[nb * 32];
                mma_f16(acc[nb][0], acc[nb][1], acc[nb][2], acc[nb][3],
                        a.x, a.y, a.z, a.w, b.x, b.y);
                mma_f16(acc[nb][0], acc[nb][1], acc[nb][2], acc[nb][3],
                        a.x, a.y, a.z, a.w, b.z, b.w);
            }
        }

        __syncthreads();
        if (ch + 1 < NCHUNKS) {
#pragma unroll
            for (int p = 0; p < PF_N; ++p)
                if (sIdx[p] >= 0) sB[sIdx[p]] = pf[p];
        }
    }

    __syncthreads();
    if (half == 1) {
        float* s = sAcc + (mb * 32 + lid) * 24;
#pragma unroll
        for (int nb = 0; nb < 6; ++nb)
#pragma unroll
            for (int c = 0; c < 4; ++c) s[nb * 4 + c] = acc[nb][c];
    }
    __syncthreads();
    if (half == 0) {
        const float* s = sAcc + (mb * 32 + lid) * 24;
#pragma unroll
        for (int nb = 0; nb < 6; ++nb)
#pragma unroll
            for (int c = 0; c < 4; ++c) acc[nb][c] += s[nb * 4 + c];

        const int r0 = mb * 16 + (lid >> 2);
#pragma unroll
        for (int nb = 0; nb < 6; ++nb) {
            int nc = (nbBase + nb) * 8 + 2 * (lid & 3);
            float b0 = ba1[nc], b1 = ba1[nc + 1];
            float2 v0 = { acc[nb][0] + b0, acc[nb][1] + b1 };
            float2 v1 = { acc[nb][2] + b0, acc[nb][3] + b1 };
            *reinterpret_cast<float2*>(rec + (size_t)r0 * N3V + nc) = v0;
            *reinterpret_cast<float2*>(rec + (size_t)(r0 + 8) * N3V + nc) = v1;
        }
    }
}

__global__ void __launch_bounds__(256, 1)
ans_update_kernel(const float* __restrict__ xza,
                  const float* __restrict__ rec,
                  const float* __restrict__ hp,
                  float* __restrict__ hn,
                  float* __restrict__ out,
                  uint4* __restrict__ hAPk,
                  int n) {
    __shared__ float red[256];
    const int tid = threadIdx.x;
    const int b = blockIdx.x;

    const float* xrow = xza + ((size_t)b * NSENT + n) * N3V;
    const float* rrow = rec + (size_t)b * N3V;
    float zv[8], tv[8];
    float m = -1e30f;
#pragma unroll
    for (int i = 0; i < 8; ++i) {
        int jj = tid + i * 256;
        if (jj < VOC) {
            float z = sigmoidf_(xrow[jj] + rrow[jj]);
            float r = sigmoidf_(xrow[VOC + jj] + rrow[VOC + jj]);
            float t = xrow[2 * VOC + jj] + r * rrow[2 * VOC + jj];
            zv[i] = z; tv[i] = t;
            m = fmaxf(m, t);
        } else { zv[i] = 0.f; tv[i] = -1e30f; }
    }
    red[tid] = m; __syncthreads();
    for (int s = 128; s > 0; s >>= 1) {
        if (tid < s) red[tid] = fmaxf(red[tid], red[tid + s]);
        __syncthreads();
    }
    m = red[0]; __syncthreads();

    float ev[8];
    float sum = 0.f;
#pragma unroll
    for (int i = 0; i < 8; ++i) {
        int jj = tid + i * 256;
        if (jj < VOC) { ev[i] = expf(tv[i] - m); sum += ev[i]; }
        else ev[i] = 0.f;
    }
    red[tid] = sum; __syncthreads();
    for (int s = 128; s > 0; s >>= 1) {
        if (tid < s) red[tid] += red[tid + s];
        __syncthreads();
    }
    const float inv = 1.f / red[0];
    __syncthreads();

#pragma unroll
    for (int i = 0; i < 8; ++i) {
        int jj = tid + i * 256;
        if (jj < VOC) {
            float hh = ev[i] * inv;
            float z  = zv[i];
            float hprev = hp[(size_t)b * VOC + jj];
            float hnew = z * hprev + (1.f - z) * hh;
            hn[(size_t)b * VOC + jj] = hnew;
            out[((size_t)b * NSENT + n) * VOC + jj] = hnew;
        }
    }
    __syncthreads();

    {
        const int mb = b >> 4;
        const int rpos = b & 15;
        const int hiHalf = (rpos >> 3) & 1;
        const int rp = rpos & 7;
        const float* hrow = hn + (size_t)b * VOC;
        for (int e = tid; e < NCH * 8; e += 256) {
            int kc = e >> 3;
            int rem = e & 7;
            int j = rem >> 1;
            int slot = rem & 1;
            int c = kc * 16 + 2 * j + 8 * slot;
            float2 v = *reinterpret_cast<const float2*>(hrow + c);
            uint32_t w = pk_h2(v.x, v.y);
            size_t f = ((size_t)mb * NCH + kc) * 32 + 4 * rp + j;
            int comp = (slot << 1) | hiHalf;
            reinterpret_cast<uint32_t*>(&hAPk[f])[comp] = w;
        }
    }
}

// ---------------------------------------------------------------------------
// Host orchestration
// ---------------------------------------------------------------------------
extern "C" void kernel_launch(void* const* d_in, const int* in_sizes, int n_in,
                              void* d_out, int out_size) {
    const int*   info      = (const int*)d_in[0];
    const int*   info_idx  = (const int*)d_in[1];
    const int*   num_sent  = (const int*)d_in[2];
    const int*   question  = (const int*)d_in[3];
    const int*   qidx      = (const int*)d_in[4];
    const float* info_emb  = (const float*)d_in[5];
    const float* Wi        = (const float*)d_in[6];
    const float* Ui        = (const float*)d_in[7];
    const float* bi        = (const float*)d_in[8];
    const float* q_emb     = (const float*)d_in[9];
    const float* Wq        = (const float*)d_in[10];
    const float* Uq        = (const float*)d_in[11];
    const float* bq        = (const float*)d_in[12];
    const float* Wm        = (const float*)d_in[13];
    const float* Um        = (const float*)d_in[14];
    const float* bm        = (const float*)d_in[15];
    const float* Wa        = (const float*)d_in[16];
    const float* Ua        = (const float*)d_in[17];
    const float* ba        = (const float*)d_in[18];
    float* out = (float*)d_out;

    float *tbl_i, *tbl_q, *hinfo, *hq, *prod, *xzm, *hidden, *xza, *rec, *hA, *hB;
    uint4 *uaPk, *hAPk, *waPk, *hHi, *hLo;
    cudaGetSymbolAddress((void**)&tbl_i, g_table_i);
    cudaGetSymbolAddress((void**)&tbl_q, g_table_q);
    cudaGetSymbolAddress((void**)&hinfo, g_hinfo);
    cudaGetSymbolAddress((void**)&hq, g_hq);
    cudaGetSymbolAddress((void**)&prod, g_prod);
    cudaGetSymbolAddress((void**)&xzm, g_xzm);
    cudaGetSymbolAddress((void**)&hidden, g_hidden);
    cudaGetSymbolAddress((void**)&xza, g_xza);
    cudaGetSymbolAddress((void**)&rec, g_rec);
    cudaGetSymbolAddress((void**)&hA, g_hA);
    cudaGetSymbolAddress((void**)&hB, g_hB);
    cudaGetSymbolAddress((void**)&uaPk, g_UaPk);
    cudaGetSymbolAddress((void**)&hAPk, g_hAPk);
    cudaGetSymbolAddress((void**)&waPk, g_WaPk);
    cudaGetSymbolAddress((void**)&hHi, g_hHi);
    cudaGetSymbolAddress((void**)&hLo, g_hLo);

    const size_t smemR = ((size_t)RUN * 48 + (size_t)16 * RUN) * 8;
    const size_t smemM = ((size_t)MEM * 48 + (size_t)16 * MEM) * 8;
    const size_t ansSmem = (size_t)CHUNK_KC * 6 * 32 * 16 + 8 * 32 * 24 * 4;
    const size_t xzaSmem = (size_t)KCH2 * 6 * 32 * 16;   // 58368

    static bool attr_set = false;
    if (!attr_set) {
        cudaFuncSetAttribute(gru_seq_kernel<RUN>,
                             cudaFuncAttributeMaxDynamicSharedMemorySize, (int)smemR);
        cudaFuncSetAttribute(gru_seq_kernel<MEM>,
                             cudaFuncAttributeMaxDynamicSharedMemorySize, (int)smemM);
        cudaFuncSetAttribute(ans_gemm_kernel,
                             cudaFuncAttributeMaxDynamicSharedMemorySize, (int)ansSmem);
        cudaFuncSetAttribute(xza_gemm_kernel,
                             cudaFuncAttributeMaxDynamicSharedMemorySize, (int)xzaSmem);
        attr_set = true;
    }

    const dim3 blk(16, 4, 2);

    build_table_kernel<<<dim3((3 * RUN + 255) / 256, 1024), 256>>>(info_emb, Wi, bi, tbl_i, 3 * RUN);
    build_table_kernel<<<dim3((3 * RUN + 255) / 256, 64), 256>>>(q_emb, Wq, bq, tbl_q, 3 * RUN);

    {
        size_t F = (size_t)NBLK * NCH * 32;
        prep_ua_frag<<<(unsigned)((F + 255) / 256), 256>>>(Ua, uaPk);
    }
    {
        size_t F = (size_t)NBLK * KCH2 * 32;
        prep_wa_frag<<<(unsigned)((F + 255) / 256), 256>>>(Wa, waPk);
    }

    // info GRU (T=1024, H=400)
    gru_seq_kernel<RUN><<<dim3((RUN + 31) / 32, 8), blk, smemR>>>(
        tbl_i, info, Ui, bi + 3 * RUN, hA, hB, hinfo, nullptr, SLEN);

    // question GRU (T=64, H=400)
    gru_seq_kernel<RUN><<<dim3((RUN + 31) / 32, 8), blk, smemR>>>(
        tbl_q, question, Uq, bq + 3 * RUN, hA, hB, hq, nullptr, QLEN);

    prod_kernel<<<dim3(NSENT, BATCH), 128>>>(hinfo, hq, info_idx, num_sent, qidx, prod);

    gemm_bias_kernel<<<dim3((3 * MEM + 63) / 64, (BATCH * NSENT) / 64), 256>>>(
        prod, Wm, bm, xzm, BATCH * NSENT, RUN, 3 * MEM);

    // memory GRU (T=64, H=300)
    gru_seq_kernel<MEM><<<dim3((MEM + 31) / 32, 8), blk, smemM>>>(
        xzm, nullptr, Um, bm + 3 * MEM, hA, hB, hidden, num_sent, NSENT);

    // xza via HMMA: prep hidden frags, then fragment GEMM
    {
        size_t F = (size_t)MB2 * KCH2 * 32;
        prep_h_frag<<<(unsigned)((F + 255) / 256), 256>>>(hidden, hHi, hLo);
    }
    xza_gemm_kernel<<<dim3(125, 64), 256, xzaSmem>>>(ba, xza, waPk, hHi, hLo);

    // --- answer loop: 2 kernels per step, graph-ordered ---
    ans_init_kernel<<<148, 256>>>(hA, hAPk);
    {
        float* hp = hA;
        float* hn = hB;
        for (int n = 0; n < NSENT; ++n) {
            ans_gemm_kernel<<<ANS_NT, ANS_THR, ansSmem>>>(ba + N3V, rec, uaPk, hAPk);
            ans_update_kernel<<<BATCH, 256>>>(xza, rec, hp, hn, out, hAPk, n);
            float* tmp = hp; hp = hn; hn = tmp;
        }
    }
}